// round 2
// baseline (speedup 1.0000x reference)
#include <cuda_runtime.h>
#include <math.h>

#define N_NODES 100000
#define N_EDGES 1600000
#define IN_CH   128
#define HIDDEN  2
#define OUT_CH  128
#define ATTR    6
#define CH_TOT  (IN_CH * HIDDEN)   // 256

// Scratch as float4 arrays -> guaranteed 16B alignment (needed for float4
// loads and red.global.add.v4.f32).
__device__ float4 g_xc4[(size_t)N_NODES * IN_CH / 4];    // concat(x, node_attr), 51.2 MB
__device__ float4 g_aggr4[(size_t)N_NODES * CH_TOT / 4]; // scatter-add target, 102.4 MB
__device__ int    g_ei_is64;                             // edge_index dtype flag

// ---------------------------------------------------------------------------
// Probe: decide whether edge_index is int64 or int32.
// If int32 data is read as int64, the high 32 bits hold another random index
// (almost surely nonzero) -> value >= N_NODES. True int64 indices are all in
// [0, N_NODES). Deterministic for fixed input.
// ---------------------------------------------------------------------------
__global__ void k_probe(const long long* __restrict__ ei)
{
    if (threadIdx.x == 0 && blockIdx.x == 0) {
        int ok = 1;
        for (int i = 0; i < 256; i++) {
            long long v = ei[i];
            if (v < 0 || v >= N_NODES) { ok = 0; break; }
        }
        g_ei_is64 = ok;
    }
}

// ---------------------------------------------------------------------------
// Kernel 0: zero g_aggr and build g_xc = concat(x[N,127], node_attr[N,1])
// ---------------------------------------------------------------------------
__global__ void k_init(const float* __restrict__ x, const float* __restrict__ na)
{
    size_t i = (size_t)blockIdx.x * blockDim.x + threadIdx.x;
    size_t stride = (size_t)gridDim.x * blockDim.x;

    const size_t n_aggr4 = (size_t)N_NODES * CH_TOT / 4;
    float4 z = make_float4(0.f, 0.f, 0.f, 0.f);
    for (size_t j = i; j < n_aggr4; j += stride) g_aggr4[j] = z;

    float* xc = reinterpret_cast<float*>(g_xc4);
    const size_t n_xc = (size_t)N_NODES * IN_CH;
    for (size_t j = i; j < n_xc; j += stride) {
        int n = (int)(j >> 7);
        int c = (int)(j & 127);
        xc[j] = (c < 127) ? x[(size_t)n * 127 + c] : na[n];
    }
}

// ---------------------------------------------------------------------------
// Kernel 1: edge phase. One warp per edge (grid-strided).
// Lane t owns channels c in [4t, 4t+4) -> flat outputs j in [8t, 8t+8).
// W_in slice register-resident per lane. Scatter via red.global.add.v4.f32.
// ---------------------------------------------------------------------------
__global__ void __launch_bounds__(256) k_edge(
    const void*  __restrict__ ei_raw,  // [2, E] int64 OR int32
    const float* __restrict__ ea,      // [E, 6]
    const float* __restrict__ W_in,    // [6, 256]
    const float* __restrict__ b_in)    // [256]
{
    const int lane   = threadIdx.x & 31;
    const int warp   = blockIdx.x * (blockDim.x >> 5) + (threadIdx.x >> 5);
    const int nwarps = gridDim.x * (blockDim.x >> 5);

    const int is64 = g_ei_is64;
    const long long* ei64 = (const long long*)ei_raw;
    const int*       ei32 = (const int*)ei_raw;

    // register-resident weights: outputs j = lane*8 + k
    float w[8][6];
    float bb[8];
#pragma unroll
    for (int k = 0; k < 8; k++) {
        int j = lane * 8 + k;
        bb[k] = __ldg(&b_in[j]);
#pragma unroll
        for (int a = 0; a < 6; a++) w[k][a] = __ldg(&W_in[a * 256 + j]);
    }

    const float4* xc4 = g_xc4;
    float* aggr = reinterpret_cast<float*>(g_aggr4);

    for (int e = warp; e < N_EDGES; e += nwarps) {
        int src, dst;
        if (is64) {
            src = (int)__ldg(&ei64[e]);
            dst = (int)__ldg(&ei64[(size_t)N_EDGES + e]);
        } else {
            src = __ldg(&ei32[e]);
            dst = __ldg(&ei32[(size_t)N_EDGES + e]);
        }

        // issue the random gather early so it overlaps the scaling FMAs
        float4 xj = __ldg(&xc4[(size_t)src * 32 + lane]);

        const float* earow = &ea[(size_t)e * 6];
        float e0 = __ldg(&earow[0]);
        float e1 = __ldg(&earow[1]);
        float e2 = __ldg(&earow[2]);
        float e3 = __ldg(&earow[3]);
        float e4 = __ldg(&earow[4]);
        float e5 = __ldg(&earow[5]);

        float m[8];
#pragma unroll
        for (int k = 0; k < 8; k++) {
            float s = bb[k];
            s = fmaf(e0, w[k][0], s);
            s = fmaf(e1, w[k][1], s);
            s = fmaf(e2, w[k][2], s);
            s = fmaf(e3, w[k][3], s);
            s = fmaf(e4, w[k][4], s);
            s = fmaf(e5, w[k][5], s);
            s = fmaxf(s, 0.f);
            float xv = (k < 2) ? xj.x : (k < 4) ? xj.y : (k < 6) ? xj.z : xj.w;
            m[k] = s * xv;
        }

        float* p = &aggr[(size_t)dst * 256 + lane * 8];
        asm volatile("red.global.add.v4.f32 [%0], {%1,%2,%3,%4};"
                     :: "l"(p), "f"(m[0]), "f"(m[1]), "f"(m[2]), "f"(m[3]) : "memory");
        asm volatile("red.global.add.v4.f32 [%0], {%1,%2,%3,%4};"
                     :: "l"(p + 4), "f"(m[4]), "f"(m[5]), "f"(m[6]), "f"(m[7]) : "memory");
    }
}

// ---------------------------------------------------------------------------
// Kernel 2: out = tanh(g_aggr[N,256] @ W_out[256,128] + b_out)
// 128x128 block tile, BK=16, 256 threads, 8x8 per-thread microtile.
// ---------------------------------------------------------------------------
#define GBM 128
#define GBK 16

__global__ void __launch_bounds__(256) k_out(
    const float* __restrict__ W,   // [256, 128]
    const float* __restrict__ bo,  // [128]
    float*       __restrict__ out) // [N, 128]
{
    __shared__ float Ash[GBK][GBM];
    __shared__ float Bsh[GBK][OUT_CH];

    const int tid = threadIdx.x;
    const int tx  = tid & 15;   // 16 col groups
    const int ty  = tid >> 4;   // 16 row groups
    const int row0 = blockIdx.x * GBM;

    const float* aggr = reinterpret_cast<const float*>(g_aggr4);

    float acc[8][8];
#pragma unroll
    for (int i = 0; i < 8; i++)
#pragma unroll
        for (int j = 0; j < 8; j++) acc[i][j] = 0.f;

    for (int k0 = 0; k0 < CH_TOT; k0 += GBK) {
        // load A tile: 128 rows x 16 k, transposed into Ash[k][row]
#pragma unroll
        for (int g = 0; g < 2; g++) {
            int gi = tid * 2 + g;         // 0..511 float4 groups
            int r  = gi >> 2;             // 0..127 row within tile
            int kq = gi & 3;              // which float4 of the 16 k's
            int row = row0 + r;
            float4 v = make_float4(0.f, 0.f, 0.f, 0.f);
            if (row < N_NODES)
                v = *reinterpret_cast<const float4*>(&aggr[(size_t)row * 256 + k0 + kq * 4]);
            Ash[kq * 4 + 0][r] = v.x;
            Ash[kq * 4 + 1][r] = v.y;
            Ash[kq * 4 + 2][r] = v.z;
            Ash[kq * 4 + 3][r] = v.w;
        }
        // load B tile: 16 k x 128 cols (row-major, direct float4)
#pragma unroll
        for (int g = 0; g < 2; g++) {
            int gi = tid * 2 + g;
            int k  = gi >> 5;             // 0..15
            int nq = gi & 31;             // float4 col group
            *reinterpret_cast<float4*>(&Bsh[k][nq * 4]) =
                *reinterpret_cast<const float4*>(&W[(size_t)(k0 + k) * 128 + nq * 4]);
        }
        __syncthreads();

#pragma unroll
        for (int kk = 0; kk < GBK; kk++) {
            float a[8], b[8];
            *reinterpret_cast<float4*>(&a[0]) = *reinterpret_cast<float4*>(&Ash[kk][ty * 8]);
            *reinterpret_cast<float4*>(&a[4]) = *reinterpret_cast<float4*>(&Ash[kk][ty * 8 + 4]);
            *reinterpret_cast<float4*>(&b[0]) = *reinterpret_cast<float4*>(&Bsh[kk][tx * 8]);
            *reinterpret_cast<float4*>(&b[4]) = *reinterpret_cast<float4*>(&Bsh[kk][tx * 8 + 4]);
#pragma unroll
            for (int i = 0; i < 8; i++)
#pragma unroll
                for (int j = 0; j < 8; j++)
                    acc[i][j] = fmaf(a[i], b[j], acc[i][j]);
        }
        __syncthreads();
    }

    float bias[8];
#pragma unroll
    for (int j = 0; j < 8; j++) bias[j] = __ldg(&bo[tx * 8 + j]);

#pragma unroll
    for (int i = 0; i < 8; i++) {
        int row = row0 + ty * 8 + i;
        if (row < N_NODES) {
            float4 o1, o2;
            o1.x = tanhf(acc[i][0] + bias[0]);
            o1.y = tanhf(acc[i][1] + bias[1]);
            o1.z = tanhf(acc[i][2] + bias[2]);
            o1.w = tanhf(acc[i][3] + bias[3]);
            o2.x = tanhf(acc[i][4] + bias[4]);
            o2.y = tanhf(acc[i][5] + bias[5]);
            o2.z = tanhf(acc[i][6] + bias[6]);
            o2.w = tanhf(acc[i][7] + bias[7]);
            *reinterpret_cast<float4*>(&out[(size_t)row * 128 + tx * 8])     = o1;
            *reinterpret_cast<float4*>(&out[(size_t)row * 128 + tx * 8 + 4]) = o2;
        }
    }
}

// ---------------------------------------------------------------------------
// kernel_launch: probe -> init -> edge -> out
// Inputs (metadata order): x, node_attr, edge_index, edge_attr,
//                          W_in, b_in, W_out, b_out
// ---------------------------------------------------------------------------
extern "C" void kernel_launch(void* const* d_in, const int* in_sizes, int n_in,
                              void* d_out, int out_size)
{
    const float* x     = (const float*)d_in[0];
    const float* na    = (const float*)d_in[1];
    const void*  ei    = d_in[2];
    const float* ea    = (const float*)d_in[3];
    const float* W_in  = (const float*)d_in[4];
    const float* b_in  = (const float*)d_in[5];
    const float* W_out = (const float*)d_in[6];
    const float* b_out = (const float*)d_in[7];
    float* out = (float*)d_out;

    k_probe<<<1, 32>>>((const long long*)ei);
    k_init<<<4096, 256>>>(x, na);
    k_edge<<<1184, 256>>>(ei, ea, W_in, b_in);

    const int gemm_blocks = (N_NODES + GBM - 1) / GBM;  // 782
    k_out<<<gemm_blocks, 256>>>(W_out, b_out, out);
}

// round 3
// speedup vs baseline: 1.2290x; 1.2290x over previous
#include <cuda_runtime.h>
#include <math.h>

#define N_NODES 100000
#define N_EDGES 1600000
#define IN_CH   128
#define HIDDEN  2
#define OUT_CH  128
#define ATTR    6
#define CH_TOT  (IN_CH * HIDDEN)   // 256

typedef unsigned long long u64;

// ------------------------------ scratch ------------------------------------
__device__ float4 g_xc4[(size_t)N_NODES * IN_CH / 4];    // concat(x,node_attr) 51.2MB
__device__ float4 g_aggr4[(size_t)N_NODES * CH_TOT / 4]; // per-node aggregate 102.4MB
__device__ int    g_deg[N_NODES];
__device__ int    g_rowptr[N_NODES + 1];
__device__ int    g_cursor[N_NODES];
__device__ int2   g_pairs[N_EDGES];                      // (src, edge_id) CSR payload
__device__ int    g_ei_is64;

#define SCAN_BLK 512
#define N_SCAN_BLOCKS ((N_NODES + SCAN_BLK - 1) / SCAN_BLK)  // 196
__device__ int g_blockSums[N_SCAN_BLOCKS];

// ------------------------------ f32x2 helpers ------------------------------
__device__ __forceinline__ u64 pack2(float lo, float hi) {
    u64 d; asm("mov.b64 %0, {%1, %2};" : "=l"(d) : "f"(lo), "f"(hi)); return d;
}
__device__ __forceinline__ void unpack2(u64 d, float& lo, float& hi) {
    asm("mov.b64 {%0, %1}, %2;" : "=f"(lo), "=f"(hi) : "l"(d));
}
__device__ __forceinline__ u64 fma2(u64 a, u64 b, u64 c) {
    u64 d; asm("fma.rn.f32x2 %0, %1, %2, %3;" : "=l"(d) : "l"(a), "l"(b), "l"(c)); return d;
}

// ------------------------------ probe --------------------------------------
__global__ void k_probe(const long long* __restrict__ ei)
{
    if (threadIdx.x == 0 && blockIdx.x == 0) {
        int ok = 1;
        for (int i = 0; i < 256; i++) {
            long long v = ei[i];
            if (v < 0 || v >= N_NODES) { ok = 0; break; }
        }
        g_ei_is64 = ok;
    }
}

__device__ __forceinline__ int load_idx(const void* p, int is64, size_t i)
{
    return is64 ? (int)((const long long*)p)[i] : ((const int*)p)[i];
}

// ------------------------------ init: xc + zero deg ------------------------
__global__ void k_init(const float* __restrict__ x, const float* __restrict__ na)
{
    size_t i = (size_t)blockIdx.x * blockDim.x + threadIdx.x;
    size_t stride = (size_t)gridDim.x * blockDim.x;

    for (size_t j = i; j < N_NODES; j += stride) g_deg[j] = 0;

    float* xc = reinterpret_cast<float*>(g_xc4);
    const size_t n_xc = (size_t)N_NODES * IN_CH;
    for (size_t j = i; j < n_xc; j += stride) {
        int n = (int)(j >> 7);
        int c = (int)(j & 127);
        xc[j] = (c < 127) ? x[(size_t)n * 127 + c] : na[n];
    }
}

// ------------------------------ CSR build ----------------------------------
__global__ void k_hist(const void* __restrict__ ei)
{
    const int is64 = g_ei_is64;
    int i = blockIdx.x * blockDim.x + threadIdx.x;
    int stride = gridDim.x * blockDim.x;
    for (int e = i; e < N_EDGES; e += stride) {
        int dst = load_idx(ei, is64, (size_t)N_EDGES + e);
        atomicAdd(&g_deg[dst], 1);
    }
}

__global__ void k_scan1()
{
    __shared__ int s[SCAN_BLK];
    int t = threadIdx.x;
    int idx = blockIdx.x * SCAN_BLK + t;
    int v = (idx < N_NODES) ? g_deg[idx] : 0;
    s[t] = v;
    __syncthreads();
#pragma unroll
    for (int off = 1; off < SCAN_BLK; off <<= 1) {
        int tv = (t >= off) ? s[t - off] : 0;
        __syncthreads();
        s[t] += tv;
        __syncthreads();
    }
    if (idx < N_NODES) g_rowptr[idx] = s[t] - v;   // exclusive within block
    if (t == SCAN_BLK - 1) g_blockSums[blockIdx.x] = s[t];
}

__global__ void k_scan2()
{
    if (threadIdx.x == 0 && blockIdx.x == 0) {
        int running = 0;
        for (int i = 0; i < N_SCAN_BLOCKS; i++) {
            int t = g_blockSums[i];
            g_blockSums[i] = running;
            running += t;
        }
    }
}

__global__ void k_scan3()
{
    int idx = blockIdx.x * blockDim.x + threadIdx.x;
    if (idx < N_NODES) {
        int rp = g_rowptr[idx] + g_blockSums[idx / SCAN_BLK];
        g_rowptr[idx] = rp;
        g_cursor[idx] = rp;
    }
    if (idx == 0) g_rowptr[N_NODES] = N_EDGES;
}

__global__ void k_fill(const void* __restrict__ ei)
{
    const int is64 = g_ei_is64;
    int i = blockIdx.x * blockDim.x + threadIdx.x;
    int stride = gridDim.x * blockDim.x;
    for (int e = i; e < N_EDGES; e += stride) {
        int src = load_idx(ei, is64, e);
        int dst = load_idx(ei, is64, (size_t)N_EDGES + e);
        int pos = atomicAdd(&g_cursor[dst], 1);
        g_pairs[pos] = make_int2(src, e);
    }
}

// ------------------------------ aggregation --------------------------------
// One warp per dst node. Lane t owns channels [4t,4t+4); flat outputs
// j = lane*8 + 2*jj + h (pair over h via f32x2). W_in slices register-resident.
struct LaneW {
    u64 w2[6][4];   // w2[a][jj] = (W_in[a, lane*8+2jj], W_in[a, lane*8+2jj+1])
    u64 b2[4];
};

__device__ __forceinline__ void edge_accum(
    u64 acc[4], const LaneW& lw,
    float e0, float e1, float e2v, float e3, float e4, float e5, float4 xj)
{
    u64 ee[6];
    ee[0] = pack2(e0, e0);  ee[1] = pack2(e1, e1);  ee[2] = pack2(e2v, e2v);
    ee[3] = pack2(e3, e3);  ee[4] = pack2(e4, e4);  ee[5] = pack2(e5, e5);
#pragma unroll
    for (int jj = 0; jj < 4; jj++) {
        u64 s = lw.b2[jj];
#pragma unroll
        for (int a = 0; a < 6; a++) s = fma2(ee[a], lw.w2[a][jj], s);
        float lo, hi;
        unpack2(s, lo, hi);
        lo = fmaxf(lo, 0.f);
        hi = fmaxf(hi, 0.f);
        float xv = (jj == 0) ? xj.x : (jj == 1) ? xj.y : (jj == 2) ? xj.z : xj.w;
        acc[jj] = fma2(pack2(lo, hi), pack2(xv, xv), acc[jj]);
    }
}

__global__ void __launch_bounds__(256) k_aggr(
    const float* __restrict__ ea,    // [E, 6]
    const float* __restrict__ W_in,  // [6, 256]
    const float* __restrict__ b_in)  // [256]
{
    const int lane   = threadIdx.x & 31;
    const int warp   = blockIdx.x * (blockDim.x >> 5) + (threadIdx.x >> 5);
    const int nwarps = gridDim.x * (blockDim.x >> 5);

    LaneW lw;
#pragma unroll
    for (int jj = 0; jj < 4; jj++) {
        int j0 = lane * 8 + 2 * jj;
        lw.b2[jj] = pack2(__ldg(&b_in[j0]), __ldg(&b_in[j0 + 1]));
#pragma unroll
        for (int a = 0; a < 6; a++)
            lw.w2[a][jj] = pack2(__ldg(&W_in[a * 256 + j0]),
                                 __ldg(&W_in[a * 256 + j0 + 1]));
    }

    const u64 z = pack2(0.f, 0.f);

    for (int n = warp; n < N_NODES; n += nwarps) {
        int beg = g_rowptr[n];
        int end = g_rowptr[n + 1];

        u64 acc[4] = {z, z, z, z};

        int idx = beg;
        // 2-edge unroll: both gathers in flight before either compute
        for (; idx + 2 <= end; idx += 2) {
            int2 p0 = __ldg(&g_pairs[idx]);
            int2 p1 = __ldg(&g_pairs[idx + 1]);
            float4 x0 = __ldg(&g_xc4[(size_t)p0.x * 32 + lane]);
            float4 x1 = __ldg(&g_xc4[(size_t)p1.x * 32 + lane]);
            const float* r0 = &ea[(size_t)p0.y * 6];
            const float* r1 = &ea[(size_t)p1.y * 6];
            float a0 = __ldg(&r0[0]), a1 = __ldg(&r0[1]), a2 = __ldg(&r0[2]);
            float a3 = __ldg(&r0[3]), a4 = __ldg(&r0[4]), a5 = __ldg(&r0[5]);
            float c0 = __ldg(&r1[0]), c1 = __ldg(&r1[1]), c2 = __ldg(&r1[2]);
            float c3 = __ldg(&r1[3]), c4 = __ldg(&r1[4]), c5 = __ldg(&r1[5]);
            edge_accum(acc, lw, a0, a1, a2, a3, a4, a5, x0);
            edge_accum(acc, lw, c0, c1, c2, c3, c4, c5, x1);
        }
        if (idx < end) {
            int2 p0 = __ldg(&g_pairs[idx]);
            float4 x0 = __ldg(&g_xc4[(size_t)p0.x * 32 + lane]);
            const float* r0 = &ea[(size_t)p0.y * 6];
            float a0 = __ldg(&r0[0]), a1 = __ldg(&r0[1]), a2 = __ldg(&r0[2]);
            float a3 = __ldg(&r0[3]), a4 = __ldg(&r0[4]), a5 = __ldg(&r0[5]);
            edge_accum(acc, lw, a0, a1, a2, a3, a4, a5, x0);
        }

        float4 o1, o2;
        unpack2(acc[0], o1.x, o1.y);
        unpack2(acc[1], o1.z, o1.w);
        unpack2(acc[2], o2.x, o2.y);
        unpack2(acc[3], o2.z, o2.w);
        g_aggr4[(size_t)n * 64 + lane * 2]     = o1;
        g_aggr4[(size_t)n * 64 + lane * 2 + 1] = o2;
    }
}

// ------------------------------ output GEMM --------------------------------
// out = tanh(aggr[N,256] @ W_out[256,128] + b_out); 128x128 tile, BK=16, 8x8.
#define GBM 128
#define GBK 16

__global__ void __launch_bounds__(256) k_out(
    const float* __restrict__ W,
    const float* __restrict__ bo,
    float*       __restrict__ out)
{
    __shared__ float Ash[GBK][GBM];
    __shared__ float Bsh[GBK][OUT_CH];

    const int tid = threadIdx.x;
    const int tx  = tid & 15;
    const int ty  = tid >> 4;
    const int row0 = blockIdx.x * GBM;

    const float* aggr = reinterpret_cast<const float*>(g_aggr4);

    float acc[8][8];
#pragma unroll
    for (int i = 0; i < 8; i++)
#pragma unroll
        for (int j = 0; j < 8; j++) acc[i][j] = 0.f;

    for (int k0 = 0; k0 < CH_TOT; k0 += GBK) {
#pragma unroll
        for (int g = 0; g < 2; g++) {
            int gi = tid * 2 + g;
            int r  = gi >> 2;
            int kq = gi & 3;
            int row = row0 + r;
            float4 v = make_float4(0.f, 0.f, 0.f, 0.f);
            if (row < N_NODES)
                v = *reinterpret_cast<const float4*>(&aggr[(size_t)row * 256 + k0 + kq * 4]);
            Ash[kq * 4 + 0][r] = v.x;
            Ash[kq * 4 + 1][r] = v.y;
            Ash[kq * 4 + 2][r] = v.z;
            Ash[kq * 4 + 3][r] = v.w;
        }
#pragma unroll
        for (int g = 0; g < 2; g++) {
            int gi = tid * 2 + g;
            int k  = gi >> 5;
            int nq = gi & 31;
            *reinterpret_cast<float4*>(&Bsh[k][nq * 4]) =
                *reinterpret_cast<const float4*>(&W[(size_t)(k0 + k) * 128 + nq * 4]);
        }
        __syncthreads();

#pragma unroll
        for (int kk = 0; kk < GBK; kk++) {
            float a[8], b[8];
            *reinterpret_cast<float4*>(&a[0]) = *reinterpret_cast<float4*>(&Ash[kk][ty * 8]);
            *reinterpret_cast<float4*>(&a[4]) = *reinterpret_cast<float4*>(&Ash[kk][ty * 8 + 4]);
            *reinterpret_cast<float4*>(&b[0]) = *reinterpret_cast<float4*>(&Bsh[kk][tx * 8]);
            *reinterpret_cast<float4*>(&b[4]) = *reinterpret_cast<float4*>(&Bsh[kk][tx * 8 + 4]);
#pragma unroll
            for (int i = 0; i < 8; i++)
#pragma unroll
                for (int j = 0; j < 8; j++)
                    acc[i][j] = fmaf(a[i], b[j], acc[i][j]);
        }
        __syncthreads();
    }

    float bias[8];
#pragma unroll
    for (int j = 0; j < 8; j++) bias[j] = __ldg(&bo[tx * 8 + j]);

#pragma unroll
    for (int i = 0; i < 8; i++) {
        int row = row0 + ty * 8 + i;
        if (row < N_NODES) {
            float4 o1, o2;
            o1.x = tanhf(acc[i][0] + bias[0]);
            o1.y = tanhf(acc[i][1] + bias[1]);
            o1.z = tanhf(acc[i][2] + bias[2]);
            o1.w = tanhf(acc[i][3] + bias[3]);
            o2.x = tanhf(acc[i][4] + bias[4]);
            o2.y = tanhf(acc[i][5] + bias[5]);
            o2.z = tanhf(acc[i][6] + bias[6]);
            o2.w = tanhf(acc[i][7] + bias[7]);
            *reinterpret_cast<float4*>(&out[(size_t)row * 128 + tx * 8])     = o1;
            *reinterpret_cast<float4*>(&out[(size_t)row * 128 + tx * 8 + 4]) = o2;
        }
    }
}

// ------------------------------ launch -------------------------------------
extern "C" void kernel_launch(void* const* d_in, const int* in_sizes, int n_in,
                              void* d_out, int out_size)
{
    const float* x     = (const float*)d_in[0];
    const float* na    = (const float*)d_in[1];
    const void*  ei    = d_in[2];
    const float* ea    = (const float*)d_in[3];
    const float* W_in  = (const float*)d_in[4];
    const float* b_in  = (const float*)d_in[5];
    const float* W_out = (const float*)d_in[6];
    const float* b_out = (const float*)d_in[7];
    float* out = (float*)d_out;

    k_probe<<<1, 32>>>((const long long*)ei);
    k_init<<<4096, 256>>>(x, na);

    k_hist<<<2048, 256>>>(ei);
    k_scan1<<<N_SCAN_BLOCKS, SCAN_BLK>>>();
    k_scan2<<<1, 32>>>();
    k_scan3<<<(N_NODES + 255) / 256, 256>>>();
    k_fill<<<2048, 256>>>(ei);

    k_aggr<<<2048, 256>>>(ea, W_in, b_in);

    const int gemm_blocks = (N_NODES + GBM - 1) / GBM;
    k_out<<<gemm_blocks, 256>>>(W_out, b_out, out);
}

// round 4
// speedup vs baseline: 1.4203x; 1.1556x over previous
#include <cuda_runtime.h>
#include <math.h>

#define N_NODES 100000
#define N_EDGES 1600000
#define IN_CH   128
#define HIDDEN  2
#define OUT_CH  128
#define ATTR    6
#define CH_TOT  (IN_CH * HIDDEN)   // 256

typedef unsigned long long u64;

// ------------------------------ scratch ------------------------------------
__device__ float4 g_xc4[(size_t)N_NODES * IN_CH / 4];    // concat(x,node_attr) 51.2MB
__device__ float4 g_aggr4[(size_t)N_NODES * CH_TOT / 4]; // per-node aggregate 102.4MB
__device__ int    g_deg[N_NODES];
__device__ int    g_rowptr[N_NODES + 1];
__device__ int    g_cursor[N_NODES];
__device__ int2   g_pairs[N_EDGES];                      // (src, edge_id) CSR payload
__device__ int    g_ei_is64;

#define SCAN_BLK 512
#define N_SCAN_BLOCKS ((N_NODES + SCAN_BLK - 1) / SCAN_BLK)  // 196
__device__ int g_blockSums[N_SCAN_BLOCKS];

// ------------------------------ f32x2 helpers ------------------------------
__device__ __forceinline__ u64 pack2(float lo, float hi) {
    u64 d; asm("mov.b64 %0, {%1, %2};" : "=l"(d) : "f"(lo), "f"(hi)); return d;
}
__device__ __forceinline__ void unpack2(u64 d, float& lo, float& hi) {
    asm("mov.b64 {%0, %1}, %2;" : "=f"(lo), "=f"(hi) : "l"(d));
}
__device__ __forceinline__ u64 fma2(u64 a, u64 b, u64 c) {
    u64 d; asm("fma.rn.f32x2 %0, %1, %2, %3;" : "=l"(d) : "l"(a), "l"(b), "l"(c)); return d;
}

// ------------------------------ probe --------------------------------------
__global__ void k_probe(const long long* __restrict__ ei)
{
    if (threadIdx.x == 0 && blockIdx.x == 0) {
        int ok = 1;
        for (int i = 0; i < 256; i++) {
            long long v = ei[i];
            if (v < 0 || v >= N_NODES) { ok = 0; break; }
        }
        g_ei_is64 = ok;
    }
}

__device__ __forceinline__ int load_idx(const void* p, int is64, size_t i)
{
    return is64 ? (int)((const long long*)p)[i] : ((const int*)p)[i];
}

// ------------------------------ zero degree --------------------------------
__global__ void k_zero()
{
    int i = blockIdx.x * blockDim.x + threadIdx.x;
    if (i < N_NODES) g_deg[i] = 0;
}

// ------------------- init: build xc + histogram dst degrees ----------------
__global__ void k_init(const float* __restrict__ x, const float* __restrict__ na,
                       const void* __restrict__ ei)
{
    size_t i = (size_t)blockIdx.x * blockDim.x + threadIdx.x;
    size_t stride = (size_t)gridDim.x * blockDim.x;
    const int is64 = g_ei_is64;

    float* xc = reinterpret_cast<float*>(g_xc4);
    const size_t n_xc = (size_t)N_NODES * IN_CH;
    for (size_t j = i; j < n_xc; j += stride) {
        int n = (int)(j >> 7);
        int c = (int)(j & 127);
        xc[j] = (c < 127) ? x[(size_t)n * 127 + c] : na[n];
    }

    for (size_t e = i; e < N_EDGES; e += stride) {
        int dst = load_idx(ei, is64, (size_t)N_EDGES + e);
        atomicAdd(&g_deg[dst], 1);
    }
}

// ------------------------------ CSR scan -----------------------------------
__global__ void k_scan1()
{
    __shared__ int s[SCAN_BLK];
    int t = threadIdx.x;
    int idx = blockIdx.x * SCAN_BLK + t;
    int v = (idx < N_NODES) ? g_deg[idx] : 0;
    s[t] = v;
    __syncthreads();
#pragma unroll
    for (int off = 1; off < SCAN_BLK; off <<= 1) {
        int tv = (t >= off) ? s[t - off] : 0;
        __syncthreads();
        s[t] += tv;
        __syncthreads();
    }
    if (idx < N_NODES) g_rowptr[idx] = s[t] - v;
    if (t == SCAN_BLK - 1) g_blockSums[blockIdx.x] = s[t];
}

__global__ void k_scan2()
{
    if (threadIdx.x == 0 && blockIdx.x == 0) {
        int running = 0;
        for (int i = 0; i < N_SCAN_BLOCKS; i++) {
            int t = g_blockSums[i];
            g_blockSums[i] = running;
            running += t;
        }
    }
}

__global__ void k_scan3()
{
    int idx = blockIdx.x * blockDim.x + threadIdx.x;
    if (idx < N_NODES) {
        int rp = g_rowptr[idx] + g_blockSums[idx / SCAN_BLK];
        g_rowptr[idx] = rp;
        g_cursor[idx] = rp;
    }
    if (idx == 0) g_rowptr[N_NODES] = N_EDGES;
}

__global__ void k_fill(const void* __restrict__ ei)
{
    const int is64 = g_ei_is64;
    int i = blockIdx.x * blockDim.x + threadIdx.x;
    int stride = gridDim.x * blockDim.x;
    for (int e = i; e < N_EDGES; e += stride) {
        int src = load_idx(ei, is64, e);
        int dst = load_idx(ei, is64, (size_t)N_EDGES + e);
        int pos = atomicAdd(&g_cursor[dst], 1);
        g_pairs[pos] = make_int2(src, e);
    }
}

// ------------------------------ aggregation --------------------------------
// One warp per dst node. Lane t owns channels [4t,4t+4); flat outputs
// j = lane*8 + 2*jj + h (pair over h via f32x2). W_in slices register-resident.
struct LaneW {
    u64 w2[6][4];
    u64 b2[4];
};

__device__ __forceinline__ void edge_accum(
    u64 acc[4], const LaneW& lw,
    float2 e01, float2 e23, float2 e45, float4 xj)
{
    u64 ee[6];
    ee[0] = pack2(e01.x, e01.x);  ee[1] = pack2(e01.y, e01.y);
    ee[2] = pack2(e23.x, e23.x);  ee[3] = pack2(e23.y, e23.y);
    ee[4] = pack2(e45.x, e45.x);  ee[5] = pack2(e45.y, e45.y);
#pragma unroll
    for (int jj = 0; jj < 4; jj++) {
        u64 s = lw.b2[jj];
#pragma unroll
        for (int a = 0; a < 6; a++) s = fma2(ee[a], lw.w2[a][jj], s);
        float lo, hi;
        unpack2(s, lo, hi);
        lo = fmaxf(lo, 0.f);
        hi = fmaxf(hi, 0.f);
        float xv = (jj == 0) ? xj.x : (jj == 1) ? xj.y : (jj == 2) ? xj.z : xj.w;
        acc[jj] = fma2(pack2(lo, hi), pack2(xv, xv), acc[jj]);
    }
}

__global__ void __launch_bounds__(128, 4) k_aggr(
    const float* __restrict__ ea,    // [E, 6]
    const float* __restrict__ W_in,  // [6, 256]
    const float* __restrict__ b_in)  // [256]
{
    const int lane   = threadIdx.x & 31;
    const int warp   = blockIdx.x * (blockDim.x >> 5) + (threadIdx.x >> 5);
    const int nwarps = gridDim.x * (blockDim.x >> 5);

    LaneW lw;
#pragma unroll
    for (int jj = 0; jj < 4; jj++) {
        int j0 = lane * 8 + 2 * jj;
        lw.b2[jj] = pack2(__ldg(&b_in[j0]), __ldg(&b_in[j0 + 1]));
#pragma unroll
        for (int a = 0; a < 6; a++)
            lw.w2[a][jj] = pack2(__ldg(&W_in[a * 256 + j0]),
                                 __ldg(&W_in[a * 256 + j0 + 1]));
    }

    const u64 z = pack2(0.f, 0.f);
    const float2* ea2 = reinterpret_cast<const float2*>(ea);

    for (int n = warp; n < N_NODES; n += nwarps) {
        int beg = g_rowptr[n];
        int end = g_rowptr[n + 1];

        u64 acc[4] = {z, z, z, z};

        int idx = beg;
        for (; idx + 2 <= end; idx += 2) {
            int2 p0 = __ldg(&g_pairs[idx]);
            int2 p1 = __ldg(&g_pairs[idx + 1]);
            float4 x0 = __ldg(&g_xc4[(size_t)p0.x * 32 + lane]);
            float4 x1 = __ldg(&g_xc4[(size_t)p1.x * 32 + lane]);
            float2 a01 = __ldg(&ea2[(size_t)p0.y * 3]);
            float2 a23 = __ldg(&ea2[(size_t)p0.y * 3 + 1]);
            float2 a45 = __ldg(&ea2[(size_t)p0.y * 3 + 2]);
            float2 c01 = __ldg(&ea2[(size_t)p1.y * 3]);
            float2 c23 = __ldg(&ea2[(size_t)p1.y * 3 + 1]);
            float2 c45 = __ldg(&ea2[(size_t)p1.y * 3 + 2]);
            edge_accum(acc, lw, a01, a23, a45, x0);
            edge_accum(acc, lw, c01, c23, c45, x1);
        }
        if (idx < end) {
            int2 p0 = __ldg(&g_pairs[idx]);
            float4 x0 = __ldg(&g_xc4[(size_t)p0.x * 32 + lane]);
            float2 a01 = __ldg(&ea2[(size_t)p0.y * 3]);
            float2 a23 = __ldg(&ea2[(size_t)p0.y * 3 + 1]);
            float2 a45 = __ldg(&ea2[(size_t)p0.y * 3 + 2]);
            edge_accum(acc, lw, a01, a23, a45, x0);
        }

        float4 o1, o2;
        unpack2(acc[0], o1.x, o1.y);
        unpack2(acc[1], o1.z, o1.w);
        unpack2(acc[2], o2.x, o2.y);
        unpack2(acc[3], o2.z, o2.w);
        g_aggr4[(size_t)n * 64 + lane * 2]     = o1;
        g_aggr4[(size_t)n * 64 + lane * 2 + 1] = o2;
    }
}

// ------------------------------ output GEMM --------------------------------
// out = tanh(aggr[N,256] @ W_out[256,128] + b_out); 128x128 tile, BK=16.
// 8x8 microtile packed as 8x4 f32x2 column pairs.
#define GBM 128
#define GBK 16

__global__ void __launch_bounds__(256) k_out(
    const float* __restrict__ W,
    const float* __restrict__ bo,
    float*       __restrict__ out)
{
    __shared__ float Ash[GBK][GBM];
    __shared__ float Bsh[GBK][OUT_CH];

    const int tid = threadIdx.x;
    const int tx  = tid & 15;
    const int ty  = tid >> 4;
    const int row0 = blockIdx.x * GBM;

    const float* aggr = reinterpret_cast<const float*>(g_aggr4);

    u64 acc2[8][4];
    const u64 z = pack2(0.f, 0.f);
#pragma unroll
    for (int i = 0; i < 8; i++)
#pragma unroll
        for (int jj = 0; jj < 4; jj++) acc2[i][jj] = z;

    for (int k0 = 0; k0 < CH_TOT; k0 += GBK) {
#pragma unroll
        for (int g = 0; g < 2; g++) {
            int gi = tid * 2 + g;
            int r  = gi >> 2;
            int kq = gi & 3;
            int row = row0 + r;
            float4 v = make_float4(0.f, 0.f, 0.f, 0.f);
            if (row < N_NODES)
                v = *reinterpret_cast<const float4*>(&aggr[(size_t)row * 256 + k0 + kq * 4]);
            Ash[kq * 4 + 0][r] = v.x;
            Ash[kq * 4 + 1][r] = v.y;
            Ash[kq * 4 + 2][r] = v.z;
            Ash[kq * 4 + 3][r] = v.w;
        }
#pragma unroll
        for (int g = 0; g < 2; g++) {
            int gi = tid * 2 + g;
            int k  = gi >> 5;
            int nq = gi & 31;
            *reinterpret_cast<float4*>(&Bsh[k][nq * 4]) =
                *reinterpret_cast<const float4*>(&W[(size_t)(k0 + k) * 128 + nq * 4]);
        }
        __syncthreads();

#pragma unroll
        for (int kk = 0; kk < GBK; kk++) {
            float a[8];
            *reinterpret_cast<float4*>(&a[0]) = *reinterpret_cast<float4*>(&Ash[kk][ty * 8]);
            *reinterpret_cast<float4*>(&a[4]) = *reinterpret_cast<float4*>(&Ash[kk][ty * 8 + 4]);
            ulonglong2 b01 = *reinterpret_cast<ulonglong2*>(&Bsh[kk][tx * 8]);
            ulonglong2 b23 = *reinterpret_cast<ulonglong2*>(&Bsh[kk][tx * 8 + 4]);
            u64 b2[4] = {b01.x, b01.y, b23.x, b23.y};
#pragma unroll
            for (int i = 0; i < 8; i++) {
                u64 ap = pack2(a[i], a[i]);
#pragma unroll
                for (int jj = 0; jj < 4; jj++)
                    acc2[i][jj] = fma2(ap, b2[jj], acc2[i][jj]);
            }
        }
        __syncthreads();
    }

    float bias[8];
#pragma unroll
    for (int j = 0; j < 8; j++) bias[j] = __ldg(&bo[tx * 8 + j]);

#pragma unroll
    for (int i = 0; i < 8; i++) {
        int row = row0 + ty * 8 + i;
        if (row < N_NODES) {
            float v[8];
#pragma unroll
            for (int jj = 0; jj < 4; jj++)
                unpack2(acc2[i][jj], v[2 * jj], v[2 * jj + 1]);
            float4 o1, o2;
            o1.x = tanhf(v[0] + bias[0]);
            o1.y = tanhf(v[1] + bias[1]);
            o1.z = tanhf(v[2] + bias[2]);
            o1.w = tanhf(v[3] + bias[3]);
            o2.x = tanhf(v[4] + bias[4]);
            o2.y = tanhf(v[5] + bias[5]);
            o2.z = tanhf(v[6] + bias[6]);
            o2.w = tanhf(v[7] + bias[7]);
            *reinterpret_cast<float4*>(&out[(size_t)row * 128 + tx * 8])     = o1;
            *reinterpret_cast<float4*>(&out[(size_t)row * 128 + tx * 8 + 4]) = o2;
        }
    }
}

// ------------------------------ launch -------------------------------------
extern "C" void kernel_launch(void* const* d_in, const int* in_sizes, int n_in,
                              void* d_out, int out_size)
{
    const float* x     = (const float*)d_in[0];
    const float* na    = (const float*)d_in[1];
    const void*  ei    = d_in[2];
    const float* ea    = (const float*)d_in[3];
    const float* W_in  = (const float*)d_in[4];
    const float* b_in  = (const float*)d_in[5];
    const float* W_out = (const float*)d_in[6];
    const float* b_out = (const float*)d_in[7];
    float* out = (float*)d_out;

    k_probe<<<1, 32>>>((const long long*)ei);
    k_zero<<<(N_NODES + 511) / 512, 512>>>();
    k_init<<<4096, 256>>>(x, na, ei);

    k_scan1<<<N_SCAN_BLOCKS, SCAN_BLK>>>();
    k_scan2<<<1, 32>>>();
    k_scan3<<<(N_NODES + 255) / 256, 256>>>();
    k_fill<<<2048, 256>>>(ei);

    k_aggr<<<4096, 128>>>(ea, W_in, b_in);

    const int gemm_blocks = (N_NODES + GBM - 1) / GBM;
    k_out<<<gemm_blocks, 256>>>(W_out, b_out, out);
}

// round 5
// speedup vs baseline: 1.4614x; 1.0290x over previous
#include <cuda_runtime.h>
#include <math.h>

#define N_NODES 100000
#define N_EDGES 1600000
#define IN_CH   128
#define HIDDEN  2
#define OUT_CH  128
#define ATTR    6
#define CH_TOT  (IN_CH * HIDDEN)   // 256

typedef unsigned long long u64;

// ------------------------------ scratch ------------------------------------
__device__ float4 g_xc4[(size_t)N_NODES * IN_CH / 4];    // concat(x,node_attr) 51.2MB
__device__ float4 g_aggr4[(size_t)N_NODES * CH_TOT / 4]; // per-node aggregate 102.4MB
__device__ float4 g_erec[(size_t)2 * N_EDGES];           // CSR-ordered (src,e0..e5) 51.2MB
__device__ int    g_deg[N_NODES];
__device__ int    g_rowptr[N_NODES + 1];
__device__ int    g_cursor[N_NODES];
__device__ int    g_ei_is64;

#define SCAN_BLK 512
#define N_SCAN_BLOCKS ((N_NODES + SCAN_BLK - 1) / SCAN_BLK)  // 196
__device__ int g_blockSums[N_SCAN_BLOCKS];

// ------------------------------ f32x2 helpers ------------------------------
__device__ __forceinline__ u64 pack2(float lo, float hi) {
    u64 d; asm("mov.b64 %0, {%1, %2};" : "=l"(d) : "f"(lo), "f"(hi)); return d;
}
__device__ __forceinline__ void unpack2(u64 d, float& lo, float& hi) {
    asm("mov.b64 {%0, %1}, %2;" : "=f"(lo), "=f"(hi) : "l"(d));
}
__device__ __forceinline__ u64 fma2(u64 a, u64 b, u64 c) {
    u64 d; asm("fma.rn.f32x2 %0, %1, %2, %3;" : "=l"(d) : "l"(a), "l"(b), "l"(c)); return d;
}

// ------------------------------ probe + zero -------------------------------
__global__ void k_probe(const long long* __restrict__ ei)
{
    int i = blockIdx.x * blockDim.x + threadIdx.x;
    if (i < N_NODES) g_deg[i] = 0;
    if (i == 0) {
        int ok = 1;
        for (int j = 0; j < 256; j++) {
            long long v = ei[j];
            if (v < 0 || v >= N_NODES) { ok = 0; break; }
        }
        g_ei_is64 = ok;
    }
}

__device__ __forceinline__ int load_idx(const void* p, int is64, size_t i)
{
    return is64 ? (int)((const long long*)p)[i] : ((const int*)p)[i];
}

// ------------------- init: build xc + histogram dst degrees ----------------
__global__ void k_init(const float* __restrict__ x, const float* __restrict__ na,
                       const void* __restrict__ ei)
{
    size_t i = (size_t)blockIdx.x * blockDim.x + threadIdx.x;
    size_t stride = (size_t)gridDim.x * blockDim.x;
    const int is64 = g_ei_is64;

    float* xc = reinterpret_cast<float*>(g_xc4);
    const size_t n_xc = (size_t)N_NODES * IN_CH;
    for (size_t j = i; j < n_xc; j += stride) {
        int n = (int)(j >> 7);
        int c = (int)(j & 127);
        xc[j] = (c < 127) ? x[(size_t)n * 127 + c] : na[n];
    }

    for (size_t e = i; e < N_EDGES; e += stride) {
        int dst = load_idx(ei, is64, (size_t)N_EDGES + e);
        atomicAdd(&g_deg[dst], 1);
    }
}

// ------------------------------ CSR scan -----------------------------------
__global__ void k_scan1()
{
    __shared__ int s[SCAN_BLK];
    int t = threadIdx.x;
    int idx = blockIdx.x * SCAN_BLK + t;
    int v = (idx < N_NODES) ? g_deg[idx] : 0;
    s[t] = v;
    __syncthreads();
#pragma unroll
    for (int off = 1; off < SCAN_BLK; off <<= 1) {
        int tv = (t >= off) ? s[t - off] : 0;
        __syncthreads();
        s[t] += tv;
        __syncthreads();
    }
    if (idx < N_NODES) g_rowptr[idx] = s[t] - v;
    if (t == SCAN_BLK - 1) g_blockSums[blockIdx.x] = s[t];
}

// one block: inclusive->exclusive scan of 196 block sums
__global__ void k_scan2()
{
    __shared__ int s[256];
    int t = threadIdx.x;
    int v = (t < N_SCAN_BLOCKS) ? g_blockSums[t] : 0;
    s[t] = v;
    __syncthreads();
#pragma unroll
    for (int off = 1; off < 256; off <<= 1) {
        int tv = (t >= off) ? s[t - off] : 0;
        __syncthreads();
        s[t] += tv;
        __syncthreads();
    }
    if (t < N_SCAN_BLOCKS) g_blockSums[t] = s[t] - v;  // exclusive
}

__global__ void k_scan3()
{
    int idx = blockIdx.x * blockDim.x + threadIdx.x;
    if (idx < N_NODES) {
        int rp = g_rowptr[idx] + g_blockSums[idx / SCAN_BLK];
        g_rowptr[idx] = rp;
        g_cursor[idx] = rp;
    }
    if (idx == 0) g_rowptr[N_NODES] = N_EDGES;
}

// ----------------- fill: CSR-ordered edge records (src + attrs) ------------
__global__ void k_fill(const void* __restrict__ ei, const float* __restrict__ ea)
{
    const int is64 = g_ei_is64;
    const float2* ea2 = reinterpret_cast<const float2*>(ea);
    int i = blockIdx.x * blockDim.x + threadIdx.x;
    int stride = gridDim.x * blockDim.x;
    for (int e = i; e < N_EDGES; e += stride) {
        int src = load_idx(ei, is64, e);
        int dst = load_idx(ei, is64, (size_t)N_EDGES + e);
        float2 a01 = __ldg(&ea2[(size_t)e * 3]);
        float2 a23 = __ldg(&ea2[(size_t)e * 3 + 1]);
        float2 a45 = __ldg(&ea2[(size_t)e * 3 + 2]);
        int pos = atomicAdd(&g_cursor[dst], 1);
        g_erec[(size_t)2 * pos]     = make_float4(__int_as_float(src), a01.x, a01.y, a23.x);
        g_erec[(size_t)2 * pos + 1] = make_float4(a23.y, a45.x, a45.y, 0.f);
    }
}

// ------------------------------ aggregation --------------------------------
// One warp per dst node. Lane t owns channels [4t,4t+4); flat outputs
// j = lane*8 + 2*jj + h (pair over h via f32x2). W_in slices register-resident.
// Edge data read sequentially from g_erec; only the xc gather is random.
struct LaneW {
    u64 w2[6][4];
    u64 b2[4];
};

__device__ __forceinline__ void edge_accum(
    u64 acc[4], const LaneW& lw, float4 ra, float4 rb, float4 xj)
{
    u64 ee[6];
    ee[0] = pack2(ra.y, ra.y);  ee[1] = pack2(ra.z, ra.z);  ee[2] = pack2(ra.w, ra.w);
    ee[3] = pack2(rb.x, rb.x);  ee[4] = pack2(rb.y, rb.y);  ee[5] = pack2(rb.z, rb.z);
#pragma unroll
    for (int jj = 0; jj < 4; jj++) {
        u64 s = lw.b2[jj];
#pragma unroll
        for (int a = 0; a < 6; a++) s = fma2(ee[a], lw.w2[a][jj], s);
        float lo, hi;
        unpack2(s, lo, hi);
        lo = fmaxf(lo, 0.f);
        hi = fmaxf(hi, 0.f);
        float xv = (jj == 0) ? xj.x : (jj == 1) ? xj.y : (jj == 2) ? xj.z : xj.w;
        acc[jj] = fma2(pack2(lo, hi), pack2(xv, xv), acc[jj]);
    }
}

__global__ void __launch_bounds__(128, 3) k_aggr(
    const float* __restrict__ W_in,  // [6, 256]
    const float* __restrict__ b_in)  // [256]
{
    const int lane   = threadIdx.x & 31;
    const int warp   = blockIdx.x * (blockDim.x >> 5) + (threadIdx.x >> 5);
    const int nwarps = gridDim.x * (blockDim.x >> 5);

    LaneW lw;
#pragma unroll
    for (int jj = 0; jj < 4; jj++) {
        int j0 = lane * 8 + 2 * jj;
        lw.b2[jj] = pack2(__ldg(&b_in[j0]), __ldg(&b_in[j0 + 1]));
#pragma unroll
        for (int a = 0; a < 6; a++)
            lw.w2[a][jj] = pack2(__ldg(&W_in[a * 256 + j0]),
                                 __ldg(&W_in[a * 256 + j0 + 1]));
    }

    const u64 z = pack2(0.f, 0.f);

    for (int n = warp; n < N_NODES; n += nwarps) {
        int beg = g_rowptr[n];
        int end = g_rowptr[n + 1];

        u64 acc[4] = {z, z, z, z};

        int idx = beg;
        // 4-edge unroll: all records + gathers in flight before compute
        for (; idx + 4 <= end; idx += 4) {
            float4 ra[4], rb[4], xv[4];
#pragma unroll
            for (int j = 0; j < 4; j++) {
                ra[j] = __ldg(&g_erec[(size_t)2 * (idx + j)]);
                rb[j] = __ldg(&g_erec[(size_t)2 * (idx + j) + 1]);
            }
#pragma unroll
            for (int j = 0; j < 4; j++) {
                int src = __float_as_int(ra[j].x);
                xv[j] = __ldg(&g_xc4[(size_t)src * 32 + lane]);
            }
#pragma unroll
            for (int j = 0; j < 4; j++)
                edge_accum(acc, lw, ra[j], rb[j], xv[j]);
        }
        for (; idx < end; idx++) {
            float4 ra = __ldg(&g_erec[(size_t)2 * idx]);
            float4 rb = __ldg(&g_erec[(size_t)2 * idx + 1]);
            int src = __float_as_int(ra.x);
            float4 xv = __ldg(&g_xc4[(size_t)src * 32 + lane]);
            edge_accum(acc, lw, ra, rb, xv);
        }

        float4 o1, o2;
        unpack2(acc[0], o1.x, o1.y);
        unpack2(acc[1], o1.z, o1.w);
        unpack2(acc[2], o2.x, o2.y);
        unpack2(acc[3], o2.z, o2.w);
        g_aggr4[(size_t)n * 64 + lane * 2]     = o1;
        g_aggr4[(size_t)n * 64 + lane * 2 + 1] = o2;
    }
}

// ------------------------------ output GEMM --------------------------------
// out = tanh(aggr[N,256] @ W_out[256,128] + b_out); 128x128 tile, BK=32.
// 8x8 microtile packed as 8x4 f32x2 column pairs.
#define GBM 128
#define GBK 32

__global__ void __launch_bounds__(256) k_out(
    const float* __restrict__ W,
    const float* __restrict__ bo,
    float*       __restrict__ out)
{
    __shared__ float Ash[GBK][GBM];
    __shared__ float Bsh[GBK][OUT_CH];

    const int tid = threadIdx.x;
    const int tx  = tid & 15;
    const int ty  = tid >> 4;
    const int row0 = blockIdx.x * GBM;

    const float* aggr = reinterpret_cast<const float*>(g_aggr4);

    u64 acc2[8][4];
    const u64 z = pack2(0.f, 0.f);
#pragma unroll
    for (int i = 0; i < 8; i++)
#pragma unroll
        for (int jj = 0; jj < 4; jj++) acc2[i][jj] = z;

    for (int k0 = 0; k0 < CH_TOT; k0 += GBK) {
        // A tile: 128 rows x 32 k -> transposed Ash[k][row]; 1024 float4 total
#pragma unroll
        for (int g = 0; g < 4; g++) {
            int gi = tid * 4 + g;
            int r  = gi >> 3;             // 0..127
            int kq = gi & 7;              // 0..7 (float4 within 32 k)
            int row = row0 + r;
            float4 v = make_float4(0.f, 0.f, 0.f, 0.f);
            if (row < N_NODES)
                v = *reinterpret_cast<const float4*>(&aggr[(size_t)row * 256 + k0 + kq * 4]);
            Ash[kq * 4 + 0][r] = v.x;
            Ash[kq * 4 + 1][r] = v.y;
            Ash[kq * 4 + 2][r] = v.z;
            Ash[kq * 4 + 3][r] = v.w;
        }
        // B tile: 32 k x 128 cols; 1024 float4 total
#pragma unroll
        for (int g = 0; g < 4; g++) {
            int gi = tid * 4 + g;
            int k  = gi >> 5;             // 0..31
            int nq = gi & 31;
            *reinterpret_cast<float4*>(&Bsh[k][nq * 4]) =
                *reinterpret_cast<const float4*>(&W[(size_t)(k0 + k) * 128 + nq * 4]);
        }
        __syncthreads();

#pragma unroll
        for (int kk = 0; kk < GBK; kk++) {
            float a[8];
            *reinterpret_cast<float4*>(&a[0]) = *reinterpret_cast<float4*>(&Ash[kk][ty * 8]);
            *reinterpret_cast<float4*>(&a[4]) = *reinterpret_cast<float4*>(&Ash[kk][ty * 8 + 4]);
            ulonglong2 b01 = *reinterpret_cast<ulonglong2*>(&Bsh[kk][tx * 8]);
            ulonglong2 b23 = *reinterpret_cast<ulonglong2*>(&Bsh[kk][tx * 8 + 4]);
            u64 b2[4] = {b01.x, b01.y, b23.x, b23.y};
#pragma unroll
            for (int i = 0; i < 8; i++) {
                u64 ap = pack2(a[i], a[i]);
#pragma unroll
                for (int jj = 0; jj < 4; jj++)
                    acc2[i][jj] = fma2(ap, b2[jj], acc2[i][jj]);
            }
        }
        __syncthreads();
    }

    float bias[8];
#pragma unroll
    for (int j = 0; j < 8; j++) bias[j] = __ldg(&bo[tx * 8 + j]);

#pragma unroll
    for (int i = 0; i < 8; i++) {
        int row = row0 + ty * 8 + i;
        if (row < N_NODES) {
            float v[8];
#pragma unroll
            for (int jj = 0; jj < 4; jj++)
                unpack2(acc2[i][jj], v[2 * jj], v[2 * jj + 1]);
            float4 o1, o2;
            o1.x = tanhf(v[0] + bias[0]);
            o1.y = tanhf(v[1] + bias[1]);
            o1.z = tanhf(v[2] + bias[2]);
            o1.w = tanhf(v[3] + bias[3]);
            o2.x = tanhf(v[4] + bias[4]);
            o2.y = tanhf(v[5] + bias[5]);
            o2.z = tanhf(v[6] + bias[6]);
            o2.w = tanhf(v[7] + bias[7]);
            *reinterpret_cast<float4*>(&out[(size_t)row * 128 + tx * 8])     = o1;
            *reinterpret_cast<float4*>(&out[(size_t)row * 128 + tx * 8 + 4]) = o2;
        }
    }
}

// ------------------------------ launch -------------------------------------
extern "C" void kernel_launch(void* const* d_in, const int* in_sizes, int n_in,
                              void* d_out, int out_size)
{
    const float* x     = (const float*)d_in[0];
    const float* na    = (const float*)d_in[1];
    const void*  ei    = d_in[2];
    const float* ea    = (const float*)d_in[3];
    const float* W_in  = (const float*)d_in[4];
    const float* b_in  = (const float*)d_in[5];
    const float* W_out = (const float*)d_in[6];
    const float* b_out = (const float*)d_in[7];
    float* out = (float*)d_out;

    k_probe<<<(N_NODES + 255) / 256, 256>>>((const long long*)ei);
    k_init<<<4096, 256>>>(x, na, ei);

    k_scan1<<<N_SCAN_BLOCKS, SCAN_BLK>>>();
    k_scan2<<<1, 256>>>();
    k_scan3<<<(N_NODES + 255) / 256, 256>>>();
    k_fill<<<2048, 256>>>(ei, ea);

    k_aggr<<<4096, 128>>>(W_in, b_in);

    const int gemm_blocks = (N_NODES + GBM - 1) / GBM;
    k_out<<<gemm_blocks, 256>>>(W_out, b_out, out);
}

// round 6
// speedup vs baseline: 1.5946x; 1.0911x over previous
#include <cuda_runtime.h>
#include <math.h>

#define N_NODES 100000
#define N_EDGES 1600000
#define IN_CH   128
#define HIDDEN  2
#define OUT_CH  128
#define ATTR    6
#define CH_TOT  (IN_CH * HIDDEN)   // 256

typedef unsigned long long u64;

// ------------------------------ scratch ------------------------------------
__device__ float4 g_xc4[(size_t)N_NODES * IN_CH / 4];    // concat(x,node_attr) 51.2MB
__device__ float4 g_aggr4[(size_t)N_NODES * CH_TOT / 4]; // per-node aggregate 102.4MB
__device__ float4 g_erec[(size_t)2 * N_EDGES];           // CSR-ordered (src,e0..e5) 51.2MB
__device__ int    g_deg[N_NODES];
__device__ int    g_rowptr[N_NODES + 1];
__device__ int    g_cursor[N_NODES];
__device__ int    g_ei_is64;

#define SCAN_BLK 512
#define N_SCAN_BLOCKS ((N_NODES + SCAN_BLK - 1) / SCAN_BLK)  // 196
__device__ int g_blockSums[N_SCAN_BLOCKS];

// ------------------------------ f32x2 helpers ------------------------------
__device__ __forceinline__ u64 pack2(float lo, float hi) {
    u64 d; asm("mov.b64 %0, {%1, %2};" : "=l"(d) : "f"(lo), "f"(hi)); return d;
}
__device__ __forceinline__ void unpack2(u64 d, float& lo, float& hi) {
    asm("mov.b64 {%0, %1}, %2;" : "=f"(lo), "=f"(hi) : "l"(d));
}
__device__ __forceinline__ u64 fma2(u64 a, u64 b, u64 c) {
    u64 d; asm("fma.rn.f32x2 %0, %1, %2, %3;" : "=l"(d) : "l"(a), "l"(b), "l"(c)); return d;
}

// ------------------------------ probe + zero -------------------------------
// Warp 0 of block 0 checks 256 leading values in parallel (8 per lane).
__global__ void k_probe(const long long* __restrict__ ei)
{
    int i = blockIdx.x * blockDim.x + threadIdx.x;
    if (i < N_NODES) g_deg[i] = 0;
    if (blockIdx.x == 0 && threadIdx.x < 32) {
        int bad = 0;
#pragma unroll
        for (int j = 0; j < 8; j++) {
            long long v = ei[threadIdx.x * 8 + j];
            if (v < 0 || v >= N_NODES) bad = 1;
        }
        unsigned m = __ballot_sync(0xFFFFFFFFu, bad);
        if (threadIdx.x == 0) g_ei_is64 = (m == 0) ? 1 : 0;
    }
}

__device__ __forceinline__ int load_idx(const void* p, int is64, size_t i)
{
    return is64 ? (int)((const long long*)p)[i] : ((const int*)p)[i];
}

// ------------------- init: build xc + histogram dst degrees ----------------
__global__ void k_init(const float* __restrict__ x, const float* __restrict__ na,
                       const void* __restrict__ ei)
{
    size_t i = (size_t)blockIdx.x * blockDim.x + threadIdx.x;
    size_t stride = (size_t)gridDim.x * blockDim.x;
    const int is64 = g_ei_is64;

    float* xc = reinterpret_cast<float*>(g_xc4);
    const size_t n_xc = (size_t)N_NODES * IN_CH;
    for (size_t j = i; j < n_xc; j += stride) {
        int n = (int)(j >> 7);
        int c = (int)(j & 127);
        xc[j] = (c < 127) ? x[(size_t)n * 127 + c] : na[n];
    }

    for (size_t e = i; e < N_EDGES; e += stride) {
        int dst = load_idx(ei, is64, (size_t)N_EDGES + e);
        atomicAdd(&g_deg[dst], 1);
    }
}

// ------------------------------ CSR scan -----------------------------------
__global__ void k_scan1()
{
    __shared__ int s[SCAN_BLK];
    int t = threadIdx.x;
    int idx = blockIdx.x * SCAN_BLK + t;
    int v = (idx < N_NODES) ? g_deg[idx] : 0;
    s[t] = v;
    __syncthreads();
#pragma unroll
    for (int off = 1; off < SCAN_BLK; off <<= 1) {
        int tv = (t >= off) ? s[t - off] : 0;
        __syncthreads();
        s[t] += tv;
        __syncthreads();
    }
    if (idx < N_NODES) g_rowptr[idx] = s[t] - v;
    if (t == SCAN_BLK - 1) g_blockSums[blockIdx.x] = s[t];
}

__global__ void k_scan2()
{
    __shared__ int s[256];
    int t = threadIdx.x;
    int v = (t < N_SCAN_BLOCKS) ? g_blockSums[t] : 0;
    s[t] = v;
    __syncthreads();
#pragma unroll
    for (int off = 1; off < 256; off <<= 1) {
        int tv = (t >= off) ? s[t - off] : 0;
        __syncthreads();
        s[t] += tv;
        __syncthreads();
    }
    if (t < N_SCAN_BLOCKS) g_blockSums[t] = s[t] - v;  // exclusive
}

__global__ void k_scan3()
{
    int idx = blockIdx.x * blockDim.x + threadIdx.x;
    if (idx < N_NODES) {
        int rp = g_rowptr[idx] + g_blockSums[idx / SCAN_BLK];
        g_rowptr[idx] = rp;
        g_cursor[idx] = rp;
    }
    if (idx == 0) g_rowptr[N_NODES] = N_EDGES;
}

// ----------------- fill: CSR-ordered edge records (src + attrs) ------------
__global__ void k_fill(const void* __restrict__ ei, const float* __restrict__ ea)
{
    const int is64 = g_ei_is64;
    const float2* ea2 = reinterpret_cast<const float2*>(ea);
    int i = blockIdx.x * blockDim.x + threadIdx.x;
    int stride = gridDim.x * blockDim.x;
    for (int e = i; e < N_EDGES; e += stride) {
        int src = load_idx(ei, is64, e);
        int dst = load_idx(ei, is64, (size_t)N_EDGES + e);
        float2 a01 = __ldg(&ea2[(size_t)e * 3]);
        float2 a23 = __ldg(&ea2[(size_t)e * 3 + 1]);
        float2 a45 = __ldg(&ea2[(size_t)e * 3 + 2]);
        int pos = atomicAdd(&g_cursor[dst], 1);
        g_erec[(size_t)2 * pos]     = make_float4(__int_as_float(src), a01.x, a01.y, a23.x);
        g_erec[(size_t)2 * pos + 1] = make_float4(a23.y, a45.x, a45.y, 0.f);
    }
}

// ------------------------------ aggregation --------------------------------
// One warp per dst node. Lane t owns channels [4t,4t+4); flat outputs
// j = lane*8 + 2*jj + h (pair over h via f32x2). W_in slices register-resident.
// Cache policy: erec streamed (__ldcs), aggr writes streamed (__stcs),
// xc gathers default -> xc (51MB, 16x reuse) stays resident in L2.
struct LaneW {
    u64 w2[6][4];
    u64 b2[4];
};

__device__ __forceinline__ void edge_accum(
    u64 acc[4], const LaneW& lw, float4 ra, float4 rb, float4 xj)
{
    u64 ee[6];
    ee[0] = pack2(ra.y, ra.y);  ee[1] = pack2(ra.z, ra.z);  ee[2] = pack2(ra.w, ra.w);
    ee[3] = pack2(rb.x, rb.x);  ee[4] = pack2(rb.y, rb.y);  ee[5] = pack2(rb.z, rb.z);
#pragma unroll
    for (int jj = 0; jj < 4; jj++) {
        u64 s = lw.b2[jj];
#pragma unroll
        for (int a = 0; a < 6; a++) s = fma2(ee[a], lw.w2[a][jj], s);
        float lo, hi;
        unpack2(s, lo, hi);
        lo = fmaxf(lo, 0.f);
        hi = fmaxf(hi, 0.f);
        float xv = (jj == 0) ? xj.x : (jj == 1) ? xj.y : (jj == 2) ? xj.z : xj.w;
        acc[jj] = fma2(pack2(lo, hi), pack2(xv, xv), acc[jj]);
    }
}

__global__ void __launch_bounds__(128, 4) k_aggr(
    const float* __restrict__ W_in,  // [6, 256]
    const float* __restrict__ b_in)  // [256]
{
    const int lane   = threadIdx.x & 31;
    const int warp   = blockIdx.x * (blockDim.x >> 5) + (threadIdx.x >> 5);
    const int nwarps = gridDim.x * (blockDim.x >> 5);

    LaneW lw;
#pragma unroll
    for (int jj = 0; jj < 4; jj++) {
        int j0 = lane * 8 + 2 * jj;
        lw.b2[jj] = pack2(__ldg(&b_in[j0]), __ldg(&b_in[j0 + 1]));
#pragma unroll
        for (int a = 0; a < 6; a++)
            lw.w2[a][jj] = pack2(__ldg(&W_in[a * 256 + j0]),
                                 __ldg(&W_in[a * 256 + j0 + 1]));
    }

    const u64 z = pack2(0.f, 0.f);

    for (int n = warp; n < N_NODES; n += nwarps) {
        int beg = g_rowptr[n];
        int end = g_rowptr[n + 1];

        u64 acc[4] = {z, z, z, z};

        int idx = beg;
        // 4-edge unroll: all records + gathers in flight before compute
        for (; idx + 4 <= end; idx += 4) {
            float4 ra[4], rb[4], xv[4];
#pragma unroll
            for (int j = 0; j < 4; j++) {
                ra[j] = __ldcs(&g_erec[(size_t)2 * (idx + j)]);
                rb[j] = __ldcs(&g_erec[(size_t)2 * (idx + j) + 1]);
            }
#pragma unroll
            for (int j = 0; j < 4; j++) {
                int src = __float_as_int(ra[j].x);
                xv[j] = __ldg(&g_xc4[(size_t)src * 32 + lane]);
            }
#pragma unroll
            for (int j = 0; j < 4; j++)
                edge_accum(acc, lw, ra[j], rb[j], xv[j]);
        }
        for (; idx < end; idx++) {
            float4 ra = __ldcs(&g_erec[(size_t)2 * idx]);
            float4 rb = __ldcs(&g_erec[(size_t)2 * idx + 1]);
            int src = __float_as_int(ra.x);
            float4 xv = __ldg(&g_xc4[(size_t)src * 32 + lane]);
            edge_accum(acc, lw, ra, rb, xv);
        }

        float4 o1, o2;
        unpack2(acc[0], o1.x, o1.y);
        unpack2(acc[1], o1.z, o1.w);
        unpack2(acc[2], o2.x, o2.y);
        unpack2(acc[3], o2.z, o2.w);
        __stcs(&g_aggr4[(size_t)n * 64 + lane * 2],     o1);
        __stcs(&g_aggr4[(size_t)n * 64 + lane * 2 + 1], o2);
    }
}

// ------------------------------ output GEMM --------------------------------
// out = tanh(aggr[N,256] @ W_out[256,128] + b_out); 128x128 tile, BK=32.
// 8x8 microtile packed as 8x4 f32x2 column pairs.
#define GBM 128
#define GBK 32

__global__ void __launch_bounds__(256) k_out(
    const float* __restrict__ W,
    const float* __restrict__ bo,
    float*       __restrict__ out)
{
    __shared__ float Ash[GBK][GBM];
    __shared__ float Bsh[GBK][OUT_CH];

    const int tid = threadIdx.x;
    const int tx  = tid & 15;
    const int ty  = tid >> 4;
    const int row0 = blockIdx.x * GBM;

    u64 acc2[8][4];
    const u64 z = pack2(0.f, 0.f);
#pragma unroll
    for (int i = 0; i < 8; i++)
#pragma unroll
        for (int jj = 0; jj < 4; jj++) acc2[i][jj] = z;

    for (int k0 = 0; k0 < CH_TOT; k0 += GBK) {
        // A tile: 128 rows x 32 k -> transposed Ash[k][row]
#pragma unroll
        for (int g = 0; g < 4; g++) {
            int gi = tid * 4 + g;
            int r  = gi >> 3;
            int kq = gi & 7;
            int row = row0 + r;
            float4 v = make_float4(0.f, 0.f, 0.f, 0.f);
            if (row < N_NODES)
                v = __ldcs(&g_aggr4[((size_t)row * 256 + k0 + kq * 4) / 4]);
            Ash[kq * 4 + 0][r] = v.x;
            Ash[kq * 4 + 1][r] = v.y;
            Ash[kq * 4 + 2][r] = v.z;
            Ash[kq * 4 + 3][r] = v.w;
        }
        // B tile: 32 k x 128 cols
#pragma unroll
        for (int g = 0; g < 4; g++) {
            int gi = tid * 4 + g;
            int k  = gi >> 5;
            int nq = gi & 31;
            *reinterpret_cast<float4*>(&Bsh[k][nq * 4]) =
                *reinterpret_cast<const float4*>(&W[(size_t)(k0 + k) * 128 + nq * 4]);
        }
        __syncthreads();

#pragma unroll
        for (int kk = 0; kk < GBK; kk++) {
            float a[8];
            *reinterpret_cast<float4*>(&a[0]) = *reinterpret_cast<float4*>(&Ash[kk][ty * 8]);
            *reinterpret_cast<float4*>(&a[4]) = *reinterpret_cast<float4*>(&Ash[kk][ty * 8 + 4]);
            ulonglong2 b01 = *reinterpret_cast<ulonglong2*>(&Bsh[kk][tx * 8]);
            ulonglong2 b23 = *reinterpret_cast<ulonglong2*>(&Bsh[kk][tx * 8 + 4]);
            u64 b2[4] = {b01.x, b01.y, b23.x, b23.y};
#pragma unroll
            for (int i = 0; i < 8; i++) {
                u64 ap = pack2(a[i], a[i]);
#pragma unroll
                for (int jj = 0; jj < 4; jj++)
                    acc2[i][jj] = fma2(ap, b2[jj], acc2[i][jj]);
            }
        }
        __syncthreads();
    }

    float bias[8];
#pragma unroll
    for (int j = 0; j < 8; j++) bias[j] = __ldg(&bo[tx * 8 + j]);

#pragma unroll
    for (int i = 0; i < 8; i++) {
        int row = row0 + ty * 8 + i;
        if (row < N_NODES) {
            float v[8];
#pragma unroll
            for (int jj = 0; jj < 4; jj++)
                unpack2(acc2[i][jj], v[2 * jj], v[2 * jj + 1]);
            float4 o1, o2;
            o1.x = tanhf(v[0] + bias[0]);
            o1.y = tanhf(v[1] + bias[1]);
            o1.z = tanhf(v[2] + bias[2]);
            o1.w = tanhf(v[3] + bias[3]);
            o2.x = tanhf(v[4] + bias[4]);
            o2.y = tanhf(v[5] + bias[5]);
            o2.z = tanhf(v[6] + bias[6]);
            o2.w = tanhf(v[7] + bias[7]);
            *reinterpret_cast<float4*>(&out[(size_t)row * 128 + tx * 8])     = o1;
            *reinterpret_cast<float4*>(&out[(size_t)row * 128 + tx * 8 + 4]) = o2;
        }
    }
}

// ------------------------------ launch -------------------------------------
extern "C" void kernel_launch(void* const* d_in, const int* in_sizes, int n_in,
                              void* d_out, int out_size)
{
    const float* x     = (const float*)d_in[0];
    const float* na    = (const float*)d_in[1];
    const void*  ei    = d_in[2];
    const float* ea    = (const float*)d_in[3];
    const float* W_in  = (const float*)d_in[4];
    const float* b_in  = (const float*)d_in[5];
    const float* W_out = (const float*)d_in[6];
    const float* b_out = (const float*)d_in[7];
    float* out = (float*)d_out;

    k_probe<<<(N_NODES + 255) / 256, 256>>>((const long long*)ei);
    k_init<<<4096, 256>>>(x, na, ei);

    k_scan1<<<N_SCAN_BLOCKS, SCAN_BLK>>>();
    k_scan2<<<1, 256>>>();
    k_scan3<<<(N_NODES + 255) / 256, 256>>>();
    k_fill<<<2048, 256>>>(ei, ea);

    k_aggr<<<4096, 128>>>(W_in, b_in);

    const int gemm_blocks = (N_NODES + GBM - 1) / GBM;
    k_out<<<gemm_blocks, 256>>>(W_out, b_out, out);
}

// round 7
// speedup vs baseline: 1.7018x; 1.0672x over previous
#include <cuda_runtime.h>
#include <math.h>

#define N_NODES 100000
#define N_EDGES 1600000
#define IN_CH   128
#define HIDDEN  2
#define OUT_CH  128
#define ATTR    6
#define CH_TOT  (IN_CH * HIDDEN)   // 256

typedef unsigned long long u64;

// ------------------------------ scratch ------------------------------------
__device__ float4 g_xc4[(size_t)N_NODES * IN_CH / 4];    // concat(x,node_attr) 51.2MB
__device__ float4 g_aggr4[(size_t)N_NODES * CH_TOT / 4]; // per-node aggregate 102.4MB
__device__ float4 g_erec[(size_t)2 * N_EDGES];           // CSR (src,a0,a1,a2)(a3,a4,a5,dst)
__device__ int    g_deg[N_NODES];
__device__ int    g_rowptr[N_NODES + 1];
__device__ int    g_cursor[N_NODES];
__device__ int    g_ei_is64;

#define SCAN_BLK 512
#define N_SCAN_BLOCKS ((N_NODES + SCAN_BLK - 1) / SCAN_BLK)  // 196
__device__ int g_blockSums[N_SCAN_BLOCKS];

// ------------------------------ f32x2 helpers ------------------------------
__device__ __forceinline__ u64 pack2(float lo, float hi) {
    u64 d; asm("mov.b64 %0, {%1, %2};" : "=l"(d) : "f"(lo), "f"(hi)); return d;
}
__device__ __forceinline__ void unpack2(u64 d, float& lo, float& hi) {
    asm("mov.b64 {%0, %1}, %2;" : "=f"(lo), "=f"(hi) : "l"(d));
}
__device__ __forceinline__ u64 fma2(u64 a, u64 b, u64 c) {
    u64 d; asm("fma.rn.f32x2 %0, %1, %2, %3;" : "=l"(d) : "l"(a), "l"(b), "l"(c)); return d;
}

// ------------------------------ cp.async helpers ---------------------------
__device__ __forceinline__ void cp16(void* smem, const void* gmem) {
    unsigned s = (unsigned)__cvta_generic_to_shared(smem);
    asm volatile("cp.async.cg.shared.global [%0], [%1], 16;" :: "r"(s), "l"(gmem) : "memory");
}
#define CP_COMMIT() asm volatile("cp.async.commit_group;" ::: "memory")
#define CP_WAIT1()  asm volatile("cp.async.wait_group 1;" ::: "memory")
#define CP_WAIT0()  asm volatile("cp.async.wait_group 0;" ::: "memory")

// ------------------------------ probe + zero -------------------------------
__global__ void k_probe(const long long* __restrict__ ei)
{
    int i = blockIdx.x * blockDim.x + threadIdx.x;
    if (i < N_NODES) g_deg[i] = 0;
    if (blockIdx.x == 0 && threadIdx.x < 32) {
        int bad = 0;
#pragma unroll
        for (int j = 0; j < 8; j++) {
            long long v = ei[threadIdx.x * 8 + j];
            if (v < 0 || v >= N_NODES) bad = 1;
        }
        unsigned m = __ballot_sync(0xFFFFFFFFu, bad);
        if (threadIdx.x == 0) g_ei_is64 = (m == 0) ? 1 : 0;
    }
}

__device__ __forceinline__ int load_idx(const void* p, int is64, size_t i)
{
    return is64 ? (int)((const long long*)p)[i] : ((const int*)p)[i];
}

// ----------- init: build xc, zero aggr, histogram dst degrees --------------
__global__ void k_init(const float* __restrict__ x, const float* __restrict__ na,
                       const void* __restrict__ ei)
{
    size_t i = (size_t)blockIdx.x * blockDim.x + threadIdx.x;
    size_t stride = (size_t)gridDim.x * blockDim.x;
    const int is64 = g_ei_is64;

    const size_t n_aggr4 = (size_t)N_NODES * CH_TOT / 4;
    float4 z = make_float4(0.f, 0.f, 0.f, 0.f);
    for (size_t j = i; j < n_aggr4; j += stride) g_aggr4[j] = z;

    float* xc = reinterpret_cast<float*>(g_xc4);
    const size_t n_xc = (size_t)N_NODES * IN_CH;
    for (size_t j = i; j < n_xc; j += stride) {
        int n = (int)(j >> 7);
        int c = (int)(j & 127);
        xc[j] = (c < 127) ? x[(size_t)n * 127 + c] : na[n];
    }

    for (size_t e = i; e < N_EDGES; e += stride) {
        int dst = load_idx(ei, is64, (size_t)N_EDGES + e);
        atomicAdd(&g_deg[dst], 1);
    }
}

// ------------------------------ CSR scan -----------------------------------
__global__ void k_scan1()
{
    __shared__ int s[SCAN_BLK];
    int t = threadIdx.x;
    int idx = blockIdx.x * SCAN_BLK + t;
    int v = (idx < N_NODES) ? g_deg[idx] : 0;
    s[t] = v;
    __syncthreads();
#pragma unroll
    for (int off = 1; off < SCAN_BLK; off <<= 1) {
        int tv = (t >= off) ? s[t - off] : 0;
        __syncthreads();
        s[t] += tv;
        __syncthreads();
    }
    if (idx < N_NODES) g_rowptr[idx] = s[t] - v;
    if (t == SCAN_BLK - 1) g_blockSums[blockIdx.x] = s[t];
}

__global__ void k_scan2()
{
    __shared__ int s[256];
    int t = threadIdx.x;
    int v = (t < N_SCAN_BLOCKS) ? g_blockSums[t] : 0;
    s[t] = v;
    __syncthreads();
#pragma unroll
    for (int off = 1; off < 256; off <<= 1) {
        int tv = (t >= off) ? s[t - off] : 0;
        __syncthreads();
        s[t] += tv;
        __syncthreads();
    }
    if (t < N_SCAN_BLOCKS) g_blockSums[t] = s[t] - v;  // exclusive
}

__global__ void k_scan3()
{
    int idx = blockIdx.x * blockDim.x + threadIdx.x;
    if (idx < N_NODES) {
        int rp = g_rowptr[idx] + g_blockSums[idx / SCAN_BLK];
        g_rowptr[idx] = rp;
        g_cursor[idx] = rp;
    }
    if (idx == 0) g_rowptr[N_NODES] = N_EDGES;
}

// ----------------- fill: CSR-ordered edge records (src + attrs + dst) ------
__global__ void k_fill(const void* __restrict__ ei, const float* __restrict__ ea)
{
    const int is64 = g_ei_is64;
    const float2* ea2 = reinterpret_cast<const float2*>(ea);
    int i = blockIdx.x * blockDim.x + threadIdx.x;
    int stride = gridDim.x * blockDim.x;
    for (int e = i; e < N_EDGES; e += stride) {
        int src = load_idx(ei, is64, e);
        int dst = load_idx(ei, is64, (size_t)N_EDGES + e);
        float2 a01 = __ldg(&ea2[(size_t)e * 3]);
        float2 a23 = __ldg(&ea2[(size_t)e * 3 + 1]);
        float2 a45 = __ldg(&ea2[(size_t)e * 3 + 2]);
        int pos = atomicAdd(&g_cursor[dst], 1);
        g_erec[(size_t)2 * pos]     = make_float4(__int_as_float(src), a01.x, a01.y, a23.x);
        g_erec[(size_t)2 * pos + 1] = make_float4(a23.y, a45.x, a45.y, __int_as_float(dst));
    }
}

// ------------------------------ aggregation --------------------------------
// Flat CSR ranges per warp + cp.async double-level pipeline.
// Lane t owns outputs j = t*8 + 2*jj + h (f32x2 over h).
#define AW    4    // warps per block
#define ACH   4    // edges per chunk
#define XBUF  3    // xc buffers in flight
#define ESLOT 8    // erec ring slots

struct LaneW {
    u64 w2[6][4];
    u64 b2[4];
};

__device__ __forceinline__ void edge_accum(
    u64 acc[4], const LaneW& lw, float4 ra, float4 rb, float4 xj)
{
    u64 ee[6];
    ee[0] = pack2(ra.y, ra.y);  ee[1] = pack2(ra.z, ra.z);  ee[2] = pack2(ra.w, ra.w);
    ee[3] = pack2(rb.x, rb.x);  ee[4] = pack2(rb.y, rb.y);  ee[5] = pack2(rb.z, rb.z);
#pragma unroll
    for (int jj = 0; jj < 4; jj++) {
        u64 s = lw.b2[jj];
#pragma unroll
        for (int a = 0; a < 6; a++) s = fma2(ee[a], lw.w2[a][jj], s);
        float lo, hi;
        unpack2(s, lo, hi);
        lo = fmaxf(lo, 0.f);
        hi = fmaxf(hi, 0.f);
        float xv = (jj == 0) ? xj.x : (jj == 1) ? xj.y : (jj == 2) ? xj.z : xj.w;
        acc[jj] = fma2(pack2(lo, hi), pack2(xv, xv), acc[jj]);
    }
}

__device__ __forceinline__ void flush_acc(u64 acc[4], int node, int lane, bool use_atomic)
{
    float4 o1, o2;
    unpack2(acc[0], o1.x, o1.y);
    unpack2(acc[1], o1.z, o1.w);
    unpack2(acc[2], o2.x, o2.y);
    unpack2(acc[3], o2.z, o2.w);
    float* p = reinterpret_cast<float*>(g_aggr4) + (size_t)node * 256 + lane * 8;
    if (use_atomic) {
        asm volatile("red.global.add.v4.f32 [%0], {%1,%2,%3,%4};"
                     :: "l"(p), "f"(o1.x), "f"(o1.y), "f"(o1.z), "f"(o1.w) : "memory");
        asm volatile("red.global.add.v4.f32 [%0], {%1,%2,%3,%4};"
                     :: "l"(p + 4), "f"(o2.x), "f"(o2.y), "f"(o2.z), "f"(o2.w) : "memory");
    } else {
        __stcs(reinterpret_cast<float4*>(p),     o1);
        __stcs(reinterpret_cast<float4*>(p) + 1, o2);
    }
    const u64 z = pack2(0.f, 0.f);
    acc[0] = z; acc[1] = z; acc[2] = z; acc[3] = z;
}

__global__ void __launch_bounds__(32 * AW, 4) k_aggr(
    const float* __restrict__ W_in,  // [6, 256]
    const float* __restrict__ b_in)  // [256]
{
    __shared__ float4 sx[AW][XBUF][ACH][32];   // 24 KB
    __shared__ float4 se[AW][ESLOT][ACH][2];   //  4 KB

    const int lane = threadIdx.x & 31;
    const int w    = threadIdx.x >> 5;
    const int wid  = blockIdx.x * AW + w;
    const int wtot = gridDim.x * AW;

    LaneW lw;
#pragma unroll
    for (int jj = 0; jj < 4; jj++) {
        int j0 = lane * 8 + 2 * jj;
        lw.b2[jj] = pack2(__ldg(&b_in[j0]), __ldg(&b_in[j0 + 1]));
#pragma unroll
        for (int a = 0; a < 6; a++)
            lw.w2[a][jj] = pack2(__ldg(&W_in[a * 256 + j0]),
                                 __ldg(&W_in[a * 256 + j0 + 1]));
    }

    const int chunks_total = (N_EDGES + ACH - 1) / ACH;
    const int cpw  = (chunks_total + wtot - 1) / wtot;
    const int c0   = wid * cpw;
    const int c1   = min(c0 + cpw, chunks_total);
    if (c0 >= c1) return;
    const int nch  = c1 - c0;
    const int eend = min(c1 * ACH, N_EDGES);

    // ---- issue erec chunk c (relative) into ring slot c&7; lanes 0-7 ----
    auto issue_erec = [&](int c) {
        if (c < nch && lane < 8) {
            size_t fbase = (size_t)(c0 + c) * (2 * ACH);  // float4 index
            if (fbase + lane < (size_t)2 * N_EDGES)
                cp16(&se[w][c & (ESLOT - 1)][lane >> 1][lane & 1], &g_erec[fbase + lane]);
        }
    };
    // ---- issue xc gathers for chunk c (needs erec c in smem) ----
    auto issue_xc = [&](int c) {
        if (c < nch) {
            int b = c % XBUF;
#pragma unroll
            for (int j = 0; j < ACH; j++) {
                int e = (c0 + c) * ACH + j;
                if (e < eend) {
                    int src = __float_as_int(se[w][c & (ESLOT - 1)][j][0].x);
                    cp16(&sx[w][b][j][lane], &g_xc4[(size_t)src * 32 + lane]);
                }
            }
        }
    };

    // ---- prologue: erec 0..2; then groups B{xc0,erec3}, C{xc1,erec4} ----
    issue_erec(0); issue_erec(1); issue_erec(2);
    CP_COMMIT();
    CP_WAIT0();
    __syncwarp();
    issue_xc(0); issue_erec(3); CP_COMMIT();
    issue_xc(1); issue_erec(4); CP_COMMIT();

    const u64 z = pack2(0.f, 0.f);
    u64 acc[4] = {z, z, z, z};
    int  cur = -1;
    bool first = true;

    for (int i = 0; i < nch; i++) {
        CP_WAIT1();          // chunk i's xc + erec i+3 complete
        __syncwarp();
        issue_xc(i + 2);     // erec i+2 already resident
        issue_erec(i + 5);
        CP_COMMIT();

        int b = i % XBUF;
        int s = i & (ESLOT - 1);
#pragma unroll
        for (int j = 0; j < ACH; j++) {
            int e = (c0 + i) * ACH + j;
            if (e >= eend) break;
            float4 ra = se[w][s][j][0];
            float4 rb = se[w][s][j][1];
            int dst = __float_as_int(rb.w);
            if (dst != cur) {
                if (cur >= 0) {
                    flush_acc(acc, cur, lane, first);
                    first = false;
                }
                cur = dst;
            }
            float4 xj = sx[w][b][j][lane];
            edge_accum(acc, lw, ra, rb, xj);
        }
    }
    if (cur >= 0) flush_acc(acc, cur, lane, true);  // boundary node: atomic
}

// ------------------------------ output GEMM --------------------------------
// out = tanh(aggr[N,256] @ W_out[256,128] + b_out); 128x128 tile, BK=32.
#define GBM 128
#define GBK 32

__global__ void __launch_bounds__(256) k_out(
    const float* __restrict__ W,
    const float* __restrict__ bo,
    float*       __restrict__ out)
{
    __shared__ float Ash[GBK][GBM];
    __shared__ float Bsh[GBK][OUT_CH];

    const int tid = threadIdx.x;
    const int tx  = tid & 15;
    const int ty  = tid >> 4;
    const int row0 = blockIdx.x * GBM;

    u64 acc2[8][4];
    const u64 z = pack2(0.f, 0.f);
#pragma unroll
    for (int i = 0; i < 8; i++)
#pragma unroll
        for (int jj = 0; jj < 4; jj++) acc2[i][jj] = z;

    for (int k0 = 0; k0 < CH_TOT; k0 += GBK) {
#pragma unroll
        for (int g = 0; g < 4; g++) {
            int gi = tid * 4 + g;
            int r  = gi >> 3;
            int kq = gi & 7;
            int row = row0 + r;
            float4 v = make_float4(0.f, 0.f, 0.f, 0.f);
            if (row < N_NODES)
                v = __ldcs(&g_aggr4[((size_t)row * 256 + k0 + kq * 4) / 4]);
            Ash[kq * 4 + 0][r] = v.x;
            Ash[kq * 4 + 1][r] = v.y;
            Ash[kq * 4 + 2][r] = v.z;
            Ash[kq * 4 + 3][r] = v.w;
        }
#pragma unroll
        for (int g = 0; g < 4; g++) {
            int gi = tid * 4 + g;
            int k  = gi >> 5;
            int nq = gi & 31;
            *reinterpret_cast<float4*>(&Bsh[k][nq * 4]) =
                *reinterpret_cast<const float4*>(&W[(size_t)(k0 + k) * 128 + nq * 4]);
        }
        __syncthreads();

#pragma unroll
        for (int kk = 0; kk < GBK; kk++) {
            float a[8];
            *reinterpret_cast<float4*>(&a[0]) = *reinterpret_cast<float4*>(&Ash[kk][ty * 8]);
            *reinterpret_cast<float4*>(&a[4]) = *reinterpret_cast<float4*>(&Ash[kk][ty * 8 + 4]);
            ulonglong2 b01 = *reinterpret_cast<ulonglong2*>(&Bsh[kk][tx * 8]);
            ulonglong2 b23 = *reinterpret_cast<ulonglong2*>(&Bsh[kk][tx * 8 + 4]);
            u64 b2[4] = {b01.x, b01.y, b23.x, b23.y};
#pragma unroll
            for (int i = 0; i < 8; i++) {
                u64 ap = pack2(a[i], a[i]);
#pragma unroll
                for (int jj = 0; jj < 4; jj++)
                    acc2[i][jj] = fma2(ap, b2[jj], acc2[i][jj]);
            }
        }
        __syncthreads();
    }

    float bias[8];
#pragma unroll
    for (int j = 0; j < 8; j++) bias[j] = __ldg(&bo[tx * 8 + j]);

#pragma unroll
    for (int i = 0; i < 8; i++) {
        int row = row0 + ty * 8 + i;
        if (row < N_NODES) {
            float v[8];
#pragma unroll
            for (int jj = 0; jj < 4; jj++)
                unpack2(acc2[i][jj], v[2 * jj], v[2 * jj + 1]);
            float4 o1, o2;
            o1.x = tanhf(v[0] + bias[0]);
            o1.y = tanhf(v[1] + bias[1]);
            o1.z = tanhf(v[2] + bias[2]);
            o1.w = tanhf(v[3] + bias[3]);
            o2.x = tanhf(v[4] + bias[4]);
            o2.y = tanhf(v[5] + bias[5]);
            o2.z = tanhf(v[6] + bias[6]);
            o2.w = tanhf(v[7] + bias[7]);
            *reinterpret_cast<float4*>(&out[(size_t)row * 128 + tx * 8])     = o1;
            *reinterpret_cast<float4*>(&out[(size_t)row * 128 + tx * 8 + 4]) = o2;
        }
    }
}

// ------------------------------ launch -------------------------------------
extern "C" void kernel_launch(void* const* d_in, const int* in_sizes, int n_in,
                              void* d_out, int out_size)
{
    const float* x     = (const float*)d_in[0];
    const float* na    = (const float*)d_in[1];
    const void*  ei    = d_in[2];
    const float* ea    = (const float*)d_in[3];
    const float* W_in  = (const float*)d_in[4];
    const float* b_in  = (const float*)d_in[5];
    const float* W_out = (const float*)d_in[6];
    const float* b_out = (const float*)d_in[7];
    float* out = (float*)d_out;

    k_probe<<<(N_NODES + 255) / 256, 256>>>((const long long*)ei);
    k_init<<<4096, 256>>>(x, na, ei);

    k_scan1<<<N_SCAN_BLOCKS, SCAN_BLK>>>();
    k_scan2<<<1, 256>>>();
    k_scan3<<<(N_NODES + 255) / 256, 256>>>();
    k_fill<<<2048, 256>>>(ei, ea);

    k_aggr<<<592, 32 * AW>>>(W_in, b_in);

    const int gemm_blocks = (N_NODES + GBM - 1) / GBM;
    k_out<<<gemm_blocks, 256>>>(W_out, b_out, out);
}

// round 8
// speedup vs baseline: 2.2489x; 1.3215x over previous
#include <cuda_runtime.h>
#include <cuda_bf16.h>
#include <math.h>

#define N_NODES 100000
#define N_EDGES 1600000
#define IN_CH   128
#define HIDDEN  2
#define OUT_CH  128
#define ATTR    6
#define CH_TOT  (IN_CH * HIDDEN)   // 256

typedef unsigned long long u64;

// ------------------------------ scratch ------------------------------------
__device__ float4 g_xc4[(size_t)N_NODES * IN_CH / 4];    // concat(x,node_attr) 51.2MB
__device__ float4 g_aggr4[(size_t)N_NODES * CH_TOT / 4]; // per-node aggregate 102.4MB
__device__ float4 g_erec[(size_t)2 * N_EDGES];           // CSR (src,a0,a1,a2)(a3,a4,a5,dst)
__device__ int    g_deg[N_NODES];
__device__ int    g_rowptr[N_NODES + 1];
__device__ int    g_cursor[N_NODES];
__device__ int    g_ei_is64;

#define SCAN_BLK 512
#define N_SCAN_BLOCKS ((N_NODES + SCAN_BLK - 1) / SCAN_BLK)  // 196
__device__ int g_blockSums[N_SCAN_BLOCKS];

// ------------------------------ f32x2 helpers ------------------------------
__device__ __forceinline__ u64 pack2(float lo, float hi) {
    u64 d; asm("mov.b64 %0, {%1, %2};" : "=l"(d) : "f"(lo), "f"(hi)); return d;
}
__device__ __forceinline__ void unpack2(u64 d, float& lo, float& hi) {
    asm("mov.b64 {%0, %1}, %2;" : "=f"(lo), "=f"(hi) : "l"(d));
}
__device__ __forceinline__ u64 fma2(u64 a, u64 b, u64 c) {
    u64 d; asm("fma.rn.f32x2 %0, %1, %2, %3;" : "=l"(d) : "l"(a), "l"(b), "l"(c)); return d;
}

// ------------------------------ cp.async helpers ---------------------------
__device__ __forceinline__ void cp16(void* smem, const void* gmem) {
    unsigned s = (unsigned)__cvta_generic_to_shared(smem);
    asm volatile("cp.async.cg.shared.global [%0], [%1], 16;" :: "r"(s), "l"(gmem) : "memory");
}
#define CP_COMMIT() asm volatile("cp.async.commit_group;" ::: "memory")
#define CP_WAIT1()  asm volatile("cp.async.wait_group 1;" ::: "memory")
#define CP_WAIT0()  asm volatile("cp.async.wait_group 0;" ::: "memory")

// ------------------------------ bf16 helpers -------------------------------
__device__ __forceinline__ unsigned short f2bf(float a) {
    unsigned short h; asm("cvt.rn.bf16.f32 %0, %1;" : "=h"(h) : "f"(a)); return h;
}
__device__ __forceinline__ float bf2f(unsigned short h) {
    return __uint_as_float(((unsigned)h) << 16);
}

// ------------------------------ probe + zero -------------------------------
__global__ void k_probe(const long long* __restrict__ ei)
{
    int i = blockIdx.x * blockDim.x + threadIdx.x;
    if (i < N_NODES) g_deg[i] = 0;
    if (blockIdx.x == 0 && threadIdx.x < 32) {
        int bad = 0;
#pragma unroll
        for (int j = 0; j < 8; j++) {
            long long v = ei[threadIdx.x * 8 + j];
            if (v < 0 || v >= N_NODES) bad = 1;
        }
        unsigned m = __ballot_sync(0xFFFFFFFFu, bad);
        if (threadIdx.x == 0) g_ei_is64 = (m == 0) ? 1 : 0;
    }
}

__device__ __forceinline__ int load_idx(const void* p, int is64, size_t i)
{
    return is64 ? (int)((const long long*)p)[i] : ((const int*)p)[i];
}

// ----------- init: build xc, zero aggr, histogram dst degrees --------------
__global__ void k_init(const float* __restrict__ x, const float* __restrict__ na,
                       const void* __restrict__ ei)
{
    size_t i = (size_t)blockIdx.x * blockDim.x + threadIdx.x;
    size_t stride = (size_t)gridDim.x * blockDim.x;
    const int is64 = g_ei_is64;

    const size_t n_aggr4 = (size_t)N_NODES * CH_TOT / 4;
    float4 z = make_float4(0.f, 0.f, 0.f, 0.f);
    for (size_t j = i; j < n_aggr4; j += stride) g_aggr4[j] = z;

    float* xc = reinterpret_cast<float*>(g_xc4);
    const size_t n_xc = (size_t)N_NODES * IN_CH;
    for (size_t j = i; j < n_xc; j += stride) {
        int n = (int)(j >> 7);
        int c = (int)(j & 127);
        xc[j] = (c < 127) ? x[(size_t)n * 127 + c] : na[n];
    }

    for (size_t e = i; e < N_EDGES; e += stride) {
        int dst = load_idx(ei, is64, (size_t)N_EDGES + e);
        atomicAdd(&g_deg[dst], 1);
    }
}

// ------------------------------ CSR scan -----------------------------------
__global__ void k_scan1()
{
    __shared__ int s[SCAN_BLK];
    int t = threadIdx.x;
    int idx = blockIdx.x * SCAN_BLK + t;
    int v = (idx < N_NODES) ? g_deg[idx] : 0;
    s[t] = v;
    __syncthreads();
#pragma unroll
    for (int off = 1; off < SCAN_BLK; off <<= 1) {
        int tv = (t >= off) ? s[t - off] : 0;
        __syncthreads();
        s[t] += tv;
        __syncthreads();
    }
    if (idx < N_NODES) g_rowptr[idx] = s[t] - v;
    if (t == SCAN_BLK - 1) g_blockSums[blockIdx.x] = s[t];
}

__global__ void k_scan2()
{
    __shared__ int s[256];
    int t = threadIdx.x;
    int v = (t < N_SCAN_BLOCKS) ? g_blockSums[t] : 0;
    s[t] = v;
    __syncthreads();
#pragma unroll
    for (int off = 1; off < 256; off <<= 1) {
        int tv = (t >= off) ? s[t - off] : 0;
        __syncthreads();
        s[t] += tv;
        __syncthreads();
    }
    if (t < N_SCAN_BLOCKS) g_blockSums[t] = s[t] - v;  // exclusive
}

__global__ void k_scan3()
{
    int idx = blockIdx.x * blockDim.x + threadIdx.x;
    if (idx < N_NODES) {
        int rp = g_rowptr[idx] + g_blockSums[idx / SCAN_BLK];
        g_rowptr[idx] = rp;
        g_cursor[idx] = rp;
    }
    if (idx == 0) g_rowptr[N_NODES] = N_EDGES;
}

// ----------------- fill: CSR-ordered edge records (src + attrs + dst) ------
__global__ void k_fill(const void* __restrict__ ei, const float* __restrict__ ea)
{
    const int is64 = g_ei_is64;
    const float2* ea2 = reinterpret_cast<const float2*>(ea);
    int i = blockIdx.x * blockDim.x + threadIdx.x;
    int stride = gridDim.x * blockDim.x;
    for (int e = i; e < N_EDGES; e += stride) {
        int src = load_idx(ei, is64, e);
        int dst = load_idx(ei, is64, (size_t)N_EDGES + e);
        float2 a01 = __ldg(&ea2[(size_t)e * 3]);
        float2 a23 = __ldg(&ea2[(size_t)e * 3 + 1]);
        float2 a45 = __ldg(&ea2[(size_t)e * 3 + 2]);
        int pos = atomicAdd(&g_cursor[dst], 1);
        g_erec[(size_t)2 * pos]     = make_float4(__int_as_float(src), a01.x, a01.y, a23.x);
        g_erec[(size_t)2 * pos + 1] = make_float4(a23.y, a45.x, a45.y, __int_as_float(dst));
    }
}

// ------------------------------ aggregation --------------------------------
// Flat CSR ranges per warp + cp.async double-level pipeline (unchanged R7).
#define AW    4
#define ACH   4
#define XBUF  3
#define ESLOT 8

struct LaneW {
    u64 w2[6][4];
    u64 b2[4];
};

__device__ __forceinline__ void edge_accum(
    u64 acc[4], const LaneW& lw, float4 ra, float4 rb, float4 xj)
{
    u64 ee[6];
    ee[0] = pack2(ra.y, ra.y);  ee[1] = pack2(ra.z, ra.z);  ee[2] = pack2(ra.w, ra.w);
    ee[3] = pack2(rb.x, rb.x);  ee[4] = pack2(rb.y, rb.y);  ee[5] = pack2(rb.z, rb.z);
#pragma unroll
    for (int jj = 0; jj < 4; jj++) {
        u64 s = lw.b2[jj];
#pragma unroll
        for (int a = 0; a < 6; a++) s = fma2(ee[a], lw.w2[a][jj], s);
        float lo, hi;
        unpack2(s, lo, hi);
        lo = fmaxf(lo, 0.f);
        hi = fmaxf(hi, 0.f);
        float xv = (jj == 0) ? xj.x : (jj == 1) ? xj.y : (jj == 2) ? xj.z : xj.w;
        acc[jj] = fma2(pack2(lo, hi), pack2(xv, xv), acc[jj]);
    }
}

__device__ __forceinline__ void flush_acc(u64 acc[4], int node, int lane, bool use_atomic)
{
    float4 o1, o2;
    unpack2(acc[0], o1.x, o1.y);
    unpack2(acc[1], o1.z, o1.w);
    unpack2(acc[2], o2.x, o2.y);
    unpack2(acc[3], o2.z, o2.w);
    float* p = reinterpret_cast<float*>(g_aggr4) + (size_t)node * 256 + lane * 8;
    if (use_atomic) {
        asm volatile("red.global.add.v4.f32 [%0], {%1,%2,%3,%4};"
                     :: "l"(p), "f"(o1.x), "f"(o1.y), "f"(o1.z), "f"(o1.w) : "memory");
        asm volatile("red.global.add.v4.f32 [%0], {%1,%2,%3,%4};"
                     :: "l"(p + 4), "f"(o2.x), "f"(o2.y), "f"(o2.z), "f"(o2.w) : "memory");
    } else {
        __stcs(reinterpret_cast<float4*>(p),     o1);
        __stcs(reinterpret_cast<float4*>(p) + 1, o2);
    }
    const u64 z = pack2(0.f, 0.f);
    acc[0] = z; acc[1] = z; acc[2] = z; acc[3] = z;
}

__global__ void __launch_bounds__(32 * AW, 4) k_aggr(
    const float* __restrict__ W_in,
    const float* __restrict__ b_in)
{
    __shared__ float4 sx[AW][XBUF][ACH][32];
    __shared__ float4 se[AW][ESLOT][ACH][2];

    const int lane = threadIdx.x & 31;
    const int w    = threadIdx.x >> 5;
    const int wid  = blockIdx.x * AW + w;
    const int wtot = gridDim.x * AW;

    LaneW lw;
#pragma unroll
    for (int jj = 0; jj < 4; jj++) {
        int j0 = lane * 8 + 2 * jj;
        lw.b2[jj] = pack2(__ldg(&b_in[j0]), __ldg(&b_in[j0 + 1]));
#pragma unroll
        for (int a = 0; a < 6; a++)
            lw.w2[a][jj] = pack2(__ldg(&W_in[a * 256 + j0]),
                                 __ldg(&W_in[a * 256 + j0 + 1]));
    }

    const int chunks_total = (N_EDGES + ACH - 1) / ACH;
    const int cpw  = (chunks_total + wtot - 1) / wtot;
    const int c0   = wid * cpw;
    const int c1   = min(c0 + cpw, chunks_total);
    if (c0 >= c1) return;
    const int nch  = c1 - c0;
    const int eend = min(c1 * ACH, N_EDGES);

    auto issue_erec = [&](int c) {
        if (c < nch && lane < 8) {
            size_t fbase = (size_t)(c0 + c) * (2 * ACH);
            if (fbase + lane < (size_t)2 * N_EDGES)
                cp16(&se[w][c & (ESLOT - 1)][lane >> 1][lane & 1], &g_erec[fbase + lane]);
        }
    };
    auto issue_xc = [&](int c) {
        if (c < nch) {
            int b = c % XBUF;
#pragma unroll
            for (int j = 0; j < ACH; j++) {
                int e = (c0 + c) * ACH + j;
                if (e < eend) {
                    int src = __float_as_int(se[w][c & (ESLOT - 1)][j][0].x);
                    cp16(&sx[w][b][j][lane], &g_xc4[(size_t)src * 32 + lane]);
                }
            }
        }
    };

    issue_erec(0); issue_erec(1); issue_erec(2);
    CP_COMMIT();
    CP_WAIT0();
    __syncwarp();
    issue_xc(0); issue_erec(3); CP_COMMIT();
    issue_xc(1); issue_erec(4); CP_COMMIT();

    const u64 z = pack2(0.f, 0.f);
    u64 acc[4] = {z, z, z, z};
    int  cur = -1;
    bool first = true;

    for (int i = 0; i < nch; i++) {
        CP_WAIT1();
        __syncwarp();
        issue_xc(i + 2);
        issue_erec(i + 5);
        CP_COMMIT();

        int b = i % XBUF;
        int s = i & (ESLOT - 1);
#pragma unroll
        for (int j = 0; j < ACH; j++) {
            int e = (c0 + i) * ACH + j;
            if (e >= eend) break;
            float4 ra = se[w][s][j][0];
            float4 rb = se[w][s][j][1];
            int dst = __float_as_int(rb.w);
            if (dst != cur) {
                if (cur >= 0) {
                    flush_acc(acc, cur, lane, first);
                    first = false;
                }
                cur = dst;
            }
            float4 xj = sx[w][b][j][lane];
            edge_accum(acc, lw, ra, rb, xj);
        }
    }
    if (cur >= 0) flush_acc(acc, cur, lane, true);
}

// ------------------------------ output GEMM (tensor core) ------------------
// out = tanh(aggr[N,256] @ W[256,128] + b). mma.sync m16n8k16 bf16, hi/lo
// split (3 terms) for ~fp32 precision. Block: 128x128 tile, 8 warps (2Mx4N),
// warp tile 64x32 = 4x4 mma tiles. K chunks of 32.
#define KO_BK   32
#define KO_APAD 8    // A row: 32+8 bf16 -> 80B stride, LDSM conflict-free
#define KO_BPAD 8    // B row: 128+8 bf16 -> 272B stride, conflict-free

__device__ __forceinline__ void ldsm_x4(unsigned r[4], unsigned addr) {
    asm volatile("ldmatrix.sync.aligned.m8n8.x4.shared.b16 {%0,%1,%2,%3}, [%4];"
                 : "=r"(r[0]), "=r"(r[1]), "=r"(r[2]), "=r"(r[3]) : "r"(addr));
}
__device__ __forceinline__ void ldsm_x2t(unsigned r[2], unsigned addr) {
    asm volatile("ldmatrix.sync.aligned.m8n8.x2.trans.shared.b16 {%0,%1}, [%2];"
                 : "=r"(r[0]), "=r"(r[1]) : "r"(addr));
}
__device__ __forceinline__ void mma_bf16(float c[4], const unsigned a[4], const unsigned b[2]) {
    asm volatile("mma.sync.aligned.m16n8k16.row.col.f32.bf16.bf16.f32 "
                 "{%0,%1,%2,%3}, {%4,%5,%6,%7}, {%8,%9}, {%0,%1,%2,%3};"
                 : "+f"(c[0]), "+f"(c[1]), "+f"(c[2]), "+f"(c[3])
                 : "r"(a[0]), "r"(a[1]), "r"(a[2]), "r"(a[3]), "r"(b[0]), "r"(b[1]));
}

__global__ void __launch_bounds__(256, 2) k_out(
    const float* __restrict__ W,   // [256, 128]
    const float* __restrict__ bo,  // [128]
    float*       __restrict__ out) // [N, 128]
{
    __shared__ __align__(16) unsigned short Ah[128][KO_BK + KO_APAD];
    __shared__ __align__(16) unsigned short Al[128][KO_BK + KO_APAD];
    __shared__ __align__(16) unsigned short Bh[KO_BK][128 + KO_BPAD];
    __shared__ __align__(16) unsigned short Bl[KO_BK][128 + KO_BPAD];

    const int tid  = threadIdx.x;
    const int lane = tid & 31;
    const int warp = tid >> 5;
    const int wm   = warp >> 2;        // 0..1 -> rows wm*64
    const int wn   = warp & 3;         // 0..3 -> cols wn*32
    const int row0 = blockIdx.x * 128;

    const float* aggr = reinterpret_cast<const float*>(g_aggr4);

    float c[4][4][4];                  // [mt][nt][frag]
#pragma unroll
    for (int mt = 0; mt < 4; mt++)
#pragma unroll
        for (int nt = 0; nt < 4; nt++)
#pragma unroll
            for (int q = 0; q < 4; q++) c[mt][nt][q] = 0.f;

    // precomputed smem byte addresses (lane-dependent parts)
    const unsigned sAh = (unsigned)__cvta_generic_to_shared(&Ah[0][0]);
    const unsigned sAl = (unsigned)__cvta_generic_to_shared(&Al[0][0]);
    const unsigned sBh = (unsigned)__cvta_generic_to_shared(&Bh[0][0]);
    const unsigned sBl = (unsigned)__cvta_generic_to_shared(&Bl[0][0]);
    const int a_row = wm * 64 + (lane & 15);          // + mt*16
    const int a_kof = (lane >> 4) << 3;               // 0 or 8
    const int b_row = (lane & 15);                    // + ks*16
    const int b_col = wn * 32;                        // + nt*8

    for (int kc = 0; kc < CH_TOT; kc += KO_BK) {
        // ---- fill A: 128 rows x 32 k (1024 float4, 4 per thread) ----
#pragma unroll
        for (int g = 0; g < 4; g++) {
            int f   = tid + g * 256;
            int r   = f >> 3;            // 8 float4 per row
            int kq  = f & 7;
            int row = row0 + r;
            float4 v = make_float4(0.f, 0.f, 0.f, 0.f);
            if (row < N_NODES)
                v = __ldcs(reinterpret_cast<const float4*>(&aggr[(size_t)row * 256 + kc + kq * 4]));
            unsigned short h0 = f2bf(v.x), h1 = f2bf(v.y), h2 = f2bf(v.z), h3 = f2bf(v.w);
            unsigned short l0 = f2bf(v.x - bf2f(h0)), l1 = f2bf(v.y - bf2f(h1));
            unsigned short l2 = f2bf(v.z - bf2f(h2)), l3 = f2bf(v.w - bf2f(h3));
            *reinterpret_cast<unsigned*>(&Ah[r][kq * 4])     = (unsigned)h0 | ((unsigned)h1 << 16);
            *reinterpret_cast<unsigned*>(&Ah[r][kq * 4 + 2]) = (unsigned)h2 | ((unsigned)h3 << 16);
            *reinterpret_cast<unsigned*>(&Al[r][kq * 4])     = (unsigned)l0 | ((unsigned)l1 << 16);
            *reinterpret_cast<unsigned*>(&Al[r][kq * 4 + 2]) = (unsigned)l2 | ((unsigned)l3 << 16);
        }
        // ---- fill B: 32 k x 128 n (1024 float4, 4 per thread) ----
#pragma unroll
        for (int g = 0; g < 4; g++) {
            int f  = tid + g * 256;
            int kr = f >> 5;             // 32 float4 per row
            int nq = f & 31;
            float4 v = *reinterpret_cast<const float4*>(&W[(size_t)(kc + kr) * 128 + nq * 4]);
            unsigned short h0 = f2bf(v.x), h1 = f2bf(v.y), h2 = f2bf(v.z), h3 = f2bf(v.w);
            unsigned short l0 = f2bf(v.x - bf2f(h0)), l1 = f2bf(v.y - bf2f(h1));
            unsigned short l2 = f2bf(v.z - bf2f(h2)), l3 = f2bf(v.w - bf2f(h3));
            *reinterpret_cast<unsigned*>(&Bh[kr][nq * 4])     = (unsigned)h0 | ((unsigned)h1 << 16);
            *reinterpret_cast<unsigned*>(&Bh[kr][nq * 4 + 2]) = (unsigned)h2 | ((unsigned)h3 << 16);
            *reinterpret_cast<unsigned*>(&Bl[kr][nq * 4])     = (unsigned)l0 | ((unsigned)l1 << 16);
            *reinterpret_cast<unsigned*>(&Bl[kr][nq * 4 + 2]) = (unsigned)l2 | ((unsigned)l3 << 16);
        }
        __syncthreads();

#pragma unroll
        for (int ks = 0; ks < KO_BK / 16; ks++) {
            // B fragments for 4 n-tiles, hi+lo
            unsigned bh[4][2], bl[4][2];
#pragma unroll
            for (int nt = 0; nt < 4; nt++) {
                unsigned boff = (unsigned)(((ks * 16 + b_row) * (128 + KO_BPAD) + b_col + nt * 8) * 2);
                ldsm_x2t(bh[nt], sBh + boff);
                ldsm_x2t(bl[nt], sBl + boff);
            }
#pragma unroll
            for (int mt = 0; mt < 4; mt++) {
                unsigned aoff = (unsigned)(((a_row + mt * 16) * (KO_BK + KO_APAD) + ks * 16 + a_kof) * 2);
                unsigned ah[4], al[4];
                ldsm_x4(ah, sAh + aoff);
                ldsm_x4(al, sAl + aoff);
#pragma unroll
                for (int nt = 0; nt < 4; nt++) {
                    mma_bf16(c[mt][nt], ah, bh[nt]);
                    mma_bf16(c[mt][nt], ah, bl[nt]);
                    mma_bf16(c[mt][nt], al, bh[nt]);
                }
            }
        }
        __syncthreads();
    }

    // ---- epilogue: bias + tanh + store ----
    float bias[4][2];
#pragma unroll
    for (int nt = 0; nt < 4; nt++) {
        int col = wn * 32 + nt * 8 + (lane & 3) * 2;
        bias[nt][0] = __ldg(&bo[col]);
        bias[nt][1] = __ldg(&bo[col + 1]);
    }
#pragma unroll
    for (int mt = 0; mt < 4; mt++) {
#pragma unroll
        for (int nt = 0; nt < 4; nt++) {
            int rg0 = row0 + wm * 64 + mt * 16 + (lane >> 2);
            int col = wn * 32 + nt * 8 + (lane & 3) * 2;
            if (rg0 < N_NODES) {
                float2 o;
                o.x = tanhf(c[mt][nt][0] + bias[nt][0]);
                o.y = tanhf(c[mt][nt][1] + bias[nt][1]);
                __stcs(reinterpret_cast<float2*>(&out[(size_t)rg0 * 128 + col]), o);
            }
            int rg1 = rg0 + 8;
            if (rg1 < N_NODES) {
                float2 o;
                o.x = tanhf(c[mt][nt][2] + bias[nt][0]);
                o.y = tanhf(c[mt][nt][3] + bias[nt][1]);
                __stcs(reinterpret_cast<float2*>(&out[(size_t)rg1 * 128 + col]), o);
            }
        }
    }
}

// ------------------------------ launch -------------------------------------
extern "C" void kernel_launch(void* const* d_in, const int* in_sizes, int n_in,
                              void* d_out, int out_size)
{
    const float* x     = (const float*)d_in[0];
    const float* na    = (const float*)d_in[1];
    const void*  ei    = d_in[2];
    const float* ea    = (const float*)d_in[3];
    const float* W_in  = (const float*)d_in[4];
    const float* b_in  = (const float*)d_in[5];
    const float* W_out = (const float*)d_in[6];
    const float* b_out = (const float*)d_in[7];
    float* out = (float*)d_out;

    k_probe<<<(N_NODES + 255) / 256, 256>>>((const long long*)ei);
    k_init<<<4096, 256>>>(x, na, ei);

    k_scan1<<<N_SCAN_BLOCKS, SCAN_BLK>>>();
    k_scan2<<<1, 256>>>();
    k_scan3<<<(N_NODES + 255) / 256, 256>>>();
    k_fill<<<2048, 256>>>(ei, ea);

    k_aggr<<<592, 32 * AW>>>(W_in, b_in);

    const int gemm_blocks = (N_NODES + 127) / 128;  // 782
    k_out<<<gemm_blocks, 256>>>(W_out, b_out, out);
}

// round 9
// speedup vs baseline: 2.3619x; 1.0502x over previous
#include <cuda_runtime.h>
#include <cuda_bf16.h>
#include <math.h>

#define N_NODES 100000
#define N_EDGES 1600000
#define IN_CH   128
#define HIDDEN  2
#define OUT_CH  128
#define ATTR    6
#define CH_TOT  (IN_CH * HIDDEN)   // 256

typedef unsigned long long u64;

// ------------------------------ scratch ------------------------------------
__device__ float4 g_xc4[(size_t)N_NODES * IN_CH / 4];    // concat(x,node_attr) 51.2MB
__device__ float4 g_aggr4[(size_t)N_NODES * CH_TOT / 4]; // per-node aggregate 102.4MB
__device__ float4 g_erec[(size_t)2 * N_EDGES];           // CSR (src,a0,a1,a2)(a3,a4,a5,dst)
__device__ int    g_deg[N_NODES];
__device__ int    g_rowptr[N_NODES + 1];
__device__ int    g_cursor[N_NODES];
__device__ int    g_ei_is64;

#define SCAN_BLK 512
#define N_SCAN_BLOCKS ((N_NODES + SCAN_BLK - 1) / SCAN_BLK)  // 196
__device__ int g_blockSums[N_SCAN_BLOCKS];

// k_aggr decomposition constants (shared with k_zero_bnd)
#define AW    4                        // warps per block
#define ACH   4                        // edges per chunk
#define XBUF  4                        // xc buffers in flight
#define ESLOT 8                        // erec ring slots
#define AGG_BLOCKS 592
#define WTOT  (AGG_BLOCKS * AW)        // 2368 warps

// ------------------------------ f32x2 helpers ------------------------------
__device__ __forceinline__ u64 pack2(float lo, float hi) {
    u64 d; asm("mov.b64 %0, {%1, %2};" : "=l"(d) : "f"(lo), "f"(hi)); return d;
}
__device__ __forceinline__ void unpack2(u64 d, float& lo, float& hi) {
    asm("mov.b64 {%0, %1}, %2;" : "=f"(lo), "=f"(hi) : "l"(d));
}
__device__ __forceinline__ u64 fma2(u64 a, u64 b, u64 c) {
    u64 d; asm("fma.rn.f32x2 %0, %1, %2, %3;" : "=l"(d) : "l"(a), "l"(b), "l"(c)); return d;
}

// ------------------------------ cp.async helpers ---------------------------
__device__ __forceinline__ void cp16(void* smem, const void* gmem) {
    unsigned s = (unsigned)__cvta_generic_to_shared(smem);
    asm volatile("cp.async.cg.shared.global [%0], [%1], 16;" :: "r"(s), "l"(gmem) : "memory");
}
#define CP_COMMIT() asm volatile("cp.async.commit_group;" ::: "memory")
#define CP_WAIT2()  asm volatile("cp.async.wait_group 2;" ::: "memory")
#define CP_WAIT0()  asm volatile("cp.async.wait_group 0;" ::: "memory")

// ------------------------------ bf16 helpers -------------------------------
__device__ __forceinline__ unsigned short f2bf(float a) {
    unsigned short h; asm("cvt.rn.bf16.f32 %0, %1;" : "=h"(h) : "f"(a)); return h;
}
__device__ __forceinline__ float bf2f(unsigned short h) {
    return __uint_as_float(((unsigned)h) << 16);
}

// ------------------------------ probe + zero deg ---------------------------
__global__ void k_probe(const long long* __restrict__ ei)
{
    int i = blockIdx.x * blockDim.x + threadIdx.x;
    if (i < N_NODES) g_deg[i] = 0;
    if (blockIdx.x == 0 && threadIdx.x < 32) {
        int bad = 0;
#pragma unroll
        for (int j = 0; j < 8; j++) {
            long long v = ei[threadIdx.x * 8 + j];
            if (v < 0 || v >= N_NODES) bad = 1;
        }
        unsigned m = __ballot_sync(0xFFFFFFFFu, bad);
        if (threadIdx.x == 0) g_ei_is64 = (m == 0) ? 1 : 0;
    }
}

__device__ __forceinline__ int load_idx(const void* p, int is64, size_t i)
{
    return is64 ? (int)((const long long*)p)[i] : ((const int*)p)[i];
}

// ----------- init: build xc + histogram dst degrees (NO aggr zeroing) ------
__global__ void k_init(const float* __restrict__ x, const float* __restrict__ na,
                       const void* __restrict__ ei)
{
    size_t i = (size_t)blockIdx.x * blockDim.x + threadIdx.x;
    size_t stride = (size_t)gridDim.x * blockDim.x;
    const int is64 = g_ei_is64;

    float* xc = reinterpret_cast<float*>(g_xc4);
    const size_t n_xc = (size_t)N_NODES * IN_CH;
    for (size_t j = i; j < n_xc; j += stride) {
        int n = (int)(j >> 7);
        int c = (int)(j & 127);
        xc[j] = (c < 127) ? x[(size_t)n * 127 + c] : na[n];
    }

    for (size_t e = i; e < N_EDGES; e += stride) {
        int dst = load_idx(ei, is64, (size_t)N_EDGES + e);
        atomicAdd(&g_deg[dst], 1);
    }
}

// ------------------------------ CSR scan -----------------------------------
__global__ void k_scan1()
{
    __shared__ int s[SCAN_BLK];
    int t = threadIdx.x;
    int idx = blockIdx.x * SCAN_BLK + t;
    int v = (idx < N_NODES) ? g_deg[idx] : 0;
    s[t] = v;
    __syncthreads();
#pragma unroll
    for (int off = 1; off < SCAN_BLK; off <<= 1) {
        int tv = (t >= off) ? s[t - off] : 0;
        __syncthreads();
        s[t] += tv;
        __syncthreads();
    }
    if (idx < N_NODES) g_rowptr[idx] = s[t] - v;
    if (t == SCAN_BLK - 1) g_blockSums[blockIdx.x] = s[t];
}

__global__ void k_scan2()
{
    __shared__ int s[256];
    int t = threadIdx.x;
    int v = (t < N_SCAN_BLOCKS) ? g_blockSums[t] : 0;
    s[t] = v;
    __syncthreads();
#pragma unroll
    for (int off = 1; off < 256; off <<= 1) {
        int tv = (t >= off) ? s[t - off] : 0;
        __syncthreads();
        s[t] += tv;
        __syncthreads();
    }
    if (t < N_SCAN_BLOCKS) g_blockSums[t] = s[t] - v;  // exclusive
}

__global__ void k_scan3()
{
    int idx = blockIdx.x * blockDim.x + threadIdx.x;
    if (idx < N_NODES) {
        int rp = g_rowptr[idx] + g_blockSums[idx / SCAN_BLK];
        g_rowptr[idx] = rp;
        g_cursor[idx] = rp;
    }
    if (idx == 0) g_rowptr[N_NODES] = N_EDGES;
}

// ----------------- fill: CSR-ordered edge records (src + attrs + dst) ------
__global__ void k_fill(const void* __restrict__ ei, const float* __restrict__ ea)
{
    const int is64 = g_ei_is64;
    const float2* ea2 = reinterpret_cast<const float2*>(ea);
    int i = blockIdx.x * blockDim.x + threadIdx.x;
    int stride = gridDim.x * blockDim.x;
    for (int e = i; e < N_EDGES; e += stride) {
        int src = load_idx(ei, is64, e);
        int dst = load_idx(ei, is64, (size_t)N_EDGES + e);
        float2 a01 = __ldg(&ea2[(size_t)e * 3]);
        float2 a23 = __ldg(&ea2[(size_t)e * 3 + 1]);
        float2 a45 = __ldg(&ea2[(size_t)e * 3 + 2]);
        int pos = atomicAdd(&g_cursor[dst], 1);
        g_erec[(size_t)2 * pos]     = make_float4(__int_as_float(src), a01.x, a01.y, a23.x);
        g_erec[(size_t)2 * pos + 1] = make_float4(a23.y, a45.x, a45.y, __int_as_float(dst));
    }
}

// ---- zero only the rows that need it: warp-range boundary nodes (atomics
// from multiple warps) and degree-0 nodes (never written; stale otherwise).
// Range math MUST mirror k_aggr exactly.
__global__ void k_zero_bnd()
{
    const float4 z4 = make_float4(0.f, 0.f, 0.f, 0.f);

    // part 1: one warp per k_aggr warp
    int gw = blockIdx.x * (blockDim.x >> 5) + (threadIdx.x >> 5);
    int lane = threadIdx.x & 31;
    if (gw < WTOT) {
        const int chunks_total = (N_EDGES + ACH - 1) / ACH;
        const int cpw = (chunks_total + WTOT - 1) / WTOT;
        const int c0  = gw * cpw;
        const int c1  = min(c0 + cpw, chunks_total);
        if (c0 < c1) {
            int e0 = c0 * ACH;
            int e1 = min(c1 * ACH, N_EDGES) - 1;
            int d0 = __float_as_int(g_erec[(size_t)2 * e0 + 1].w);
            int d1 = __float_as_int(g_erec[(size_t)2 * e1 + 1].w);
            g_aggr4[(size_t)d0 * 64 + lane * 2]     = z4;
            g_aggr4[(size_t)d0 * 64 + lane * 2 + 1] = z4;
            g_aggr4[(size_t)d1 * 64 + lane * 2]     = z4;
            g_aggr4[(size_t)d1 * 64 + lane * 2 + 1] = z4;
        }
    }

    // part 2: degree-0 nodes (expected ~0 of them, but must be correct)
    int n = blockIdx.x * blockDim.x + threadIdx.x;
    if (n < N_NODES && g_rowptr[n] == g_rowptr[n + 1]) {
        for (int q = 0; q < 64; q++) g_aggr4[(size_t)n * 64 + q] = z4;
    }
}

// ------------------------------ aggregation --------------------------------
// Flat CSR ranges per warp; cp.async pipeline, 3 xc groups in flight.
struct LaneW {
    u64 w2[6][4];
    u64 b2[4];
};

__device__ __forceinline__ void edge_accum(
    u64 acc[4], const LaneW& lw, float4 ra, float4 rb, float4 xj)
{
    u64 ee[6];
    ee[0] = pack2(ra.y, ra.y);  ee[1] = pack2(ra.z, ra.z);  ee[2] = pack2(ra.w, ra.w);
    ee[3] = pack2(rb.x, rb.x);  ee[4] = pack2(rb.y, rb.y);  ee[5] = pack2(rb.z, rb.z);
#pragma unroll
    for (int jj = 0; jj < 4; jj++) {
        u64 s = lw.b2[jj];
#pragma unroll
        for (int a = 0; a < 6; a++) s = fma2(ee[a], lw.w2[a][jj], s);
        float lo, hi;
        unpack2(s, lo, hi);
        lo = fmaxf(lo, 0.f);
        hi = fmaxf(hi, 0.f);
        float xv = (jj == 0) ? xj.x : (jj == 1) ? xj.y : (jj == 2) ? xj.z : xj.w;
        acc[jj] = fma2(pack2(lo, hi), pack2(xv, xv), acc[jj]);
    }
}

__device__ __forceinline__ void flush_acc(u64 acc[4], int node, int lane, bool use_atomic)
{
    float4 o1, o2;
    unpack2(acc[0], o1.x, o1.y);
    unpack2(acc[1], o1.z, o1.w);
    unpack2(acc[2], o2.x, o2.y);
    unpack2(acc[3], o2.z, o2.w);
    float* p = reinterpret_cast<float*>(g_aggr4) + (size_t)node * 256 + lane * 8;
    if (use_atomic) {
        asm volatile("red.global.add.v4.f32 [%0], {%1,%2,%3,%4};"
                     :: "l"(p), "f"(o1.x), "f"(o1.y), "f"(o1.z), "f"(o1.w) : "memory");
        asm volatile("red.global.add.v4.f32 [%0], {%1,%2,%3,%4};"
                     :: "l"(p + 4), "f"(o2.x), "f"(o2.y), "f"(o2.z), "f"(o2.w) : "memory");
    } else {
        __stcs(reinterpret_cast<float4*>(p),     o1);
        __stcs(reinterpret_cast<float4*>(p) + 1, o2);
    }
    const u64 z = pack2(0.f, 0.f);
    acc[0] = z; acc[1] = z; acc[2] = z; acc[3] = z;
}

__global__ void __launch_bounds__(32 * AW, 4) k_aggr(
    const float* __restrict__ W_in,
    const float* __restrict__ b_in)
{
    __shared__ float4 sx[AW][XBUF][ACH][32];   // 32 KB
    __shared__ float4 se[AW][ESLOT][ACH][2];   //  4 KB

    const int lane = threadIdx.x & 31;
    const int w    = threadIdx.x >> 5;
    const int wid  = blockIdx.x * AW + w;

    LaneW lw;
#pragma unroll
    for (int jj = 0; jj < 4; jj++) {
        int j0 = lane * 8 + 2 * jj;
        lw.b2[jj] = pack2(__ldg(&b_in[j0]), __ldg(&b_in[j0 + 1]));
#pragma unroll
        for (int a = 0; a < 6; a++)
            lw.w2[a][jj] = pack2(__ldg(&W_in[a * 256 + j0]),
                                 __ldg(&W_in[a * 256 + j0 + 1]));
    }

    const int chunks_total = (N_EDGES + ACH - 1) / ACH;
    const int cpw  = (chunks_total + WTOT - 1) / WTOT;
    const int c0   = wid * cpw;
    const int c1   = min(c0 + cpw, chunks_total);
    if (c0 >= c1) return;
    const int nch  = c1 - c0;
    const int eend = min(c1 * ACH, N_EDGES);

    auto issue_erec = [&](int c) {
        if (c < nch && lane < 8) {
            size_t fbase = (size_t)(c0 + c) * (2 * ACH);
            if (fbase + lane < (size_t)2 * N_EDGES)
                cp16(&se[w][c & (ESLOT - 1)][lane >> 1][lane & 1], &g_erec[fbase + lane]);
        }
    };
    auto issue_xc = [&](int c) {
        if (c < nch) {
            int b = c & (XBUF - 1);
#pragma unroll
            for (int j = 0; j < ACH; j++) {
                int e = (c0 + c) * ACH + j;
                if (e < eend) {
                    int src = __float_as_int(se[w][c & (ESLOT - 1)][j][0].x);
                    cp16(&sx[w][b][j][lane], &g_xc4[(size_t)src * 32 + lane]);
                }
            }
        }
    };

    // prologue: erec 0..3 resident, then groups G0{xc0,erec4} G1{xc1,erec5}
    // G2{xc2,erec6}
    issue_erec(0); issue_erec(1); issue_erec(2); issue_erec(3);
    CP_COMMIT();
    CP_WAIT0();
    __syncwarp();
    issue_xc(0); issue_erec(4); CP_COMMIT();
    issue_xc(1); issue_erec(5); CP_COMMIT();
    issue_xc(2); issue_erec(6); CP_COMMIT();

    const u64 z = pack2(0.f, 0.f);
    u64 acc[4] = {z, z, z, z};
    int  cur = -1;
    bool first = true;

    for (int i = 0; i < nch; i++) {
        CP_WAIT2();          // completes G_i: xc(i) + erec(i+4)
        __syncwarp();
        issue_xc(i + 3);     // erec(i+3) resident since G_{i-1}
        issue_erec(i + 7);
        CP_COMMIT();

        int b = i & (XBUF - 1);
        int s = i & (ESLOT - 1);
#pragma unroll
        for (int j = 0; j < ACH; j++) {
            int e = (c0 + i) * ACH + j;
            if (e >= eend) break;
            float4 ra = se[w][s][j][0];
            float4 rb = se[w][s][j][1];
            int dst = __float_as_int(rb.w);
            if (dst != cur) {
                if (cur >= 0) {
                    flush_acc(acc, cur, lane, first);
                    first = false;
                }
                cur = dst;
            }
            float4 xj = sx[w][b][j][lane];
            edge_accum(acc, lw, ra, rb, xj);
        }
    }
    if (cur >= 0) flush_acc(acc, cur, lane, true);
}

// ------------------------------ output GEMM (tensor core) ------------------
#define KO_BK   32
#define KO_APAD 8
#define KO_BPAD 8

__device__ __forceinline__ void ldsm_x4(unsigned r[4], unsigned addr) {
    asm volatile("ldmatrix.sync.aligned.m8n8.x4.shared.b16 {%0,%1,%2,%3}, [%4];"
                 : "=r"(r[0]), "=r"(r[1]), "=r"(r[2]), "=r"(r[3]) : "r"(addr));
}
__device__ __forceinline__ void ldsm_x2t(unsigned r[2], unsigned addr) {
    asm volatile("ldmatrix.sync.aligned.m8n8.x2.trans.shared.b16 {%0,%1}, [%2];"
                 : "=r"(r[0]), "=r"(r[1]) : "r"(addr));
}
__device__ __forceinline__ void mma_bf16(float c[4], const unsigned a[4], const unsigned b[2]) {
    asm volatile("mma.sync.aligned.m16n8k16.row.col.f32.bf16.bf16.f32 "
                 "{%0,%1,%2,%3}, {%4,%5,%6,%7}, {%8,%9}, {%0,%1,%2,%3};"
                 : "+f"(c[0]), "+f"(c[1]), "+f"(c[2]), "+f"(c[3])
                 : "r"(a[0]), "r"(a[1]), "r"(a[2]), "r"(a[3]), "r"(b[0]), "r"(b[1]));
}

__global__ void __launch_bounds__(256, 2) k_out(
    const float* __restrict__ W,   // [256, 128]
    const float* __restrict__ bo,  // [128]
    float*       __restrict__ out) // [N, 128]
{
    __shared__ __align__(16) unsigned short Ah[128][KO_BK + KO_APAD];
    __shared__ __align__(16) unsigned short Al[128][KO_BK + KO_APAD];
    __shared__ __align__(16) unsigned short Bh[KO_BK][128 + KO_BPAD];
    __shared__ __align__(16) unsigned short Bl[KO_BK][128 + KO_BPAD];

    const int tid  = threadIdx.x;
    const int lane = tid & 31;
    const int warp = tid >> 5;
    const int wm   = warp >> 2;
    const int wn   = warp & 3;
    const int row0 = blockIdx.x * 128;

    const float* aggr = reinterpret_cast<const float*>(g_aggr4);

    float c[4][4][4];
#pragma unroll
    for (int mt = 0; mt < 4; mt++)
#pragma unroll
        for (int nt = 0; nt < 4; nt++)
#pragma unroll
            for (int q = 0; q < 4; q++) c[mt][nt][q] = 0.f;

    const unsigned sAh = (unsigned)__cvta_generic_to_shared(&Ah[0][0]);
    const unsigned sAl = (unsigned)__cvta_generic_to_shared(&Al[0][0]);
    const unsigned sBh = (unsigned)__cvta_generic_to_shared(&Bh[0][0]);
    const unsigned sBl = (unsigned)__cvta_generic_to_shared(&Bl[0][0]);
    const int a_row = wm * 64 + (lane & 15);
    const int a_kof = (lane >> 4) << 3;
    const int b_row = (lane & 15);
    const int b_col = wn * 32;

    for (int kc = 0; kc < CH_TOT; kc += KO_BK) {
#pragma unroll
        for (int g = 0; g < 4; g++) {
            int f   = tid + g * 256;
            int r   = f >> 3;
            int kq  = f & 7;
            int row = row0 + r;
            float4 v = make_float4(0.f, 0.f, 0.f, 0.f);
            if (row < N_NODES)
                v = __ldcs(reinterpret_cast<const float4*>(&aggr[(size_t)row * 256 + kc + kq * 4]));
            unsigned short h0 = f2bf(v.x), h1 = f2bf(v.y), h2 = f2bf(v.z), h3 = f2bf(v.w);
            unsigned short l0 = f2bf(v.x - bf2f(h0)), l1 = f2bf(v.y - bf2f(h1));
            unsigned short l2 = f2bf(v.z - bf2f(h2)), l3 = f2bf(v.w - bf2f(h3));
            *reinterpret_cast<unsigned*>(&Ah[r][kq * 4])     = (unsigned)h0 | ((unsigned)h1 << 16);
            *reinterpret_cast<unsigned*>(&Ah[r][kq * 4 + 2]) = (unsigned)h2 | ((unsigned)h3 << 16);
            *reinterpret_cast<unsigned*>(&Al[r][kq * 4])     = (unsigned)l0 | ((unsigned)l1 << 16);
            *reinterpret_cast<unsigned*>(&Al[r][kq * 4 + 2]) = (unsigned)l2 | ((unsigned)l3 << 16);
        }
#pragma unroll
        for (int g = 0; g < 4; g++) {
            int f  = tid + g * 256;
            int kr = f >> 5;
            int nq = f & 31;
            float4 v = *reinterpret_cast<const float4*>(&W[(size_t)(kc + kr) * 128 + nq * 4]);
            unsigned short h0 = f2bf(v.x), h1 = f2bf(v.y), h2 = f2bf(v.z), h3 = f2bf(v.w);
            unsigned short l0 = f2bf(v.x - bf2f(h0)), l1 = f2bf(v.y - bf2f(h1));
            unsigned short l2 = f2bf(v.z - bf2f(h2)), l3 = f2bf(v.w - bf2f(h3));
            *reinterpret_cast<unsigned*>(&Bh[kr][nq * 4])     = (unsigned)h0 | ((unsigned)h1 << 16);
            *reinterpret_cast<unsigned*>(&Bh[kr][nq * 4 + 2]) = (unsigned)h2 | ((unsigned)h3 << 16);
            *reinterpret_cast<unsigned*>(&Bl[kr][nq * 4])     = (unsigned)l0 | ((unsigned)l1 << 16);
            *reinterpret_cast<unsigned*>(&Bl[kr][nq * 4 + 2]) = (unsigned)l2 | ((unsigned)l3 << 16);
        }
        __syncthreads();

#pragma unroll
        for (int ks = 0; ks < KO_BK / 16; ks++) {
            unsigned bh[4][2], bl[4][2];
#pragma unroll
            for (int nt = 0; nt < 4; nt++) {
                unsigned boff = (unsigned)(((ks * 16 + b_row) * (128 + KO_BPAD) + b_col + nt * 8) * 2);
                ldsm_x2t(bh[nt], sBh + boff);
                ldsm_x2t(bl[nt], sBl + boff);
            }
#pragma unroll
            for (int mt = 0; mt < 4; mt++) {
                unsigned aoff = (unsigned)(((a_row + mt * 16) * (KO_BK + KO_APAD) + ks * 16 + a_kof) * 2);
                unsigned ah[4], al[4];
                ldsm_x4(ah, sAh + aoff);
                ldsm_x4(al, sAl + aoff);
#pragma unroll
                for (int nt = 0; nt < 4; nt++) {
                    mma_bf16(c[mt][nt], ah, bh[nt]);
                    mma_bf16(c[mt][nt], ah, bl[nt]);
                    mma_bf16(c[mt][nt], al, bh[nt]);
                }
            }
        }
        __syncthreads();
    }

    float bias[4][2];
#pragma unroll
    for (int nt = 0; nt < 4; nt++) {
        int col = wn * 32 + nt * 8 + (lane & 3) * 2;
        bias[nt][0] = __ldg(&bo[col]);
        bias[nt][1] = __ldg(&bo[col + 1]);
    }
#pragma unroll
    for (int mt = 0; mt < 4; mt++) {
#pragma unroll
        for (int nt = 0; nt < 4; nt++) {
            int rg0 = row0 + wm * 64 + mt * 16 + (lane >> 2);
            int col = wn * 32 + nt * 8 + (lane & 3) * 2;
            if (rg0 < N_NODES) {
                float2 o;
                o.x = tanhf(c[mt][nt][0] + bias[nt][0]);
                o.y = tanhf(c[mt][nt][1] + bias[nt][1]);
                __stcs(reinterpret_cast<float2*>(&out[(size_t)rg0 * 128 + col]), o);
            }
            int rg1 = rg0 + 8;
            if (rg1 < N_NODES) {
                float2 o;
                o.x = tanhf(c[mt][nt][2] + bias[nt][0]);
                o.y = tanhf(c[mt][nt][3] + bias[nt][1]);
                __stcs(reinterpret_cast<float2*>(&out[(size_t)rg1 * 128 + col]), o);
            }
        }
    }
}

// ------------------------------ launch -------------------------------------
extern "C" void kernel_launch(void* const* d_in, const int* in_sizes, int n_in,
                              void* d_out, int out_size)
{
    const float* x     = (const float*)d_in[0];
    const float* na    = (const float*)d_in[1];
    const void*  ei    = d_in[2];
    const float* ea    = (const float*)d_in[3];
    const float* W_in  = (const float*)d_in[4];
    const float* b_in  = (const float*)d_in[5];
    const float* W_out = (const float*)d_in[6];
    const float* b_out = (const float*)d_in[7];
    float* out = (float*)d_out;

    k_probe<<<(N_NODES + 255) / 256, 256>>>((const long long*)ei);
    k_init<<<4096, 256>>>(x, na, ei);

    k_scan1<<<N_SCAN_BLOCKS, SCAN_BLK>>>();
    k_scan2<<<1, 256>>>();
    k_scan3<<<(N_NODES + 255) / 256, 256>>>();
    k_fill<<<2048, 256>>>(ei, ea);
    k_zero_bnd<<<400, 256>>>();

    k_aggr<<<AGG_BLOCKS, 32 * AW>>>(W_in, b_in);

    const int gemm_blocks = (N_NODES + 127) / 128;  // 782
    k_out<<<gemm_blocks, 256>>>(W_out, b_out, out);
}

// round 10
// speedup vs baseline: 2.3990x; 1.0157x over previous
#include <cuda_runtime.h>
#include <cuda_bf16.h>
#include <cuda_fp16.h>
#include <math.h>

#define N_NODES 100000
#define N_EDGES 1600000
#define IN_CH   128
#define HIDDEN  2
#define OUT_CH  128
#define ATTR    6
#define CH_TOT  (IN_CH * HIDDEN)   // 256

typedef unsigned long long u64;

// ------------------------------ scratch ------------------------------------
__device__ uint4  g_xch4[(size_t)N_NODES * 16];          // xc as fp16: 256B/row, 25.6MB
__device__ float4 g_aggr4[(size_t)N_NODES * CH_TOT / 4]; // per-node aggregate 102.4MB
__device__ float4 g_erec[(size_t)2 * N_EDGES];           // CSR (src,a0,a1,a2)(a3,a4,a5,dst)
__device__ int    g_deg[N_NODES];
__device__ int    g_rowptr[N_NODES + 1];
__device__ int    g_cursor[N_NODES];
__device__ int    g_ei_is64;

#define SCAN_BLK 512
#define N_SCAN_BLOCKS ((N_NODES + SCAN_BLK - 1) / SCAN_BLK)  // 196
__device__ int g_blockSums[N_SCAN_BLOCKS];

// k_aggr decomposition constants (shared with k_zero_bnd)
#define AW    4                        // warps per block
#define ACH   4                        // edges per chunk
#define XBUF  4                        // xc buffers in flight
#define ESLOT 8                        // erec ring slots
#define AGG_BLOCKS 592
#define WTOT  (AGG_BLOCKS * AW)        // 2368 warps

// ------------------------------ f32x2 helpers ------------------------------
__device__ __forceinline__ u64 pack2(float lo, float hi) {
    u64 d; asm("mov.b64 %0, {%1, %2};" : "=l"(d) : "f"(lo), "f"(hi)); return d;
}
__device__ __forceinline__ void unpack2(u64 d, float& lo, float& hi) {
    asm("mov.b64 {%0, %1}, %2;" : "=f"(lo), "=f"(hi) : "l"(d));
}
__device__ __forceinline__ u64 fma2(u64 a, u64 b, u64 c) {
    u64 d; asm("fma.rn.f32x2 %0, %1, %2, %3;" : "=l"(d) : "l"(a), "l"(b), "l"(c)); return d;
}

// ------------------------------ cp.async helpers ---------------------------
__device__ __forceinline__ void cp16(void* smem, const void* gmem) {
    unsigned s = (unsigned)__cvta_generic_to_shared(smem);
    asm volatile("cp.async.cg.shared.global [%0], [%1], 16;" :: "r"(s), "l"(gmem) : "memory");
}
#define CP_COMMIT() asm volatile("cp.async.commit_group;" ::: "memory")
#define CP_WAIT2()  asm volatile("cp.async.wait_group 2;" ::: "memory")
#define CP_WAIT0()  asm volatile("cp.async.wait_group 0;" ::: "memory")

// ------------------------------ bf16 helpers -------------------------------
__device__ __forceinline__ unsigned short f2bf(float a) {
    unsigned short h; asm("cvt.rn.bf16.f32 %0, %1;" : "=h"(h) : "f"(a)); return h;
}
__device__ __forceinline__ float bf2f(unsigned short h) {
    return __uint_as_float(((unsigned)h) << 16);
}

// ------------------------------ probe + zero deg ---------------------------
__global__ void k_probe(const long long* __restrict__ ei)
{
    int i = blockIdx.x * blockDim.x + threadIdx.x;
    if (i < N_NODES) g_deg[i] = 0;
    if (blockIdx.x == 0 && threadIdx.x < 32) {
        int bad = 0;
#pragma unroll
        for (int j = 0; j < 8; j++) {
            long long v = ei[threadIdx.x * 8 + j];
            if (v < 0 || v >= N_NODES) bad = 1;
        }
        unsigned m = __ballot_sync(0xFFFFFFFFu, bad);
        if (threadIdx.x == 0) g_ei_is64 = (m == 0) ? 1 : 0;
    }
}

__device__ __forceinline__ int load_idx(const void* p, int is64, size_t i)
{
    return is64 ? (int)((const long long*)p)[i] : ((const int*)p)[i];
}

// ----------- init: build fp16 xc + histogram dst degrees -------------------
__global__ void k_init(const float* __restrict__ x, const float* __restrict__ na,
                       const void* __restrict__ ei)
{
    size_t i = (size_t)blockIdx.x * blockDim.x + threadIdx.x;
    size_t stride = (size_t)gridDim.x * blockDim.x;
    const int is64 = g_ei_is64;

    __half2* xch = reinterpret_cast<__half2*>(g_xch4);
    const size_t n_pairs = (size_t)N_NODES * 64;     // 64 half2 per node
    for (size_t j = i; j < n_pairs; j += stride) {
        int n  = (int)(j >> 6);
        int c2 = (int)(j & 63);
        float a, b;
        if (c2 < 63) {
            a = x[(size_t)n * 127 + 2 * c2];
            b = x[(size_t)n * 127 + 2 * c2 + 1];
        } else {
            a = x[(size_t)n * 127 + 126];
            b = na[n];
        }
        xch[j] = __floats2half2_rn(a, b);
    }

    for (size_t e = i; e < N_EDGES; e += stride) {
        int dst = load_idx(ei, is64, (size_t)N_EDGES + e);
        atomicAdd(&g_deg[dst], 1);
    }
}

// ------------------------------ CSR scan -----------------------------------
__global__ void k_scan1()
{
    __shared__ int s[SCAN_BLK];
    int t = threadIdx.x;
    int idx = blockIdx.x * SCAN_BLK + t;
    int v = (idx < N_NODES) ? g_deg[idx] : 0;
    s[t] = v;
    __syncthreads();
#pragma unroll
    for (int off = 1; off < SCAN_BLK; off <<= 1) {
        int tv = (t >= off) ? s[t - off] : 0;
        __syncthreads();
        s[t] += tv;
        __syncthreads();
    }
    if (idx < N_NODES) g_rowptr[idx] = s[t] - v;
    if (t == SCAN_BLK - 1) g_blockSums[blockIdx.x] = s[t];
}

__global__ void k_scan2()
{
    __shared__ int s[256];
    int t = threadIdx.x;
    int v = (t < N_SCAN_BLOCKS) ? g_blockSums[t] : 0;
    s[t] = v;
    __syncthreads();
#pragma unroll
    for (int off = 1; off < 256; off <<= 1) {
        int tv = (t >= off) ? s[t - off] : 0;
        __syncthreads();
        s[t] += tv;
        __syncthreads();
    }
    if (t < N_SCAN_BLOCKS) g_blockSums[t] = s[t] - v;  // exclusive
}

__global__ void k_scan3()
{
    int idx = blockIdx.x * blockDim.x + threadIdx.x;
    if (idx < N_NODES) {
        int rp = g_rowptr[idx] + g_blockSums[idx / SCAN_BLK];
        g_rowptr[idx] = rp;
        g_cursor[idx] = rp;
    }
    if (idx == 0) g_rowptr[N_NODES] = N_EDGES;
}

// ----------------- fill: CSR-ordered edge records (src + attrs + dst) ------
__global__ void k_fill(const void* __restrict__ ei, const float* __restrict__ ea)
{
    const int is64 = g_ei_is64;
    const float2* ea2 = reinterpret_cast<const float2*>(ea);
    int i = blockIdx.x * blockDim.x + threadIdx.x;
    int stride = gridDim.x * blockDim.x;
    for (int e = i; e < N_EDGES; e += stride) {
        int src = load_idx(ei, is64, e);
        int dst = load_idx(ei, is64, (size_t)N_EDGES + e);
        float2 a01 = __ldg(&ea2[(size_t)e * 3]);
        float2 a23 = __ldg(&ea2[(size_t)e * 3 + 1]);
        float2 a45 = __ldg(&ea2[(size_t)e * 3 + 2]);
        int pos = atomicAdd(&g_cursor[dst], 1);
        g_erec[(size_t)2 * pos]     = make_float4(__int_as_float(src), a01.x, a01.y, a23.x);
        g_erec[(size_t)2 * pos + 1] = make_float4(a23.y, a45.x, a45.y, __int_as_float(dst));
    }
}

// ---- zero only rows that need it: warp-range boundary + degree-0 nodes ----
__global__ void k_zero_bnd()
{
    const float4 z4 = make_float4(0.f, 0.f, 0.f, 0.f);

    int gw = blockIdx.x * (blockDim.x >> 5) + (threadIdx.x >> 5);
    int lane = threadIdx.x & 31;
    if (gw < WTOT) {
        const int chunks_total = (N_EDGES + ACH - 1) / ACH;
        const int cpw = (chunks_total + WTOT - 1) / WTOT;
        const int c0  = gw * cpw;
        const int c1  = min(c0 + cpw, chunks_total);
        if (c0 < c1) {
            int e0 = c0 * ACH;
            int e1 = min(c1 * ACH, N_EDGES) - 1;
            int d0 = __float_as_int(g_erec[(size_t)2 * e0 + 1].w);
            int d1 = __float_as_int(g_erec[(size_t)2 * e1 + 1].w);
            g_aggr4[(size_t)d0 * 64 + lane * 2]     = z4;
            g_aggr4[(size_t)d0 * 64 + lane * 2 + 1] = z4;
            g_aggr4[(size_t)d1 * 64 + lane * 2]     = z4;
            g_aggr4[(size_t)d1 * 64 + lane * 2 + 1] = z4;
        }
    }

    int n = blockIdx.x * blockDim.x + threadIdx.x;
    if (n < N_NODES && g_rowptr[n] == g_rowptr[n + 1]) {
        for (int q = 0; q < 64; q++) g_aggr4[(size_t)n * 64 + q] = z4;
    }
}

// ------------------------------ aggregation --------------------------------
// Flat CSR ranges per warp; cp.async pipeline; fp16 xc rows (256B).
struct LaneW {
    u64 w2[6][4];
    u64 b2[4];
};

__device__ __forceinline__ void edge_accum(
    u64 acc[4], const LaneW& lw, float4 ra, float4 rb, float4 xj)
{
    u64 ee[6];
    ee[0] = pack2(ra.y, ra.y);  ee[1] = pack2(ra.z, ra.z);  ee[2] = pack2(ra.w, ra.w);
    ee[3] = pack2(rb.x, rb.x);  ee[4] = pack2(rb.y, rb.y);  ee[5] = pack2(rb.z, rb.z);
#pragma unroll
    for (int jj = 0; jj < 4; jj++) {
        u64 s = lw.b2[jj];
#pragma unroll
        for (int a = 0; a < 6; a++) s = fma2(ee[a], lw.w2[a][jj], s);
        float lo, hi;
        unpack2(s, lo, hi);
        lo = fmaxf(lo, 0.f);
        hi = fmaxf(hi, 0.f);
        float xv = (jj == 0) ? xj.x : (jj == 1) ? xj.y : (jj == 2) ? xj.z : xj.w;
        acc[jj] = fma2(pack2(lo, hi), pack2(xv, xv), acc[jj]);
    }
}

__device__ __forceinline__ void flush_acc(u64 acc[4], int node, int lane, bool use_atomic)
{
    float4 o1, o2;
    unpack2(acc[0], o1.x, o1.y);
    unpack2(acc[1], o1.z, o1.w);
    unpack2(acc[2], o2.x, o2.y);
    unpack2(acc[3], o2.z, o2.w);
    float* p = reinterpret_cast<float*>(g_aggr4) + (size_t)node * 256 + lane * 8;
    if (use_atomic) {
        asm volatile("red.global.add.v4.f32 [%0], {%1,%2,%3,%4};"
                     :: "l"(p), "f"(o1.x), "f"(o1.y), "f"(o1.z), "f"(o1.w) : "memory");
        asm volatile("red.global.add.v4.f32 [%0], {%1,%2,%3,%4};"
                     :: "l"(p + 4), "f"(o2.x), "f"(o2.y), "f"(o2.z), "f"(o2.w) : "memory");
    } else {
        __stcs(reinterpret_cast<float4*>(p),     o1);
        __stcs(reinterpret_cast<float4*>(p) + 1, o2);
    }
    const u64 z = pack2(0.f, 0.f);
    acc[0] = z; acc[1] = z; acc[2] = z; acc[3] = z;
}

__global__ void __launch_bounds__(32 * AW, 4) k_aggr(
    const float* __restrict__ W_in,
    const float* __restrict__ b_in)
{
    __shared__ __align__(16) __half sx[AW][XBUF][ACH][128];  // 16 KB
    __shared__ float4 se[AW][ESLOT][ACH][2];                 //  4 KB

    const int lane = threadIdx.x & 31;
    const int w    = threadIdx.x >> 5;
    const int wid  = blockIdx.x * AW + w;

    LaneW lw;
#pragma unroll
    for (int jj = 0; jj < 4; jj++) {
        int j0 = lane * 8 + 2 * jj;
        lw.b2[jj] = pack2(__ldg(&b_in[j0]), __ldg(&b_in[j0 + 1]));
#pragma unroll
        for (int a = 0; a < 6; a++)
            lw.w2[a][jj] = pack2(__ldg(&W_in[a * 256 + j0]),
                                 __ldg(&W_in[a * 256 + j0 + 1]));
    }

    const int chunks_total = (N_EDGES + ACH - 1) / ACH;
    const int cpw  = (chunks_total + WTOT - 1) / WTOT;
    const int c0   = wid * cpw;
    const int c1   = min(c0 + cpw, chunks_total);
    if (c0 >= c1) return;
    const int nch  = c1 - c0;
    const int eend = min(c1 * ACH, N_EDGES);

    auto issue_erec = [&](int c) {
        if (c < nch && lane < 8) {
            size_t fbase = (size_t)(c0 + c) * (2 * ACH);
            if (fbase + lane < (size_t)2 * N_EDGES)
                cp16(&se[w][c & (ESLOT - 1)][lane >> 1][lane & 1], &g_erec[fbase + lane]);
        }
    };
    // fp16 rows: one 256B row = 16 lanes x 16B; 2 edges per warp instruction.
    auto issue_xc = [&](int c) {
        if (c < nch) {
            int b   = c & (XBUF - 1);
            int s   = c & (ESLOT - 1);
            int seg = lane & 15;
            int hlf = lane >> 4;     // 0/1: which edge of the pair
#pragma unroll
            for (int pr = 0; pr < ACH / 2; pr++) {
                int j = pr * 2 + hlf;
                int e = (c0 + c) * ACH + j;
                if (e < eend) {
                    int src = __float_as_int(se[w][s][j][0].x);
                    cp16(&sx[w][b][j][seg * 8], &g_xch4[(size_t)src * 16 + seg]);
                }
            }
        }
    };

    issue_erec(0); issue_erec(1); issue_erec(2); issue_erec(3);
    CP_COMMIT();
    CP_WAIT0();
    __syncwarp();
    issue_xc(0); issue_erec(4); CP_COMMIT();
    issue_xc(1); issue_erec(5); CP_COMMIT();
    issue_xc(2); issue_erec(6); CP_COMMIT();

    const u64 z = pack2(0.f, 0.f);
    u64 acc[4] = {z, z, z, z};
    int  cur = -1;
    bool first = true;

    for (int i = 0; i < nch; i++) {
        CP_WAIT2();          // completes G_i: xc(i) + erec(i+4)
        __syncwarp();
        issue_xc(i + 3);     // erec(i+3) resident since G_{i-1}
        issue_erec(i + 7);
        CP_COMMIT();

        int b = i & (XBUF - 1);
        int s = i & (ESLOT - 1);
#pragma unroll
        for (int j = 0; j < ACH; j++) {
            int e = (c0 + i) * ACH + j;
            if (e >= eend) break;
            float4 ra = se[w][s][j][0];
            float4 rb = se[w][s][j][1];
            int dst = __float_as_int(rb.w);
            if (dst != cur) {
                if (cur >= 0) {
                    flush_acc(acc, cur, lane, first);
                    first = false;
                }
                cur = dst;
            }
            // lane t owns channels [4t, 4t+4): 2 half2 -> float4
            const __half2* hp = reinterpret_cast<const __half2*>(&sx[w][b][j][lane * 4]);
            float2 f0 = __half22float2(hp[0]);
            float2 f1 = __half22float2(hp[1]);
            float4 xj = make_float4(f0.x, f0.y, f1.x, f1.y);
            edge_accum(acc, lw, ra, rb, xj);
        }
    }
    if (cur >= 0) flush_acc(acc, cur, lane, true);
}

// ------------------------------ output GEMM (tensor core) ------------------
#define KO_BK   32
#define KO_APAD 8
#define KO_BPAD 8

__device__ __forceinline__ void ldsm_x4(unsigned r[4], unsigned addr) {
    asm volatile("ldmatrix.sync.aligned.m8n8.x4.shared.b16 {%0,%1,%2,%3}, [%4];"
                 : "=r"(r[0]), "=r"(r[1]), "=r"(r[2]), "=r"(r[3]) : "r"(addr));
}
__device__ __forceinline__ void ldsm_x2t(unsigned r[2], unsigned addr) {
    asm volatile("ldmatrix.sync.aligned.m8n8.x2.trans.shared.b16 {%0,%1}, [%2];"
                 : "=r"(r[0]), "=r"(r[1]) : "r"(addr));
}
__device__ __forceinline__ void mma_bf16(float c[4], const unsigned a[4], const unsigned b[2]) {
    asm volatile("mma.sync.aligned.m16n8k16.row.col.f32.bf16.bf16.f32 "
                 "{%0,%1,%2,%3}, {%4,%5,%6,%7}, {%8,%9}, {%0,%1,%2,%3};"
                 : "+f"(c[0]), "+f"(c[1]), "+f"(c[2]), "+f"(c[3])
                 : "r"(a[0]), "r"(a[1]), "r"(a[2]), "r"(a[3]), "r"(b[0]), "r"(b[1]));
}

__global__ void __launch_bounds__(256, 2) k_out(
    const float* __restrict__ W,   // [256, 128]
    const float* __restrict__ bo,  // [128]
    float*       __restrict__ out) // [N, 128]
{
    __shared__ __align__(16) unsigned short Ah[128][KO_BK + KO_APAD];
    __shared__ __align__(16) unsigned short Al[128][KO_BK + KO_APAD];
    __shared__ __align__(16) unsigned short Bh[KO_BK][128 + KO_BPAD];
    __shared__ __align__(16) unsigned short Bl[KO_BK][128 + KO_BPAD];

    const int tid  = threadIdx.x;
    const int lane = tid & 31;
    const int warp = tid >> 5;
    const int wm   = warp >> 2;
    const int wn   = warp & 3;
    const int row0 = blockIdx.x * 128;

    const float* aggr = reinterpret_cast<const float*>(g_aggr4);

    float c[4][4][4];
#pragma unroll
    for (int mt = 0; mt < 4; mt++)
#pragma unroll
        for (int nt = 0; nt < 4; nt++)
#pragma unroll
            for (int q = 0; q < 4; q++) c[mt][nt][q] = 0.f;

    const unsigned sAh = (unsigned)__cvta_generic_to_shared(&Ah[0][0]);
    const unsigned sAl = (unsigned)__cvta_generic_to_shared(&Al[0][0]);
    const unsigned sBh = (unsigned)__cvta_generic_to_shared(&Bh[0][0]);
    const unsigned sBl = (unsigned)__cvta_generic_to_shared(&Bl[0][0]);
    const int a_row = wm * 64 + (lane & 15);
    const int a_kof = (lane >> 4) << 3;
    const int b_row = (lane & 15);
    const int b_col = wn * 32;

    for (int kc = 0; kc < CH_TOT; kc += KO_BK) {
#pragma unroll
        for (int g = 0; g < 4; g++) {
            int f   = tid + g * 256;
            int r   = f >> 3;
            int kq  = f & 7;
            int row = row0 + r;
            float4 v = make_float4(0.f, 0.f, 0.f, 0.f);
            if (row < N_NODES)
                v = __ldcs(reinterpret_cast<const float4*>(&aggr[(size_t)row * 256 + kc + kq * 4]));
            unsigned short h0 = f2bf(v.x), h1 = f2bf(v.y), h2 = f2bf(v.z), h3 = f2bf(v.w);
            unsigned short l0 = f2bf(v.x - bf2f(h0)), l1 = f2bf(v.y - bf2f(h1));
            unsigned short l2 = f2bf(v.z - bf2f(h2)), l3 = f2bf(v.w - bf2f(h3));
            *reinterpret_cast<unsigned*>(&Ah[r][kq * 4])     = (unsigned)h0 | ((unsigned)h1 << 16);
            *reinterpret_cast<unsigned*>(&Ah[r][kq * 4 + 2]) = (unsigned)h2 | ((unsigned)h3 << 16);
            *reinterpret_cast<unsigned*>(&Al[r][kq * 4])     = (unsigned)l0 | ((unsigned)l1 << 16);
            *reinterpret_cast<unsigned*>(&Al[r][kq * 4 + 2]) = (unsigned)l2 | ((unsigned)l3 << 16);
        }
#pragma unroll
        for (int g = 0; g < 4; g++) {
            int f  = tid + g * 256;
            int kr = f >> 5;
            int nq = f & 31;
            float4 v = *reinterpret_cast<const float4*>(&W[(size_t)(kc + kr) * 128 + nq * 4]);
            unsigned short h0 = f2bf(v.x), h1 = f2bf(v.y), h2 = f2bf(v.z), h3 = f2bf(v.w);
            unsigned short l0 = f2bf(v.x - bf2f(h0)), l1 = f2bf(v.y - bf2f(h1));
            unsigned short l2 = f2bf(v.z - bf2f(h2)), l3 = f2bf(v.w - bf2f(h3));
            *reinterpret_cast<unsigned*>(&Bh[kr][nq * 4])     = (unsigned)h0 | ((unsigned)h1 << 16);
            *reinterpret_cast<unsigned*>(&Bh[kr][nq * 4 + 2]) = (unsigned)h2 | ((unsigned)h3 << 16);
            *reinterpret_cast<unsigned*>(&Bl[kr][nq * 4])     = (unsigned)l0 | ((unsigned)l1 << 16);
            *reinterpret_cast<unsigned*>(&Bl[kr][nq * 4 + 2]) = (unsigned)l2 | ((unsigned)l3 << 16);
        }
        __syncthreads();

#pragma unroll
        for (int ks = 0; ks < KO_BK / 16; ks++) {
            unsigned bh[4][2], bl[4][2];
#pragma unroll
            for (int nt = 0; nt < 4; nt++) {
                unsigned boff = (unsigned)(((ks * 16 + b_row) * (128 + KO_BPAD) + b_col + nt * 8) * 2);
                ldsm_x2t(bh[nt], sBh + boff);
                ldsm_x2t(bl[nt], sBl + boff);
            }
#pragma unroll
            for (int mt = 0; mt < 4; mt++) {
                unsigned aoff = (unsigned)(((a_row + mt * 16) * (KO_BK + KO_APAD) + ks * 16 + a_kof) * 2);
                unsigned ah[4], al[4];
                ldsm_x4(ah, sAh + aoff);
                ldsm_x4(al, sAl + aoff);
#pragma unroll
                for (int nt = 0; nt < 4; nt++) {
                    mma_bf16(c[mt][nt], ah, bh[nt]);
                    mma_bf16(c[mt][nt], ah, bl[nt]);
                    mma_bf16(c[mt][nt], al, bh[nt]);
                }
            }
        }
        __syncthreads();
    }

    float bias[4][2];
#pragma unroll
    for (int nt = 0; nt < 4; nt++) {
        int col = wn * 32 + nt * 8 + (lane & 3) * 2;
        bias[nt][0] = __ldg(&bo[col]);
        bias[nt][1] = __ldg(&bo[col + 1]);
    }
#pragma unroll
    for (int mt = 0; mt < 4; mt++) {
#pragma unroll
        for (int nt = 0; nt < 4; nt++) {
            int rg0 = row0 + wm * 64 + mt * 16 + (lane >> 2);
            int col = wn * 32 + nt * 8 + (lane & 3) * 2;
            if (rg0 < N_NODES) {
                float2 o;
                o.x = tanhf(c[mt][nt][0] + bias[nt][0]);
                o.y = tanhf(c[mt][nt][1] + bias[nt][1]);
                __stcs(reinterpret_cast<float2*>(&out[(size_t)rg0 * 128 + col]), o);
            }
            int rg1 = rg0 + 8;
            if (rg1 < N_NODES) {
                float2 o;
                o.x = tanhf(c[mt][nt][2] + bias[nt][0]);
                o.y = tanhf(c[mt][nt][3] + bias[nt][1]);
                __stcs(reinterpret_cast<float2*>(&out[(size_t)rg1 * 128 + col]), o);
            }
        }
    }
}

// ------------------------------ launch -------------------------------------
extern "C" void kernel_launch(void* const* d_in, const int* in_sizes, int n_in,
                              void* d_out, int out_size)
{
    const float* x     = (const float*)d_in[0];
    const float* na    = (const float*)d_in[1];
    const void*  ei    = d_in[2];
    const float* ea    = (const float*)d_in[3];
    const float* W_in  = (const float*)d_in[4];
    const float* b_in  = (const float*)d_in[5];
    const float* W_out = (const float*)d_in[6];
    const float* b_out = (const float*)d_in[7];
    float* out = (float*)d_out;

    k_probe<<<(N_NODES + 255) / 256, 256>>>((const long long*)ei);
    k_init<<<4096, 256>>>(x, na, ei);

    k_scan1<<<N_SCAN_BLOCKS, SCAN_BLK>>>();
    k_scan2<<<1, 256>>>();
    k_scan3<<<(N_NODES + 255) / 256, 256>>>();
    k_fill<<<2048, 256>>>(ei, ea);
    k_zero_bnd<<<400, 256>>>();

    k_aggr<<<AGG_BLOCKS, 32 * AW>>>(W_in, b_in);

    const int gemm_blocks = (N_NODES + 127) / 128;  // 782
    k_out<<<gemm_blocks, 256>>>(W_out, b_out, out);
}

// round 11
// speedup vs baseline: 2.4901x; 1.0380x over previous
#include <cuda_runtime.h>
#include <cuda_bf16.h>
#include <cuda_fp16.h>
#include <math.h>

#define N_NODES 100000
#define N_EDGES 1600000
#define IN_CH   128
#define HIDDEN  2
#define OUT_CH  128
#define ATTR    6
#define CH_TOT  (IN_CH * HIDDEN)   // 256

typedef unsigned long long u64;

// ------------------------------ scratch ------------------------------------
__device__ uint4  g_xch4[(size_t)N_NODES * 16];          // xc fp16: 256B/row, 25.6MB
__device__ float4 g_aggr4[(size_t)N_NODES * CH_TOT / 4]; // per-node aggregate 102.4MB
__device__ float4 g_erec[(size_t)2 * N_EDGES];           // CSR (src,a0,a1,a2)(a3,a4,a5,dst)
__device__ int    g_deg[N_NODES];
__device__ int    g_rowptr[N_NODES + 1];
__device__ int    g_cursor[N_NODES];
__device__ int    g_ei_is64;

#define SCAN_BLK 512
#define N_SCAN_BLOCKS ((N_NODES + SCAN_BLK - 1) / SCAN_BLK)  // 196
__device__ int g_blockSums[N_SCAN_BLOCKS];

// k_aggr decomposition constants (shared with k_zero_bnd)
#define AW    4                        // warps per block
#define ACH   8                        // edges per chunk
#define XBUF  4                        // xc buffers in flight
#define ESLOT 8                        // erec ring slots
#define AGG_BLOCKS 592
#define WTOT  (AGG_BLOCKS * AW)        // 2368 warps

// ------------------------------ f32x2 helpers ------------------------------
__device__ __forceinline__ u64 pack2(float lo, float hi) {
    u64 d; asm("mov.b64 %0, {%1, %2};" : "=l"(d) : "f"(lo), "f"(hi)); return d;
}
__device__ __forceinline__ void unpack2(u64 d, float& lo, float& hi) {
    asm("mov.b64 {%0, %1}, %2;" : "=f"(lo), "=f"(hi) : "l"(d));
}
__device__ __forceinline__ u64 fma2(u64 a, u64 b, u64 c) {
    u64 d; asm("fma.rn.f32x2 %0, %1, %2, %3;" : "=l"(d) : "l"(a), "l"(b), "l"(c)); return d;
}

// ------------------------------ cp.async helpers ---------------------------
__device__ __forceinline__ void cp16(void* smem, const void* gmem) {
    unsigned s = (unsigned)__cvta_generic_to_shared(smem);
    asm volatile("cp.async.cg.shared.global [%0], [%1], 16;" :: "r"(s), "l"(gmem) : "memory");
}
#define CP_COMMIT() asm volatile("cp.async.commit_group;" ::: "memory")
#define CP_WAIT2()  asm volatile("cp.async.wait_group 2;" ::: "memory")
#define CP_WAIT0()  asm volatile("cp.async.wait_group 0;" ::: "memory")

// ------------------------------ bf16 helpers -------------------------------
__device__ __forceinline__ unsigned short f2bf(float a) {
    unsigned short h; asm("cvt.rn.bf16.f32 %0, %1;" : "=h"(h) : "f"(a)); return h;
}
__device__ __forceinline__ float bf2f(unsigned short h) {
    return __uint_as_float(((unsigned)h) << 16);
}

// ------------------------------ probe + zero deg ---------------------------
__global__ void k_probe(const long long* __restrict__ ei)
{
    int i = blockIdx.x * blockDim.x + threadIdx.x;
    if (i < N_NODES) g_deg[i] = 0;
    if (blockIdx.x == 0 && threadIdx.x < 32) {
        int bad = 0;
#pragma unroll
        for (int j = 0; j < 8; j++) {
            long long v = ei[threadIdx.x * 8 + j];
            if (v < 0 || v >= N_NODES) bad = 1;
        }
        unsigned m = __ballot_sync(0xFFFFFFFFu, bad);
        if (threadIdx.x == 0) g_ei_is64 = (m == 0) ? 1 : 0;
    }
}

__device__ __forceinline__ int load_idx(const void* p, int is64, size_t i)
{
    return is64 ? (int)((const long long*)p)[i] : ((const int*)p)[i];
}

// --------------------- xc fp16 table build (forked stream) -----------------
__global__ void k_xc(const float* __restrict__ x, const float* __restrict__ na)
{
    size_t i = (size_t)blockIdx.x * blockDim.x + threadIdx.x;
    size_t stride = (size_t)gridDim.x * blockDim.x;

    __half2* xch = reinterpret_cast<__half2*>(g_xch4);
    const size_t n_pairs = (size_t)N_NODES * 64;
    for (size_t j = i; j < n_pairs; j += stride) {
        int n  = (int)(j >> 6);
        int c2 = (int)(j & 63);
        float a, b;
        if (c2 < 63) {
            a = x[(size_t)n * 127 + 2 * c2];
            b = x[(size_t)n * 127 + 2 * c2 + 1];
        } else {
            a = x[(size_t)n * 127 + 126];
            b = na[n];
        }
        xch[j] = __floats2half2_rn(a, b);
    }
}

// --------------------- histogram of dst degrees (main stream) --------------
__global__ void k_hist(const void* __restrict__ ei)
{
    const int is64 = g_ei_is64;
    size_t i = (size_t)blockIdx.x * blockDim.x + threadIdx.x;
    size_t stride = (size_t)gridDim.x * blockDim.x;
    for (size_t e = i; e < N_EDGES; e += stride) {
        int dst = load_idx(ei, is64, (size_t)N_EDGES + e);
        atomicAdd(&g_deg[dst], 1);
    }
}

// ------------------------------ CSR scan -----------------------------------
__global__ void k_scan1()
{
    __shared__ int s[SCAN_BLK];
    int t = threadIdx.x;
    int idx = blockIdx.x * SCAN_BLK + t;
    int v = (idx < N_NODES) ? g_deg[idx] : 0;
    s[t] = v;
    __syncthreads();
#pragma unroll
    for (int off = 1; off < SCAN_BLK; off <<= 1) {
        int tv = (t >= off) ? s[t - off] : 0;
        __syncthreads();
        s[t] += tv;
        __syncthreads();
    }
    if (idx < N_NODES) g_rowptr[idx] = s[t] - v;
    if (t == SCAN_BLK - 1) g_blockSums[blockIdx.x] = s[t];
}

__global__ void k_scan2()
{
    __shared__ int s[256];
    int t = threadIdx.x;
    int v = (t < N_SCAN_BLOCKS) ? g_blockSums[t] : 0;
    s[t] = v;
    __syncthreads();
#pragma unroll
    for (int off = 1; off < 256; off <<= 1) {
        int tv = (t >= off) ? s[t - off] : 0;
        __syncthreads();
        s[t] += tv;
        __syncthreads();
    }
    if (t < N_SCAN_BLOCKS) g_blockSums[t] = s[t] - v;  // exclusive
}

__global__ void k_scan3()
{
    int idx = blockIdx.x * blockDim.x + threadIdx.x;
    if (idx < N_NODES) {
        int rp = g_rowptr[idx] + g_blockSums[idx / SCAN_BLK];
        g_rowptr[idx] = rp;
        g_cursor[idx] = rp;
    }
    if (idx == 0) g_rowptr[N_NODES] = N_EDGES;
}

// ----------------- fill: CSR-ordered edge records (src + attrs + dst) ------
__global__ void k_fill(const void* __restrict__ ei, const float* __restrict__ ea)
{
    const int is64 = g_ei_is64;
    const float2* ea2 = reinterpret_cast<const float2*>(ea);
    int i = blockIdx.x * blockDim.x + threadIdx.x;
    int stride = gridDim.x * blockDim.x;
    for (int e = i; e < N_EDGES; e += stride) {
        int src = load_idx(ei, is64, e);
        int dst = load_idx(ei, is64, (size_t)N_EDGES + e);
        float2 a01 = __ldg(&ea2[(size_t)e * 3]);
        float2 a23 = __ldg(&ea2[(size_t)e * 3 + 1]);
        float2 a45 = __ldg(&ea2[(size_t)e * 3 + 2]);
        int pos = atomicAdd(&g_cursor[dst], 1);
        g_erec[(size_t)2 * pos]     = make_float4(__int_as_float(src), a01.x, a01.y, a23.x);
        g_erec[(size_t)2 * pos + 1] = make_float4(a23.y, a45.x, a45.y, __int_as_float(dst));
    }
}

// ---- zero only rows that need it: warp-range boundary + degree-0 nodes ----
__global__ void k_zero_bnd()
{
    const float4 z4 = make_float4(0.f, 0.f, 0.f, 0.f);

    int gw = blockIdx.x * (blockDim.x >> 5) + (threadIdx.x >> 5);
    int lane = threadIdx.x & 31;
    if (gw < WTOT) {
        const int chunks_total = (N_EDGES + ACH - 1) / ACH;
        const int cpw = (chunks_total + WTOT - 1) / WTOT;
        const int c0  = gw * cpw;
        const int c1  = min(c0 + cpw, chunks_total);
        if (c0 < c1) {
            int e0 = c0 * ACH;
            int e1 = min(c1 * ACH, N_EDGES) - 1;
            int d0 = __float_as_int(g_erec[(size_t)2 * e0 + 1].w);
            int d1 = __float_as_int(g_erec[(size_t)2 * e1 + 1].w);
            g_aggr4[(size_t)d0 * 64 + lane * 2]     = z4;
            g_aggr4[(size_t)d0 * 64 + lane * 2 + 1] = z4;
            g_aggr4[(size_t)d1 * 64 + lane * 2]     = z4;
            g_aggr4[(size_t)d1 * 64 + lane * 2 + 1] = z4;
        }
    }

    int n = blockIdx.x * blockDim.x + threadIdx.x;
    if (n < N_NODES && g_rowptr[n] == g_rowptr[n + 1]) {
        for (int q = 0; q < 64; q++) g_aggr4[(size_t)n * 64 + q] = z4;
    }
}

// ------------------------------ aggregation --------------------------------
// Flat CSR ranges per warp; cp.async pipeline; fp16 xc rows (256B); ACH=8.
struct LaneW {
    u64 w2[6][4];
    u64 b2[4];
};

__device__ __forceinline__ void edge_accum(
    u64 acc[4], const LaneW& lw, float4 ra, float4 rb, float4 xj)
{
    u64 ee[6];
    ee[0] = pack2(ra.y, ra.y);  ee[1] = pack2(ra.z, ra.z);  ee[2] = pack2(ra.w, ra.w);
    ee[3] = pack2(rb.x, rb.x);  ee[4] = pack2(rb.y, rb.y);  ee[5] = pack2(rb.z, rb.z);
#pragma unroll
    for (int jj = 0; jj < 4; jj++) {
        u64 s = lw.b2[jj];
#pragma unroll
        for (int a = 0; a < 6; a++) s = fma2(ee[a], lw.w2[a][jj], s);
        float lo, hi;
        unpack2(s, lo, hi);
        lo = fmaxf(lo, 0.f);
        hi = fmaxf(hi, 0.f);
        float xv = (jj == 0) ? xj.x : (jj == 1) ? xj.y : (jj == 2) ? xj.z : xj.w;
        acc[jj] = fma2(pack2(lo, hi), pack2(xv, xv), acc[jj]);
    }
}

__device__ __forceinline__ void flush_acc(u64 acc[4], int node, int lane, bool use_atomic)
{
    float4 o1, o2;
    unpack2(acc[0], o1.x, o1.y);
    unpack2(acc[1], o1.z, o1.w);
    unpack2(acc[2], o2.x, o2.y);
    unpack2(acc[3], o2.z, o2.w);
    float* p = reinterpret_cast<float*>(g_aggr4) + (size_t)node * 256 + lane * 8;
    if (use_atomic) {
        asm volatile("red.global.add.v4.f32 [%0], {%1,%2,%3,%4};"
                     :: "l"(p), "f"(o1.x), "f"(o1.y), "f"(o1.z), "f"(o1.w) : "memory");
        asm volatile("red.global.add.v4.f32 [%0], {%1,%2,%3,%4};"
                     :: "l"(p + 4), "f"(o2.x), "f"(o2.y), "f"(o2.z), "f"(o2.w) : "memory");
    } else {
        __stcs(reinterpret_cast<float4*>(p),     o1);
        __stcs(reinterpret_cast<float4*>(p) + 1, o2);
    }
    const u64 z = pack2(0.f, 0.f);
    acc[0] = z; acc[1] = z; acc[2] = z; acc[3] = z;
}

__global__ void __launch_bounds__(32 * AW, 4) k_aggr(
    const float* __restrict__ W_in,
    const float* __restrict__ b_in)
{
    __shared__ __align__(16) __half sx[AW][XBUF][ACH][128];  // 32 KB
    __shared__ float4 se[AW][ESLOT][ACH][2];                 //  8 KB

    const int lane = threadIdx.x & 31;
    const int w    = threadIdx.x >> 5;
    const int wid  = blockIdx.x * AW + w;

    LaneW lw;
#pragma unroll
    for (int jj = 0; jj < 4; jj++) {
        int j0 = lane * 8 + 2 * jj;
        lw.b2[jj] = pack2(__ldg(&b_in[j0]), __ldg(&b_in[j0 + 1]));
#pragma unroll
        for (int a = 0; a < 6; a++)
            lw.w2[a][jj] = pack2(__ldg(&W_in[a * 256 + j0]),
                                 __ldg(&W_in[a * 256 + j0 + 1]));
    }

    const int chunks_total = (N_EDGES + ACH - 1) / ACH;
    const int cpw  = (chunks_total + WTOT - 1) / WTOT;
    const int c0   = wid * cpw;
    const int c1   = min(c0 + cpw, chunks_total);
    if (c0 >= c1) return;
    const int nch  = c1 - c0;
    const int eend = min(c1 * ACH, N_EDGES);

    // erec chunk: 8 edges x 2 float4 = 16 float4 -> lanes 0..15
    auto issue_erec = [&](int c) {
        if (c < nch && lane < 16) {
            size_t fbase = (size_t)(c0 + c) * (2 * ACH);
            if (fbase + lane < (size_t)2 * N_EDGES)
                cp16(&se[w][c & (ESLOT - 1)][lane >> 1][lane & 1], &g_erec[fbase + lane]);
        }
    };
    // xc fp16 rows: one 256B row = 16 lanes x 16B; 2 rows per warp-instr.
    auto issue_xc = [&](int c) {
        if (c < nch) {
            int b   = c & (XBUF - 1);
            int s   = c & (ESLOT - 1);
            int seg = lane & 15;
            int hlf = lane >> 4;
#pragma unroll
            for (int pr = 0; pr < ACH / 2; pr++) {
                int j = pr * 2 + hlf;
                int e = (c0 + c) * ACH + j;
                if (e < eend) {
                    int src = __float_as_int(se[w][s][j][0].x);
                    cp16(&sx[w][b][j][seg * 8], &g_xch4[(size_t)src * 16 + seg]);
                }
            }
        }
    };

    issue_erec(0); issue_erec(1); issue_erec(2); issue_erec(3);
    CP_COMMIT();
    CP_WAIT0();
    __syncwarp();
    issue_xc(0); issue_erec(4); CP_COMMIT();
    issue_xc(1); issue_erec(5); CP_COMMIT();
    issue_xc(2); issue_erec(6); CP_COMMIT();

    const u64 z = pack2(0.f, 0.f);
    u64 acc[4] = {z, z, z, z};
    int  cur = -1;
    bool first = true;

    for (int i = 0; i < nch; i++) {
        CP_WAIT2();          // completes G_i: xc(i) + erec(i+4)
        __syncwarp();
        issue_xc(i + 3);     // erec(i+3) resident since G_{i-1}
        issue_erec(i + 7);
        CP_COMMIT();

        int b = i & (XBUF - 1);
        int s = i & (ESLOT - 1);
#pragma unroll
        for (int j = 0; j < ACH; j++) {
            int e = (c0 + i) * ACH + j;
            if (e >= eend) break;
            float4 ra = se[w][s][j][0];
            float4 rb = se[w][s][j][1];
            int dst = __float_as_int(rb.w);
            if (dst != cur) {
                if (cur >= 0) {
                    flush_acc(acc, cur, lane, first);
                    first = false;
                }
                cur = dst;
            }
            const __half2* hp = reinterpret_cast<const __half2*>(&sx[w][b][j][lane * 4]);
            float2 f0 = __half22float2(hp[0]);
            float2 f1 = __half22float2(hp[1]);
            float4 xj = make_float4(f0.x, f0.y, f1.x, f1.y);
            edge_accum(acc, lw, ra, rb, xj);
        }
    }
    if (cur >= 0) flush_acc(acc, cur, lane, true);
}

// ------------------------------ output GEMM (tensor core) ------------------
#define KO_BK   32
#define KO_APAD 8
#define KO_BPAD 8

__device__ __forceinline__ void ldsm_x4(unsigned r[4], unsigned addr) {
    asm volatile("ldmatrix.sync.aligned.m8n8.x4.shared.b16 {%0,%1,%2,%3}, [%4];"
                 : "=r"(r[0]), "=r"(r[1]), "=r"(r[2]), "=r"(r[3]) : "r"(addr));
}
__device__ __forceinline__ void ldsm_x2t(unsigned r[2], unsigned addr) {
    asm volatile("ldmatrix.sync.aligned.m8n8.x2.trans.shared.b16 {%0,%1}, [%2];"
                 : "=r"(r[0]), "=r"(r[1]) : "r"(addr));
}
__device__ __forceinline__ void mma_bf16(float c[4], const unsigned a[4], const unsigned b[2]) {
    asm volatile("mma.sync.aligned.m16n8k16.row.col.f32.bf16.bf16.f32 "
                 "{%0,%1,%2,%3}, {%4,%5,%6,%7}, {%8,%9}, {%0,%1,%2,%3};"
                 : "+f"(c[0]), "+f"(c[1]), "+f"(c[2]), "+f"(c[3])
                 : "r"(a[0]), "r"(a[1]), "r"(a[2]), "r"(a[3]), "r"(b[0]), "r"(b[1]));
}

__global__ void __launch_bounds__(256, 2) k_out(
    const float* __restrict__ W,   // [256, 128]
    const float* __restrict__ bo,  // [128]
    float*       __restrict__ out) // [N, 128]
{
    __shared__ __align__(16) unsigned short Ah[128][KO_BK + KO_APAD];
    __shared__ __align__(16) unsigned short Al[128][KO_BK + KO_APAD];
    __shared__ __align__(16) unsigned short Bh[KO_BK][128 + KO_BPAD];
    __shared__ __align__(16) unsigned short Bl[KO_BK][128 + KO_BPAD];

    const int tid  = threadIdx.x;
    const int lane = tid & 31;
    const int warp = tid >> 5;
    const int wm   = warp >> 2;
    const int wn   = warp & 3;
    const int row0 = blockIdx.x * 128;

    const float* aggr = reinterpret_cast<const float*>(g_aggr4);

    float c[4][4][4];
#pragma unroll
    for (int mt = 0; mt < 4; mt++)
#pragma unroll
        for (int nt = 0; nt < 4; nt++)
#pragma unroll
            for (int q = 0; q < 4; q++) c[mt][nt][q] = 0.f;

    const unsigned sAh = (unsigned)__cvta_generic_to_shared(&Ah[0][0]);
    const unsigned sAl = (unsigned)__cvta_generic_to_shared(&Al[0][0]);
    const unsigned sBh = (unsigned)__cvta_generic_to_shared(&Bh[0][0]);
    const unsigned sBl = (unsigned)__cvta_generic_to_shared(&Bl[0][0]);
    const int a_row = wm * 64 + (lane & 15);
    const int a_kof = (lane >> 4) << 3;
    const int b_row = (lane & 15);
    const int b_col = wn * 32;

    for (int kc = 0; kc < CH_TOT; kc += KO_BK) {
#pragma unroll
        for (int g = 0; g < 4; g++) {
            int f   = tid + g * 256;
            int r   = f >> 3;
            int kq  = f & 7;
            int row = row0 + r;
            float4 v = make_float4(0.f, 0.f, 0.f, 0.f);
            if (row < N_NODES)
                v = __ldcs(reinterpret_cast<const float4*>(&aggr[(size_t)row * 256 + kc + kq * 4]));
            unsigned short h0 = f2bf(v.x), h1 = f2bf(v.y), h2 = f2bf(v.z), h3 = f2bf(v.w);
            unsigned short l0 = f2bf(v.x - bf2f(h0)), l1 = f2bf(v.y - bf2f(h1));
            unsigned short l2 = f2bf(v.z - bf2f(h2)), l3 = f2bf(v.w - bf2f(h3));
            *reinterpret_cast<unsigned*>(&Ah[r][kq * 4])     = (unsigned)h0 | ((unsigned)h1 << 16);
            *reinterpret_cast<unsigned*>(&Ah[r][kq * 4 + 2]) = (unsigned)h2 | ((unsigned)h3 << 16);
            *reinterpret_cast<unsigned*>(&Al[r][kq * 4])     = (unsigned)l0 | ((unsigned)l1 << 16);
            *reinterpret_cast<unsigned*>(&Al[r][kq * 4 + 2]) = (unsigned)l2 | ((unsigned)l3 << 16);
        }
#pragma unroll
        for (int g = 0; g < 4; g++) {
            int f  = tid + g * 256;
            int kr = f >> 5;
            int nq = f & 31;
            float4 v = *reinterpret_cast<const float4*>(&W[(size_t)(kc + kr) * 128 + nq * 4]);
            unsigned short h0 = f2bf(v.x), h1 = f2bf(v.y), h2 = f2bf(v.z), h3 = f2bf(v.w);
            unsigned short l0 = f2bf(v.x - bf2f(h0)), l1 = f2bf(v.y - bf2f(h1));
            unsigned short l2 = f2bf(v.z - bf2f(h2)), l3 = f2bf(v.w - bf2f(h3));
            *reinterpret_cast<unsigned*>(&Bh[kr][nq * 4])     = (unsigned)h0 | ((unsigned)h1 << 16);
            *reinterpret_cast<unsigned*>(&Bh[kr][nq * 4 + 2]) = (unsigned)h2 | ((unsigned)h3 << 16);
            *reinterpret_cast<unsigned*>(&Bl[kr][nq * 4])     = (unsigned)l0 | ((unsigned)l1 << 16);
            *reinterpret_cast<unsigned*>(&Bl[kr][nq * 4 + 2]) = (unsigned)l2 | ((unsigned)l3 << 16);
        }
        __syncthreads();

#pragma unroll
        for (int ks = 0; ks < KO_BK / 16; ks++) {
            unsigned bh[4][2], bl[4][2];
#pragma unroll
            for (int nt = 0; nt < 4; nt++) {
                unsigned boff = (unsigned)(((ks * 16 + b_row) * (128 + KO_BPAD) + b_col + nt * 8) * 2);
                ldsm_x2t(bh[nt], sBh + boff);
                ldsm_x2t(bl[nt], sBl + boff);
            }
#pragma unroll
            for (int mt = 0; mt < 4; mt++) {
                unsigned aoff = (unsigned)(((a_row + mt * 16) * (KO_BK + KO_APAD) + ks * 16 + a_kof) * 2);
                unsigned ah[4], al[4];
                ldsm_x4(ah, sAh + aoff);
                ldsm_x4(al, sAl + aoff);
#pragma unroll
                for (int nt = 0; nt < 4; nt++) {
                    mma_bf16(c[mt][nt], ah, bh[nt]);
                    mma_bf16(c[mt][nt], ah, bl[nt]);
                    mma_bf16(c[mt][nt], al, bh[nt]);
                }
            }
        }
        __syncthreads();
    }

    float bias[4][2];
#pragma unroll
    for (int nt = 0; nt < 4; nt++) {
        int col = wn * 32 + nt * 8 + (lane & 3) * 2;
        bias[nt][0] = __ldg(&bo[col]);
        bias[nt][1] = __ldg(&bo[col + 1]);
    }
#pragma unroll
    for (int mt = 0; mt < 4; mt++) {
#pragma unroll
        for (int nt = 0; nt < 4; nt++) {
            int rg0 = row0 + wm * 64 + mt * 16 + (lane >> 2);
            int col = wn * 32 + nt * 8 + (lane & 3) * 2;
            if (rg0 < N_NODES) {
                float2 o;
                o.x = tanhf(c[mt][nt][0] + bias[nt][0]);
                o.y = tanhf(c[mt][nt][1] + bias[nt][1]);
                __stcs(reinterpret_cast<float2*>(&out[(size_t)rg0 * 128 + col]), o);
            }
            int rg1 = rg0 + 8;
            if (rg1 < N_NODES) {
                float2 o;
                o.x = tanhf(c[mt][nt][2] + bias[nt][0]);
                o.y = tanhf(c[mt][nt][3] + bias[nt][1]);
                __stcs(reinterpret_cast<float2*>(&out[(size_t)rg1 * 128 + col]), o);
            }
        }
    }
}

// ------------------------------ launch -------------------------------------
// Fork/join: xc-table build runs on a forked stream, concurrent with the
// histogram -> scan -> fill -> zero_bnd chain on the main (legacy) stream.
// Streams/events are created per call (graph replay captures only the DAG;
// host-side creation cost is outside the timed graph). Not destroyed: destroy
// during an active capture risks invalidating it; a few leaked handles over
// <=3 calls are host-side only.
extern "C" void kernel_launch(void* const* d_in, const int* in_sizes, int n_in,
                              void* d_out, int out_size)
{
    const float* x     = (const float*)d_in[0];
    const float* na    = (const float*)d_in[1];
    const void*  ei    = d_in[2];
    const float* ea    = (const float*)d_in[3];
    const float* W_in  = (const float*)d_in[4];
    const float* b_in  = (const float*)d_in[5];
    const float* W_out = (const float*)d_in[6];
    const float* b_out = (const float*)d_in[7];
    float* out = (float*)d_out;

    cudaStream_t s1;
    cudaStreamCreateWithFlags(&s1, cudaStreamNonBlocking);
    cudaEvent_t eFork, eJoin;
    cudaEventCreateWithFlags(&eFork, cudaEventDisableTiming);
    cudaEventCreateWithFlags(&eJoin, cudaEventDisableTiming);

    k_probe<<<(N_NODES + 255) / 256, 256>>>((const long long*)ei);

    cudaEventRecord(eFork, 0);
    cudaStreamWaitEvent(s1, eFork, 0);

    // forked stream: xc table build
    k_xc<<<2048, 256, 0, s1>>>(x, na);

    // main stream: CSR pipeline
    k_hist<<<2048, 256>>>(ei);
    k_scan1<<<N_SCAN_BLOCKS, SCAN_BLK>>>();
    k_scan2<<<1, 256>>>();
    k_scan3<<<(N_NODES + 255) / 256, 256>>>();
    k_fill<<<2048, 256>>>(ei, ea);
    k_zero_bnd<<<400, 256>>>();

    cudaEventRecord(eJoin, s1);
    cudaStreamWaitEvent(0, eJoin, 0);

    k_aggr<<<AGG_BLOCKS, 32 * AW>>>(W_in, b_in);

    const int gemm_blocks = (N_NODES + 127) / 128;  // 782
    k_out<<<gemm_blocks, 256>>>(W_out, b_out, out);
}

// round 13
// speedup vs baseline: 2.5633x; 1.0294x over previous
#include <cuda_runtime.h>
#include <cuda_bf16.h>
#include <cuda_fp16.h>
#include <math.h>

#define N_NODES 100000
#define N_EDGES 1600000
#define IN_CH   128
#define HIDDEN  2
#define OUT_CH  128
#define ATTR    6
#define CH_TOT  (IN_CH * HIDDEN)   // 256

typedef unsigned long long u64;

// ------------------------------ scratch ------------------------------------
__device__ uint4  g_xch4[(size_t)N_NODES * 16];          // xc fp16: 256B/row, 25.6MB
__device__ float4 g_aggr4[(size_t)N_NODES * CH_TOT / 4]; // per-node aggregate 102.4MB
__device__ float4 g_erec[(size_t)2 * N_EDGES];           // CSR (src,a0,a1,a2)(a3,a4,a5,dst)
__device__ int    g_deg[N_NODES];
__device__ int    g_rowptr[N_NODES + 1];
__device__ int    g_cursor[N_NODES];
__device__ int    g_ei_is64;

#define SCAN_BLK 512
#define N_SCAN_BLOCKS ((N_NODES + SCAN_BLK - 1) / SCAN_BLK)  // 196
__device__ int g_blockSums[N_SCAN_BLOCKS];

// k_aggr decomposition constants (shared with the zero part of k_fillz)
#define AW    4                        // warps per block
#define ACH   8                        // edges per chunk
#define XBUF  4                        // xc buffers in flight
#define ESLOT 8                        // erec ring slots
#define AGG_BLOCKS 592
#define WTOT  (AGG_BLOCKS * AW)        // 2368 warps

#define ZB_BLOCKS   592                // zero-part blocks in k_fillz
#define FILL_BLOCKS 2048               // fill-part blocks in k_fillz

// ------------------------------ f32x2 helpers ------------------------------
__device__ __forceinline__ u64 pack2(float lo, float hi) {
    u64 d; asm("mov.b64 %0, {%1, %2};" : "=l"(d) : "f"(lo), "f"(hi)); return d;
}
__device__ __forceinline__ void unpack2(u64 d, float& lo, float& hi) {
    asm("mov.b64 {%0, %1}, %2;" : "=f"(lo), "=f"(hi) : "l"(d));
}
__device__ __forceinline__ u64 fma2(u64 a, u64 b, u64 c) {
    u64 d; asm("fma.rn.f32x2 %0, %1, %2, %3;" : "=l"(d) : "l"(a), "l"(b), "l"(c)); return d;
}

// ------------------------------ cp.async helpers ---------------------------
__device__ __forceinline__ void cp16(void* smem, const void* gmem) {
    unsigned s = (unsigned)__cvta_generic_to_shared(smem);
    asm volatile("cp.async.cg.shared.global [%0], [%1], 16;" :: "r"(s), "l"(gmem) : "memory");
}
#define CP_COMMIT() asm volatile("cp.async.commit_group;" ::: "memory")
#define CP_WAIT2()  asm volatile("cp.async.wait_group 2;" ::: "memory")
#define CP_WAIT0()  asm volatile("cp.async.wait_group 0;" ::: "memory")

// ------------------------------ bf16 helpers -------------------------------
__device__ __forceinline__ unsigned short f2bf(float a) {
    unsigned short h; asm("cvt.rn.bf16.f32 %0, %1;" : "=h"(h) : "f"(a)); return h;
}
__device__ __forceinline__ float bf2f(unsigned short h) {
    return __uint_as_float(((unsigned)h) << 16);
}

// ------------------------------ probe + zero deg ---------------------------
__global__ void k_probe(const long long* __restrict__ ei)
{
    int i = blockIdx.x * blockDim.x + threadIdx.x;
    if (i < N_NODES) g_deg[i] = 0;
    if (blockIdx.x == 0 && threadIdx.x < 32) {
        int bad = 0;
#pragma unroll
        for (int j = 0; j < 8; j++) {
            long long v = ei[threadIdx.x * 8 + j];
            if (v < 0 || v >= N_NODES) bad = 1;
        }
        unsigned m = __ballot_sync(0xFFFFFFFFu, bad);
        if (threadIdx.x == 0) g_ei_is64 = (m == 0) ? 1 : 0;
    }
}

// ------------- init: fused xc fp16 table build + dst histogram --------------
// Overlap by occupancy: memory-bound xc writes fill the latency bubbles of
// the atomic-bound histogram (same kernel, grid-stride both).
__global__ void k_init(const float* __restrict__ x, const float* __restrict__ na,
                       const void* __restrict__ ei)
{
    size_t i = (size_t)blockIdx.x * blockDim.x + threadIdx.x;
    size_t stride = (size_t)gridDim.x * blockDim.x;
    const int is64 = g_ei_is64;

    __half2* xch = reinterpret_cast<__half2*>(g_xch4);
    const size_t n_pairs = (size_t)N_NODES * 64;     // 64 half2 per node
    for (size_t j = i; j < n_pairs; j += stride) {
        int n  = (int)(j >> 6);
        int c2 = (int)(j & 63);
        float a, b;
        if (c2 < 63) {
            a = x[(size_t)n * 127 + 2 * c2];
            b = x[(size_t)n * 127 + 2 * c2 + 1];
        } else {
            a = x[(size_t)n * 127 + 126];
            b = na[n];
        }
        xch[j] = __floats2half2_rn(a, b);
    }

    if (is64) {
        const longlong2* d2 = reinterpret_cast<const longlong2*>(
            (const long long*)ei + N_EDGES);
        for (size_t k = i; k < N_EDGES / 2; k += stride) {
            longlong2 v = __ldg(&d2[k]);
            atomicAdd(&g_deg[(int)v.x], 1);
            atomicAdd(&g_deg[(int)v.y], 1);
        }
    } else {
        const int4* d4 = reinterpret_cast<const int4*>((const int*)ei + N_EDGES);
        for (size_t k = i; k < N_EDGES / 4; k += stride) {
            int4 v = __ldg(&d4[k]);
            atomicAdd(&g_deg[v.x], 1);
            atomicAdd(&g_deg[v.y], 1);
            atomicAdd(&g_deg[v.z], 1);
            atomicAdd(&g_deg[v.w], 1);
        }
    }
}

// ------------------------------ CSR scan -----------------------------------
__global__ void k_scan1()
{
    __shared__ int s[SCAN_BLK];
    int t = threadIdx.x;
    int idx = blockIdx.x * SCAN_BLK + t;
    int v = (idx < N_NODES) ? g_deg[idx] : 0;
    s[t] = v;
    __syncthreads();
#pragma unroll
    for (int off = 1; off < SCAN_BLK; off <<= 1) {
        int tv = (t >= off) ? s[t - off] : 0;
        __syncthreads();
        s[t] += tv;
        __syncthreads();
    }
    if (idx < N_NODES) g_rowptr[idx] = s[t] - v;   // exclusive within block
    if (t == SCAN_BLK - 1) g_blockSums[blockIdx.x] = s[t];  // block total
}

// Fused scan2+scan3: each block reduces blockSums[0..sblk) itself.
__global__ void k_scan3()
{
    __shared__ int sdata[256];
    int t = threadIdx.x;
    int sblk = blockIdx.x >> 1;   // 256-node block -> covering 512-node scan blk
    sdata[t] = (t < sblk) ? g_blockSums[t] : 0;   // sblk <= 195 < 256
    __syncthreads();
#pragma unroll
    for (int off = 128; off > 0; off >>= 1) {
        if (t < off) sdata[t] += sdata[t + off];
        __syncthreads();
    }
    int base = sdata[0];

    int idx = blockIdx.x * blockDim.x + t;
    if (idx < N_NODES) {
        int rp = g_rowptr[idx] + base;
        g_rowptr[idx] = rp;
        g_cursor[idx] = rp;
    }
    if (idx == 0) g_rowptr[N_NODES] = N_EDGES;
}

// ---------- fused: boundary/deg0 zeroing (blocks < ZB) + CSR fill ----------
// Both parts depend only on rowptr/cursor; they write disjoint buffers
// (aggr vs erec), so running them in one kernel = free overlap, no streams.
__global__ void k_fillz(const void* __restrict__ ei, const float* __restrict__ ea)
{
    if (blockIdx.x < ZB_BLOCKS) {
        // ---- zero part: warp-range boundary nodes (binary search on rowptr)
        const float4 z4 = make_float4(0.f, 0.f, 0.f, 0.f);

        int gw   = blockIdx.x * (blockDim.x >> 5) + (threadIdx.x >> 5);
        int lane = threadIdx.x & 31;
        if (gw < 2 * WTOT) {
            int r = gw >> 1;
            const int chunks_total = (N_EDGES + ACH - 1) / ACH;
            const int cpw = (chunks_total + WTOT - 1) / WTOT;
            const int c0  = r * cpw;
            const int c1  = min(c0 + cpw, chunks_total);
            if (c0 < c1) {
                int p = (gw & 1) ? (min(c1 * ACH, N_EDGES) - 1) : (c0 * ACH);
                int lo = 0, hi = N_NODES;
                while (lo + 1 < hi) {
                    int mid = (lo + hi) >> 1;
                    if (g_rowptr[mid] <= p) lo = mid; else hi = mid;
                }
                g_aggr4[(size_t)lo * 64 + lane * 2]     = z4;
                g_aggr4[(size_t)lo * 64 + lane * 2 + 1] = z4;
            }
        }
        // degree-0 nodes
        int n = blockIdx.x * blockDim.x + threadIdx.x;
        if (n < N_NODES && g_rowptr[n] == g_rowptr[n + 1]) {
            for (int q = 0; q < 64; q++) g_aggr4[(size_t)n * 64 + q] = z4;
        }
        return;
    }

    // ---- fill part: CSR-ordered edge records, pair-vectorized ----
    const int is64 = g_ei_is64;
    const float4* ea4 = reinterpret_cast<const float4*>(ea);
    int i = (blockIdx.x - ZB_BLOCKS) * blockDim.x + threadIdx.x;
    int stride = FILL_BLOCKS * blockDim.x;
    for (int p = i; p < N_EDGES / 2; p += stride) {
        int e = 2 * p;
        int s0, s1, d0, d1;
        if (is64) {
            const long long* ei64 = (const long long*)ei;
            longlong2 sv = __ldg(reinterpret_cast<const longlong2*>(ei64 + e));
            longlong2 dv = __ldg(reinterpret_cast<const longlong2*>(ei64 + N_EDGES + e));
            s0 = (int)sv.x; s1 = (int)sv.y; d0 = (int)dv.x; d1 = (int)dv.y;
        } else {
            const int* ei32 = (const int*)ei;
            int2 sv = __ldg(reinterpret_cast<const int2*>(ei32 + e));
            int2 dv = __ldg(reinterpret_cast<const int2*>(ei32 + N_EDGES + e));
            s0 = sv.x; s1 = sv.y; d0 = dv.x; d1 = dv.y;
        }
        float4 f0 = __ldg(&ea4[3 * (size_t)p]);
        float4 f1 = __ldg(&ea4[3 * (size_t)p + 1]);
        float4 f2 = __ldg(&ea4[3 * (size_t)p + 2]);
        int p0 = atomicAdd(&g_cursor[d0], 1);
        g_erec[(size_t)2 * p0]     = make_float4(__int_as_float(s0), f0.x, f0.y, f0.z);
        g_erec[(size_t)2 * p0 + 1] = make_float4(f0.w, f1.x, f1.y, __int_as_float(d0));
        int p1 = atomicAdd(&g_cursor[d1], 1);
        g_erec[(size_t)2 * p1]     = make_float4(__int_as_float(s1), f1.z, f1.w, f2.x);
        g_erec[(size_t)2 * p1 + 1] = make_float4(f2.y, f2.z, f2.w, __int_as_float(d1));
    }
}

// ------------------------------ aggregation --------------------------------
// Flat CSR ranges per warp; cp.async pipeline; fp16 xc rows (256B); ACH=8.
struct LaneW {
    u64 w2[6][4];
    u64 b2[4];
};

__device__ __forceinline__ void edge_accum(
    u64 acc[4], const LaneW& lw, float4 ra, float4 rb, float4 xj)
{
    u64 ee[6];
    ee[0] = pack2(ra.y, ra.y);  ee[1] = pack2(ra.z, ra.z);  ee[2] = pack2(ra.w, ra.w);
    ee[3] = pack2(rb.x, rb.x);  ee[4] = pack2(rb.y, rb.y);  ee[5] = pack2(rb.z, rb.z);
#pragma unroll
    for (int jj = 0; jj < 4; jj++) {
        u64 s = lw.b2[jj];
#pragma unroll
        for (int a = 0; a < 6; a++) s = fma2(ee[a], lw.w2[a][jj], s);
        float lo, hi;
        unpack2(s, lo, hi);
        lo = fmaxf(lo, 0.f);
        hi = fmaxf(hi, 0.f);
        float xv = (jj == 0) ? xj.x : (jj == 1) ? xj.y : (jj == 2) ? xj.z : xj.w;
        acc[jj] = fma2(pack2(lo, hi), pack2(xv, xv), acc[jj]);
    }
}

__device__ __forceinline__ void flush_acc(u64 acc[4], int node, int lane, bool use_atomic)
{
    float4 o1, o2;
    unpack2(acc[0], o1.x, o1.y);
    unpack2(acc[1], o1.z, o1.w);
    unpack2(acc[2], o2.x, o2.y);
    unpack2(acc[3], o2.z, o2.w);
    float* p = reinterpret_cast<float*>(g_aggr4) + (size_t)node * 256 + lane * 8;
    if (use_atomic) {
        asm volatile("red.global.add.v4.f32 [%0], {%1,%2,%3,%4};"
                     :: "l"(p), "f"(o1.x), "f"(o1.y), "f"(o1.z), "f"(o1.w) : "memory");
        asm volatile("red.global.add.v4.f32 [%0], {%1,%2,%3,%4};"
                     :: "l"(p + 4), "f"(o2.x), "f"(o2.y), "f"(o2.z), "f"(o2.w) : "memory");
    } else {
        __stcs(reinterpret_cast<float4*>(p),     o1);
        __stcs(reinterpret_cast<float4*>(p) + 1, o2);
    }
    const u64 z = pack2(0.f, 0.f);
    acc[0] = z; acc[1] = z; acc[2] = z; acc[3] = z;
}

__global__ void __launch_bounds__(32 * AW, 4) k_aggr(
    const float* __restrict__ W_in,
    const float* __restrict__ b_in)
{
    __shared__ __align__(16) __half sx[AW][XBUF][ACH][128];  // 32 KB
    __shared__ float4 se[AW][ESLOT][ACH][2];                 //  8 KB

    const int lane = threadIdx.x & 31;
    const int w    = threadIdx.x >> 5;
    const int wid  = blockIdx.x * AW + w;

    LaneW lw;
#pragma unroll
    for (int jj = 0; jj < 4; jj++) {
        int j0 = lane * 8 + 2 * jj;
        lw.b2[jj] = pack2(__ldg(&b_in[j0]), __ldg(&b_in[j0 + 1]));
#pragma unroll
        for (int a = 0; a < 6; a++)
            lw.w2[a][jj] = pack2(__ldg(&W_in[a * 256 + j0]),
                                 __ldg(&W_in[a * 256 + j0 + 1]));
    }

    const int chunks_total = (N_EDGES + ACH - 1) / ACH;
    const int cpw  = (chunks_total + WTOT - 1) / WTOT;
    const int c0   = wid * cpw;
    const int c1   = min(c0 + cpw, chunks_total);
    if (c0 >= c1) return;
    const int nch  = c1 - c0;
    const int eend = min(c1 * ACH, N_EDGES);

    // erec chunk: 8 edges x 2 float4 = 16 float4 -> lanes 0..15
    auto issue_erec = [&](int c) {
        if (c < nch && lane < 16) {
            size_t fbase = (size_t)(c0 + c) * (2 * ACH);
            if (fbase + lane < (size_t)2 * N_EDGES)
                cp16(&se[w][c & (ESLOT - 1)][lane >> 1][lane & 1], &g_erec[fbase + lane]);
        }
    };
    // xc fp16 rows: one 256B row = 16 lanes x 16B; 2 rows per warp-instr.
    auto issue_xc = [&](int c) {
        if (c < nch) {
            int b   = c & (XBUF - 1);
            int s   = c & (ESLOT - 1);
            int seg = lane & 15;
            int hlf = lane >> 4;
#pragma unroll
            for (int pr = 0; pr < ACH / 2; pr++) {
                int j = pr * 2 + hlf;
                int e = (c0 + c) * ACH + j;
                if (e < eend) {
                    int src = __float_as_int(se[w][s][j][0].x);
                    cp16(&sx[w][b][j][seg * 8], &g_xch4[(size_t)src * 16 + seg]);
                }
            }
        }
    };

    issue_erec(0); issue_erec(1); issue_erec(2); issue_erec(3);
    CP_COMMIT();
    CP_WAIT0();
    __syncwarp();
    issue_xc(0); issue_erec(4); CP_COMMIT();
    issue_xc(1); issue_erec(5); CP_COMMIT();
    issue_xc(2); issue_erec(6); CP_COMMIT();

    const u64 z = pack2(0.f, 0.f);
    u64 acc[4] = {z, z, z, z};
    int  cur = -1;
    bool first = true;

    for (int i = 0; i < nch; i++) {
        CP_WAIT2();          // completes G_i: xc(i) + erec(i+4)
        __syncwarp();
        issue_xc(i + 3);     // erec(i+3) resident since G_{i-1}
        issue_erec(i + 7);
        CP_COMMIT();

        int b = i & (XBUF - 1);
        int s = i & (ESLOT - 1);
        bool full = ((c0 + i + 1) * ACH) <= eend;
        if (full) {
#pragma unroll
            for (int j = 0; j < ACH; j++) {
                float4 ra = se[w][s][j][0];
                float4 rb = se[w][s][j][1];
                int dst = __float_as_int(rb.w);
                if (dst != cur) {
                    if (cur >= 0) {
                        flush_acc(acc, cur, lane, first);
                        first = false;
                    }
                    cur = dst;
                }
                const __half2* hp = reinterpret_cast<const __half2*>(&sx[w][b][j][lane * 4]);
                float2 f0 = __half22float2(hp[0]);
                float2 f1 = __half22float2(hp[1]);
                float4 xj = make_float4(f0.x, f0.y, f1.x, f1.y);
                edge_accum(acc, lw, ra, rb, xj);
            }
        } else {
#pragma unroll
            for (int j = 0; j < ACH; j++) {
                int e = (c0 + i) * ACH + j;
                if (e >= eend) break;
                float4 ra = se[w][s][j][0];
                float4 rb = se[w][s][j][1];
                int dst = __float_as_int(rb.w);
                if (dst != cur) {
                    if (cur >= 0) {
                        flush_acc(acc, cur, lane, first);
                        first = false;
                    }
                    cur = dst;
                }
                const __half2* hp = reinterpret_cast<const __half2*>(&sx[w][b][j][lane * 4]);
                float2 f0 = __half22float2(hp[0]);
                float2 f1 = __half22float2(hp[1]);
                float4 xj = make_float4(f0.x, f0.y, f1.x, f1.y);
                edge_accum(acc, lw, ra, rb, xj);
            }
        }
    }
    if (cur >= 0) flush_acc(acc, cur, lane, true);
}

// ------------------------------ output GEMM (tensor core) ------------------
#define KO_BK   32
#define KO_APAD 8
#define KO_BPAD 8

__device__ __forceinline__ void ldsm_x4(unsigned r[4], unsigned addr) {
    asm volatile("ldmatrix.sync.aligned.m8n8.x4.shared.b16 {%0,%1,%2,%3}, [%4];"
                 : "=r"(r[0]), "=r"(r[1]), "=r"(r[2]), "=r"(r[3]) : "r"(addr));
}
__device__ __forceinline__ void ldsm_x2t(unsigned r[2], unsigned addr) {
    asm volatile("ldmatrix.sync.aligned.m8n8.x2.trans.shared.b16 {%0,%1}, [%2];"
                 : "=r"(r[0]), "=r"(r[1]) : "r"(addr));
}
__device__ __forceinline__ void mma_bf16(float c[4], const unsigned a[4], const unsigned b[2]) {
    asm volatile("mma.sync.aligned.m16n8k16.row.col.f32.bf16.bf16.f32 "
                 "{%0,%1,%2,%3}, {%4,%5,%6,%7}, {%8,%9}, {%0,%1,%2,%3};"
                 : "+f"(c[0]), "+f"(c[1]), "+f"(c[2]), "+f"(c[3])
                 : "r"(a[0]), "r"(a[1]), "r"(a[2]), "r"(a[3]), "r"(b[0]), "r"(b[1]));
}

__global__ void __launch_bounds__(256, 2) k_out(
    const float* __restrict__ W,   // [256, 128]
    const float* __restrict__ bo,  // [128]
    float*       __restrict__ out) // [N, 128]
{
    __shared__ __align__(16) unsigned short Ah[128][KO_BK + KO_APAD];
    __shared__ __align__(16) unsigned short Al[128][KO_BK + KO_APAD];
    __shared__ __align__(16) unsigned short Bh[KO_BK][128 + KO_BPAD];
    __shared__ __align__(16) unsigned short Bl[KO_BK][128 + KO_BPAD];

    const int tid  = threadIdx.x;
    const int lane = tid & 31;
    const int warp = tid >> 5;
    const int wm   = warp >> 2;
    const int wn   = warp & 3;
    const int row0 = blockIdx.x * 128;

    const float* aggr = reinterpret_cast<const float*>(g_aggr4);

    float c[4][4][4];
#pragma unroll
    for (int mt = 0; mt < 4; mt++)
#pragma unroll
        for (int nt = 0; nt < 4; nt++)
#pragma unroll
            for (int q = 0; q < 4; q++) c[mt][nt][q] = 0.f;

    const unsigned sAh = (unsigned)__cvta_generic_to_shared(&Ah[0][0]);
    const unsigned sAl = (unsigned)__cvta_generic_to_shared(&Al[0][0]);
    const unsigned sBh = (unsigned)__cvta_generic_to_shared(&Bh[0][0]);
    const unsigned sBl = (unsigned)__cvta_generic_to_shared(&Bl[0][0]);
    const int a_row = wm * 64 + (lane & 15);
    const int a_kof = (lane >> 4) << 3;
    const int b_row = (lane & 15);
    const int b_col = wn * 32;

    for (int kc = 0; kc < CH_TOT; kc += KO_BK) {
#pragma unroll
        for (int g = 0; g < 4; g++) {
            int f   = tid + g * 256;
            int r   = f >> 3;
            int kq  = f & 7;
            int row = row0 + r;
            float4 v = make_float4(0.f, 0.f, 0.f, 0.f);
            if (row < N_NODES)
                v = __ldcs(reinterpret_cast<const float4*>(&aggr[(size_t)row * 256 + kc + kq * 4]));
            unsigned short h0 = f2bf(v.x), h1 = f2bf(v.y), h2 = f2bf(v.z), h3 = f2bf(v.w);
            unsigned short l0 = f2bf(v.x - bf2f(h0)), l1 = f2bf(v.y - bf2f(h1));
            unsigned short l2 = f2bf(v.z - bf2f(h2)), l3 = f2bf(v.w - bf2f(h3));
            *reinterpret_cast<unsigned*>(&Ah[r][kq * 4])     = (unsigned)h0 | ((unsigned)h1 << 16);
            *reinterpret_cast<unsigned*>(&Ah[r][kq * 4 + 2]) = (unsigned)h2 | ((unsigned)h3 << 16);
            *reinterpret_cast<unsigned*>(&Al[r][kq * 4])     = (unsigned)l0 | ((unsigned)l1 << 16);
            *reinterpret_cast<unsigned*>(&Al[r][kq * 4 + 2]) = (unsigned)l2 | ((unsigned)l3 << 16);
        }
#pragma unroll
        for (int g = 0; g < 4; g++) {
            int f  = tid + g * 256;
            int kr = f >> 5;
            int nq = f & 31;
            float4 v = *reinterpret_cast<const float4*>(&W[(size_t)(kc + kr) * 128 + nq * 4]);
            unsigned short h0 = f2bf(v.x), h1 = f2bf(v.y), h2 = f2bf(v.z), h3 = f2bf(v.w);
            unsigned short l0 = f2bf(v.x - bf2f(h0)), l1 = f2bf(v.y - bf2f(h1));
            unsigned short l2 = f2bf(v.z - bf2f(h2)), l3 = f2bf(v.w - bf2f(h3));
            *reinterpret_cast<unsigned*>(&Bh[kr][nq * 4])     = (unsigned)h0 | ((unsigned)h1 << 16);
            *reinterpret_cast<unsigned*>(&Bh[kr][nq * 4 + 2]) = (unsigned)h2 | ((unsigned)h3 << 16);
            *reinterpret_cast<unsigned*>(&Bl[kr][nq * 4])     = (unsigned)l0 | ((unsigned)l1 << 16);
            *reinterpret_cast<unsigned*>(&Bl[kr][nq * 4 + 2]) = (unsigned)l2 | ((unsigned)l3 << 16);
        }
        __syncthreads();

#pragma unroll
        for (int ks = 0; ks < KO_BK / 16; ks++) {
            unsigned bh[4][2], bl[4][2];
#pragma unroll
            for (int nt = 0; nt < 4; nt++) {
                unsigned boff = (unsigned)(((ks * 16 + b_row) * (128 + KO_BPAD) + b_col + nt * 8) * 2);
                ldsm_x2t(bh[nt], sBh + boff);
                ldsm_x2t(bl[nt], sBl + boff);
            }
#pragma unroll
            for (int mt = 0; mt < 4; mt++) {
                unsigned aoff = (unsigned)(((a_row + mt * 16) * (KO_BK + KO_APAD) + ks * 16 + a_kof) * 2);
                unsigned ah[4], al[4];
                ldsm_x4(ah, sAh + aoff);
                ldsm_x4(al, sAl + aoff);
#pragma unroll
                for (int nt = 0; nt < 4; nt++) {
                    mma_bf16(c[mt][nt], ah, bh[nt]);
                    mma_bf16(c[mt][nt], ah, bl[nt]);
                    mma_bf16(c[mt][nt], al, bh[nt]);
                }
            }
        }
        __syncthreads();
    }

    float bias[4][2];
#pragma unroll
    for (int nt = 0; nt < 4; nt++) {
        int col = wn * 32 + nt * 8 + (lane & 3) * 2;
        bias[nt][0] = __ldg(&bo[col]);
        bias[nt][1] = __ldg(&bo[col + 1]);
    }
#pragma unroll
    for (int mt = 0; mt < 4; mt++) {
#pragma unroll
        for (int nt = 0; nt < 4; nt++) {
            int rg0 = row0 + wm * 64 + mt * 16 + (lane >> 2);
            int col = wn * 32 + nt * 8 + (lane & 3) * 2;
            if (rg0 < N_NODES) {
                float2 o;
                o.x = tanhf(c[mt][nt][0] + bias[nt][0]);
                o.y = tanhf(c[mt][nt][1] + bias[nt][1]);
                __stcs(reinterpret_cast<float2*>(&out[(size_t)rg0 * 128 + col]), o);
            }
            int rg1 = rg0 + 8;
            if (rg1 < N_NODES) {
                float2 o;
                o.x = tanhf(c[mt][nt][2] + bias[nt][0]);
                o.y = tanhf(c[mt][nt][3] + bias[nt][1]);
                __stcs(reinterpret_cast<float2*>(&out[(size_t)rg1 * 128 + col]), o);
            }
        }
    }
}

// ------------------------------ launch -------------------------------------
// Single default stream; NO stream/event creation (allocation guard).
// Overlap achieved by kernel fusion: k_init = xc+hist, k_fillz = zero+fill.
extern "C" void kernel_launch(void* const* d_in, const int* in_sizes, int n_in,
                              void* d_out, int out_size)
{
    const float* x     = (const float*)d_in[0];
    const float* na    = (const float*)d_in[1];
    const void*  ei    = d_in[2];
    const float* ea    = (const float*)d_in[3];
    const float* W_in  = (const float*)d_in[4];
    const float* b_in  = (const float*)d_in[5];
    const float* W_out = (const float*)d_in[6];
    const float* b_out = (const float*)d_in[7];
    float* out = (float*)d_out;

    k_probe<<<(N_NODES + 255) / 256, 256>>>((const long long*)ei);
    k_init<<<4096, 256>>>(x, na, ei);

    k_scan1<<<N_SCAN_BLOCKS, SCAN_BLK>>>();
    k_scan3<<<(N_NODES + 255) / 256, 256>>>();    // fused scan2+scan3

    k_fillz<<<ZB_BLOCKS + FILL_BLOCKS, 256>>>(ei, ea);

    k_aggr<<<AGG_BLOCKS, 32 * AW>>>(W_in, b_in);

    const int gemm_blocks = (N_NODES + 127) / 128;  // 782
    k_out<<<gemm_blocks, 256>>>(W_out, b_out, out);
}

// round 14
// speedup vs baseline: 2.6103x; 1.0183x over previous
#include <cuda_runtime.h>
#include <cuda_bf16.h>
#include <cuda_fp16.h>
#include <math.h>

#define N_NODES 100000
#define N_EDGES 1600000
#define IN_CH   128
#define HIDDEN  2
#define OUT_CH  128
#define ATTR    6
#define CH_TOT  (IN_CH * HIDDEN)   // 256

typedef unsigned long long u64;

// ------------------------------ scratch ------------------------------------
__device__ uint4  g_xch4[(size_t)N_NODES * 16];          // xc fp16: 256B/row, 25.6MB
__device__ float4 g_aggr4[(size_t)N_NODES * CH_TOT / 4]; // per-node aggregate 102.4MB
__device__ uint4  g_erec[(size_t)N_EDGES];               // CSR (src, eid, dst, 0) 25.6MB
__device__ int    g_deg[N_NODES];
__device__ int    g_rowptr[N_NODES + 1];
__device__ int    g_cursor[N_NODES];
__device__ int    g_ei_is64;

#define SCAN_BLK 512
#define N_SCAN_BLOCKS ((N_NODES + SCAN_BLK - 1) / SCAN_BLK)  // 196
__device__ int g_blockSums[N_SCAN_BLOCKS];

// k_aggr decomposition constants (shared with the zero part of k_fillz)
#define AW    4                        // warps per block
#define ACH   8                        // edges per chunk (N_EDGES % ACH == 0)
#define XBUF  4                        // xc/ea buffers in flight
#define ESLOT 8                        // erec ring slots
#define AGG_BLOCKS 592
#define WTOT  (AGG_BLOCKS * AW)        // 2368 warps

#define ZB_BLOCKS   592                // zero-part blocks in k_fillz
#define FILL_BLOCKS 2048               // fill-part blocks in k_fillz

// ------------------------------ f32x2 helpers ------------------------------
__device__ __forceinline__ u64 pack2(float lo, float hi) {
    u64 d; asm("mov.b64 %0, {%1, %2};" : "=l"(d) : "f"(lo), "f"(hi)); return d;
}
__device__ __forceinline__ void unpack2(u64 d, float& lo, float& hi) {
    asm("mov.b64 {%0, %1}, %2;" : "=f"(lo), "=f"(hi) : "l"(d));
}
__device__ __forceinline__ u64 fma2(u64 a, u64 b, u64 c) {
    u64 d; asm("fma.rn.f32x2 %0, %1, %2, %3;" : "=l"(d) : "l"(a), "l"(b), "l"(c)); return d;
}

// ------------------------------ cp.async helpers ---------------------------
__device__ __forceinline__ void cp16(void* smem, const void* gmem) {
    unsigned s = (unsigned)__cvta_generic_to_shared(smem);
    asm volatile("cp.async.cg.shared.global [%0], [%1], 16;" :: "r"(s), "l"(gmem) : "memory");
}
__device__ __forceinline__ void cp8(void* smem, const void* gmem) {
    unsigned s = (unsigned)__cvta_generic_to_shared(smem);
    asm volatile("cp.async.ca.shared.global [%0], [%1], 8;" :: "r"(s), "l"(gmem) : "memory");
}
#define CP_COMMIT() asm volatile("cp.async.commit_group;" ::: "memory")
#define CP_WAIT2()  asm volatile("cp.async.wait_group 2;" ::: "memory")
#define CP_WAIT0()  asm volatile("cp.async.wait_group 0;" ::: "memory")

// ------------------------------ bf16 helpers -------------------------------
__device__ __forceinline__ unsigned short f2bf(float a) {
    unsigned short h; asm("cvt.rn.bf16.f32 %0, %1;" : "=h"(h) : "f"(a)); return h;
}
__device__ __forceinline__ float bf2f(unsigned short h) {
    return __uint_as_float(((unsigned)h) << 16);
}

// ------------------------------ probe + zero deg ---------------------------
__global__ void k_probe(const long long* __restrict__ ei)
{
    int i = blockIdx.x * blockDim.x + threadIdx.x;
    if (i < N_NODES) g_deg[i] = 0;
    if (blockIdx.x == 0 && threadIdx.x < 32) {
        int bad = 0;
#pragma unroll
        for (int j = 0; j < 8; j++) {
            long long v = ei[threadIdx.x * 8 + j];
            if (v < 0 || v >= N_NODES) bad = 1;
        }
        unsigned m = __ballot_sync(0xFFFFFFFFu, bad);
        if (threadIdx.x == 0) g_ei_is64 = (m == 0) ? 1 : 0;
    }
}

// ------------- init: fused xc fp16 table build + dst histogram --------------
__global__ void k_init(const float* __restrict__ x, const float* __restrict__ na,
                       const void* __restrict__ ei)
{
    size_t i = (size_t)blockIdx.x * blockDim.x + threadIdx.x;
    size_t stride = (size_t)gridDim.x * blockDim.x;
    const int is64 = g_ei_is64;

    __half2* xch = reinterpret_cast<__half2*>(g_xch4);
    const size_t n_pairs = (size_t)N_NODES * 64;     // 64 half2 per node
    for (size_t j = i; j < n_pairs; j += stride) {
        int n  = (int)(j >> 6);
        int c2 = (int)(j & 63);
        float a, b;
        if (c2 < 63) {
            a = x[(size_t)n * 127 + 2 * c2];
            b = x[(size_t)n * 127 + 2 * c2 + 1];
        } else {
            a = x[(size_t)n * 127 + 126];
            b = na[n];
        }
        xch[j] = __floats2half2_rn(a, b);
    }

    if (is64) {
        const longlong2* d2 = reinterpret_cast<const longlong2*>(
            (const long long*)ei + N_EDGES);
        for (size_t k = i; k < N_EDGES / 2; k += stride) {
            longlong2 v = __ldg(&d2[k]);
            atomicAdd(&g_deg[(int)v.x], 1);
            atomicAdd(&g_deg[(int)v.y], 1);
        }
    } else {
        const int4* d4 = reinterpret_cast<const int4*>((const int*)ei + N_EDGES);
        for (size_t k = i; k < N_EDGES / 4; k += stride) {
            int4 v = __ldg(&d4[k]);
            atomicAdd(&g_deg[v.x], 1);
            atomicAdd(&g_deg[v.y], 1);
            atomicAdd(&g_deg[v.z], 1);
            atomicAdd(&g_deg[v.w], 1);
        }
    }
}

// ------------------------------ CSR scan -----------------------------------
__global__ void k_scan1()
{
    __shared__ int s[SCAN_BLK];
    int t = threadIdx.x;
    int idx = blockIdx.x * SCAN_BLK + t;
    int v = (idx < N_NODES) ? g_deg[idx] : 0;
    s[t] = v;
    __syncthreads();
#pragma unroll
    for (int off = 1; off < SCAN_BLK; off <<= 1) {
        int tv = (t >= off) ? s[t - off] : 0;
        __syncthreads();
        s[t] += tv;
        __syncthreads();
    }
    if (idx < N_NODES) g_rowptr[idx] = s[t] - v;   // exclusive within block
    if (t == SCAN_BLK - 1) g_blockSums[blockIdx.x] = s[t];  // block total
}

// Fused scan2+scan3: each block reduces blockSums[0..sblk) itself.
__global__ void k_scan3()
{
    __shared__ int sdata[256];
    int t = threadIdx.x;
    int sblk = blockIdx.x >> 1;
    sdata[t] = (t < sblk) ? g_blockSums[t] : 0;
    __syncthreads();
#pragma unroll
    for (int off = 128; off > 0; off >>= 1) {
        if (t < off) sdata[t] += sdata[t + off];
        __syncthreads();
    }
    int base = sdata[0];

    int idx = blockIdx.x * blockDim.x + t;
    if (idx < N_NODES) {
        int rp = g_rowptr[idx] + base;
        g_rowptr[idx] = rp;
        g_cursor[idx] = rp;
    }
    if (idx == 0) g_rowptr[N_NODES] = N_EDGES;
}

// ---------- fused: boundary/deg0 zeroing (blocks < ZB) + CSR fill ----------
// Fill now writes only a 16B record (src, eid, dst, 0) per edge: one STG.128.
__global__ void k_fillz(const void* __restrict__ ei)
{
    if (blockIdx.x < ZB_BLOCKS) {
        const float4 z4 = make_float4(0.f, 0.f, 0.f, 0.f);

        int gw   = blockIdx.x * (blockDim.x >> 5) + (threadIdx.x >> 5);
        int lane = threadIdx.x & 31;
        if (gw < 2 * WTOT) {
            int r = gw >> 1;
            const int chunks_total = N_EDGES / ACH;
            const int cpw = (chunks_total + WTOT - 1) / WTOT;
            const int c0  = r * cpw;
            const int c1  = min(c0 + cpw, chunks_total);
            if (c0 < c1) {
                int p = (gw & 1) ? (c1 * ACH - 1) : (c0 * ACH);
                int lo = 0, hi = N_NODES;
                while (lo + 1 < hi) {
                    int mid = (lo + hi) >> 1;
                    if (g_rowptr[mid] <= p) lo = mid; else hi = mid;
                }
                g_aggr4[(size_t)lo * 64 + lane * 2]     = z4;
                g_aggr4[(size_t)lo * 64 + lane * 2 + 1] = z4;
            }
        }
        int n = blockIdx.x * blockDim.x + threadIdx.x;
        if (n < N_NODES && g_rowptr[n] == g_rowptr[n + 1]) {
            for (int q = 0; q < 64; q++) g_aggr4[(size_t)n * 64 + q] = z4;
        }
        return;
    }

    const int is64 = g_ei_is64;
    int i = (blockIdx.x - ZB_BLOCKS) * blockDim.x + threadIdx.x;
    int stride = FILL_BLOCKS * blockDim.x;
    for (int p = i; p < N_EDGES / 2; p += stride) {
        int e = 2 * p;
        int s0, s1, d0, d1;
        if (is64) {
            const long long* ei64 = (const long long*)ei;
            longlong2 sv = __ldg(reinterpret_cast<const longlong2*>(ei64 + e));
            longlong2 dv = __ldg(reinterpret_cast<const longlong2*>(ei64 + N_EDGES + e));
            s0 = (int)sv.x; s1 = (int)sv.y; d0 = (int)dv.x; d1 = (int)dv.y;
        } else {
            const int* ei32 = (const int*)ei;
            int2 sv = __ldg(reinterpret_cast<const int2*>(ei32 + e));
            int2 dv = __ldg(reinterpret_cast<const int2*>(ei32 + N_EDGES + e));
            s0 = sv.x; s1 = sv.y; d0 = dv.x; d1 = dv.y;
        }
        int p0 = atomicAdd(&g_cursor[d0], 1);
        g_erec[p0] = make_uint4((unsigned)s0, (unsigned)e, (unsigned)d0, 0u);
        int p1 = atomicAdd(&g_cursor[d1], 1);
        g_erec[p1] = make_uint4((unsigned)s1, (unsigned)(e + 1), (unsigned)d1, 0u);
    }
}

// ------------------------------ aggregation --------------------------------
// Flat CSR ranges per warp. Pipeline: rec (cp16) -> {xc gather (cp16) + ea
// fetch (cp8, via eid)} -> compute. ea stays fp32 (no extra precision loss).
struct LaneW {
    u64 w2[6][4];
    u64 b2[4];
};

__device__ __forceinline__ void edge_accum(
    u64 acc[4], const LaneW& lw, float4 a03, float2 a45, float4 xj)
{
    u64 ee[6];
    ee[0] = pack2(a03.x, a03.x);  ee[1] = pack2(a03.y, a03.y);
    ee[2] = pack2(a03.z, a03.z);  ee[3] = pack2(a03.w, a03.w);
    ee[4] = pack2(a45.x, a45.x);  ee[5] = pack2(a45.y, a45.y);
#pragma unroll
    for (int jj = 0; jj < 4; jj++) {
        u64 s = lw.b2[jj];
#pragma unroll
        for (int a = 0; a < 6; a++) s = fma2(ee[a], lw.w2[a][jj], s);
        float lo, hi;
        unpack2(s, lo, hi);
        lo = fmaxf(lo, 0.f);
        hi = fmaxf(hi, 0.f);
        float xv = (jj == 0) ? xj.x : (jj == 1) ? xj.y : (jj == 2) ? xj.z : xj.w;
        acc[jj] = fma2(pack2(lo, hi), pack2(xv, xv), acc[jj]);
    }
}

__device__ __forceinline__ void flush_acc(u64 acc[4], int node, int lane, bool use_atomic)
{
    float4 o1, o2;
    unpack2(acc[0], o1.x, o1.y);
    unpack2(acc[1], o1.z, o1.w);
    unpack2(acc[2], o2.x, o2.y);
    unpack2(acc[3], o2.z, o2.w);
    float* p = reinterpret_cast<float*>(g_aggr4) + (size_t)node * 256 + lane * 8;
    if (use_atomic) {
        asm volatile("red.global.add.v4.f32 [%0], {%1,%2,%3,%4};"
                     :: "l"(p), "f"(o1.x), "f"(o1.y), "f"(o1.z), "f"(o1.w) : "memory");
        asm volatile("red.global.add.v4.f32 [%0], {%1,%2,%3,%4};"
                     :: "l"(p + 4), "f"(o2.x), "f"(o2.y), "f"(o2.z), "f"(o2.w) : "memory");
    } else {
        __stcs(reinterpret_cast<float4*>(p),     o1);
        __stcs(reinterpret_cast<float4*>(p) + 1, o2);
    }
    const u64 z = pack2(0.f, 0.f);
    acc[0] = z; acc[1] = z; acc[2] = z; acc[3] = z;
}

__global__ void __launch_bounds__(32 * AW, 4) k_aggr(
    const float* __restrict__ ea,    // [E, 6]
    const float* __restrict__ W_in,  // [6, 256]
    const float* __restrict__ b_in)  // [256]
{
    __shared__ __align__(16) __half sx[AW][XBUF][ACH][128];  // 32 KB
    __shared__ __align__(16) float  sa[AW][XBUF][ACH][8];    //  4 KB (24B attrs, 32B slot)
    __shared__ __align__(16) uint4  se[AW][ESLOT][ACH];      //  4 KB

    const int lane = threadIdx.x & 31;
    const int w    = threadIdx.x >> 5;
    const int wid  = blockIdx.x * AW + w;

    LaneW lw;
#pragma unroll
    for (int jj = 0; jj < 4; jj++) {
        int j0 = lane * 8 + 2 * jj;
        lw.b2[jj] = pack2(__ldg(&b_in[j0]), __ldg(&b_in[j0 + 1]));
#pragma unroll
        for (int a = 0; a < 6; a++)
            lw.w2[a][jj] = pack2(__ldg(&W_in[a * 256 + j0]),
                                 __ldg(&W_in[a * 256 + j0 + 1]));
    }

    const float2* ea2 = reinterpret_cast<const float2*>(ea);

    const int chunks_total = N_EDGES / ACH;   // exact: N_EDGES % ACH == 0
    const int cpw  = (chunks_total + WTOT - 1) / WTOT;
    const int c0   = wid * cpw;
    const int c1   = min(c0 + cpw, chunks_total);
    if (c0 >= c1) return;
    const int nch  = c1 - c0;

    // rec chunk: 8 edges x 16B -> lanes 0..7
    auto issue_erec = [&](int c) {
        if (c < nch && lane < 8)
            cp16(&se[w][c & (ESLOT - 1)][lane], &g_erec[(size_t)(c0 + c) * ACH + lane]);
    };
    // xc (fp16 rows, 2 rows per warp-instr) + ea (3 lanes x 8B per edge)
    auto issue_xcea = [&](int c) {
        if (c < nch) {
            int b   = c & (XBUF - 1);
            int s   = c & (ESLOT - 1);
            int seg = lane & 15;
            int hlf = lane >> 4;
#pragma unroll
            for (int pr = 0; pr < ACH / 2; pr++) {
                int j = pr * 2 + hlf;
                int src = (int)se[w][s][j].x;
                cp16(&sx[w][b][j][seg * 8], &g_xch4[(size_t)src * 16 + seg]);
            }
            if (lane < 3 * ACH) {
                int j  = lane / 3;
                int wd = lane % 3;
                int eid = (int)se[w][s][j].y;
                cp8(&sa[w][b][j][wd * 2], &ea2[(size_t)eid * 3 + wd]);
            }
        }
    };

    issue_erec(0); issue_erec(1); issue_erec(2); issue_erec(3);
    CP_COMMIT();
    CP_WAIT0();
    __syncwarp();
    issue_xcea(0); issue_erec(4); CP_COMMIT();
    issue_xcea(1); issue_erec(5); CP_COMMIT();
    issue_xcea(2); issue_erec(6); CP_COMMIT();

    const u64 z = pack2(0.f, 0.f);
    u64 acc[4] = {z, z, z, z};
    int  cur = -1;
    bool first = true;

    for (int i = 0; i < nch; i++) {
        CP_WAIT2();          // completes G_i: xc/ea(i) + erec(i+4)
        __syncwarp();
        issue_xcea(i + 3);   // erec(i+3) resident since G_{i-1}
        issue_erec(i + 7);
        CP_COMMIT();

        int b = i & (XBUF - 1);
        int s = i & (ESLOT - 1);
#pragma unroll
        for (int j = 0; j < ACH; j++) {
            int dst = (int)se[w][s][j].z;
            if (dst != cur) {
                if (cur >= 0) {
                    flush_acc(acc, cur, lane, first);
                    first = false;
                }
                cur = dst;
            }
            float4 a03 = *reinterpret_cast<const float4*>(&sa[w][b][j][0]);
            float2 a45 = *reinterpret_cast<const float2*>(&sa[w][b][j][4]);
            const __half2* hp = reinterpret_cast<const __half2*>(&sx[w][b][j][lane * 4]);
            float2 f0 = __half22float2(hp[0]);
            float2 f1 = __half22float2(hp[1]);
            float4 xj = make_float4(f0.x, f0.y, f1.x, f1.y);
            edge_accum(acc, lw, a03, a45, xj);
        }
    }
    if (cur >= 0) flush_acc(acc, cur, lane, true);
}

// ------------------------------ output GEMM (tensor core) ------------------
#define KO_BK   32
#define KO_APAD 8
#define KO_BPAD 8

__device__ __forceinline__ void ldsm_x4(unsigned r[4], unsigned addr) {
    asm volatile("ldmatrix.sync.aligned.m8n8.x4.shared.b16 {%0,%1,%2,%3}, [%4];"
                 : "=r"(r[0]), "=r"(r[1]), "=r"(r[2]), "=r"(r[3]) : "r"(addr));
}
__device__ __forceinline__ void ldsm_x2t(unsigned r[2], unsigned addr) {
    asm volatile("ldmatrix.sync.aligned.m8n8.x2.trans.shared.b16 {%0,%1}, [%2];"
                 : "=r"(r[0]), "=r"(r[1]) : "r"(addr));
}
__device__ __forceinline__ void mma_bf16(float c[4], const unsigned a[4], const unsigned b[2]) {
    asm volatile("mma.sync.aligned.m16n8k16.row.col.f32.bf16.bf16.f32 "
                 "{%0,%1,%2,%3}, {%4,%5,%6,%7}, {%8,%9}, {%0,%1,%2,%3};"
                 : "+f"(c[0]), "+f"(c[1]), "+f"(c[2]), "+f"(c[3])
                 : "r"(a[0]), "r"(a[1]), "r"(a[2]), "r"(a[3]), "r"(b[0]), "r"(b[1]));
}

__global__ void __launch_bounds__(256, 2) k_out(
    const float* __restrict__ W,   // [256, 128]
    const float* __restrict__ bo,  // [128]
    float*       __restrict__ out) // [N, 128]
{
    __shared__ __align__(16) unsigned short Ah[128][KO_BK + KO_APAD];
    __shared__ __align__(16) unsigned short Al[128][KO_BK + KO_APAD];
    __shared__ __align__(16) unsigned short Bh[KO_BK][128 + KO_BPAD];
    __shared__ __align__(16) unsigned short Bl[KO_BK][128 + KO_BPAD];

    const int tid  = threadIdx.x;
    const int lane = tid & 31;
    const int warp = tid >> 5;
    const int wm   = warp >> 2;
    const int wn   = warp & 3;
    const int row0 = blockIdx.x * 128;

    const float* aggr = reinterpret_cast<const float*>(g_aggr4);

    float c[4][4][4];
#pragma unroll
    for (int mt = 0; mt < 4; mt++)
#pragma unroll
        for (int nt = 0; nt < 4; nt++)
#pragma unroll
            for (int q = 0; q < 4; q++) c[mt][nt][q] = 0.f;

    const unsigned sAh = (unsigned)__cvta_generic_to_shared(&Ah[0][0]);
    const unsigned sAl = (unsigned)__cvta_generic_to_shared(&Al[0][0]);
    const unsigned sBh = (unsigned)__cvta_generic_to_shared(&Bh[0][0]);
    const unsigned sBl = (unsigned)__cvta_generic_to_shared(&Bl[0][0]);
    const int a_row = wm * 64 + (lane & 15);
    const int a_kof = (lane >> 4) << 3;
    const int b_row = (lane & 15);
    const int b_col = wn * 32;

    for (int kc = 0; kc < CH_TOT; kc += KO_BK) {
#pragma unroll
        for (int g = 0; g < 4; g++) {
            int f   = tid + g * 256;
            int r   = f >> 3;
            int kq  = f & 7;
            int row = row0 + r;
            float4 v = make_float4(0.f, 0.f, 0.f, 0.f);
            if (row < N_NODES)
                v = __ldcs(reinterpret_cast<const float4*>(&aggr[(size_t)row * 256 + kc + kq * 4]));
            unsigned short h0 = f2bf(v.x), h1 = f2bf(v.y), h2 = f2bf(v.z), h3 = f2bf(v.w);
            unsigned short l0 = f2bf(v.x - bf2f(h0)), l1 = f2bf(v.y - bf2f(h1));
            unsigned short l2 = f2bf(v.z - bf2f(h2)), l3 = f2bf(v.w - bf2f(h3));
            *reinterpret_cast<unsigned*>(&Ah[r][kq * 4])     = (unsigned)h0 | ((unsigned)h1 << 16);
            *reinterpret_cast<unsigned*>(&Ah[r][kq * 4 + 2]) = (unsigned)h2 | ((unsigned)h3 << 16);
            *reinterpret_cast<unsigned*>(&Al[r][kq * 4])     = (unsigned)l0 | ((unsigned)l1 << 16);
            *reinterpret_cast<unsigned*>(&Al[r][kq * 4 + 2]) = (unsigned)l2 | ((unsigned)l3 << 16);
        }
#pragma unroll
        for (int g = 0; g < 4; g++) {
            int f  = tid + g * 256;
            int kr = f >> 5;
            int nq = f & 31;
            float4 v = *reinterpret_cast<const float4*>(&W[(size_t)(kc + kr) * 128 + nq * 4]);
            unsigned short h0 = f2bf(v.x), h1 = f2bf(v.y), h2 = f2bf(v.z), h3 = f2bf(v.w);
            unsigned short l0 = f2bf(v.x - bf2f(h0)), l1 = f2bf(v.y - bf2f(h1));
            unsigned short l2 = f2bf(v.z - bf2f(h2)), l3 = f2bf(v.w - bf2f(h3));
            *reinterpret_cast<unsigned*>(&Bh[kr][nq * 4])     = (unsigned)h0 | ((unsigned)h1 << 16);
            *reinterpret_cast<unsigned*>(&Bh[kr][nq * 4 + 2]) = (unsigned)h2 | ((unsigned)h3 << 16);
            *reinterpret_cast<unsigned*>(&Bl[kr][nq * 4])     = (unsigned)l0 | ((unsigned)l1 << 16);
            *reinterpret_cast<unsigned*>(&Bl[kr][nq * 4 + 2]) = (unsigned)l2 | ((unsigned)l3 << 16);
        }
        __syncthreads();

#pragma unroll
        for (int ks = 0; ks < KO_BK / 16; ks++) {
            unsigned bh[4][2], bl[4][2];
#pragma unroll
            for (int nt = 0; nt < 4; nt++) {
                unsigned boff = (unsigned)(((ks * 16 + b_row) * (128 + KO_BPAD) + b_col + nt * 8) * 2);
                ldsm_x2t(bh[nt], sBh + boff);
                ldsm_x2t(bl[nt], sBl + boff);
            }
#pragma unroll
            for (int mt = 0; mt < 4; mt++) {
                unsigned aoff = (unsigned)(((a_row + mt * 16) * (KO_BK + KO_APAD) + ks * 16 + a_kof) * 2);
                unsigned ah[4], al[4];
                ldsm_x4(ah, sAh + aoff);
                ldsm_x4(al, sAl + aoff);
#pragma unroll
                for (int nt = 0; nt < 4; nt++) {
                    mma_bf16(c[mt][nt], ah, bh[nt]);
                    mma_bf16(c[mt][nt], ah, bl[nt]);
                    mma_bf16(c[mt][nt], al, bh[nt]);
                }
            }
        }
        __syncthreads();
    }

    float bias[4][2];
#pragma unroll
    for (int nt = 0; nt < 4; nt++) {
        int col = wn * 32 + nt * 8 + (lane & 3) * 2;
        bias[nt][0] = __ldg(&bo[col]);
        bias[nt][1] = __ldg(&bo[col + 1]);
    }
#pragma unroll
    for (int mt = 0; mt < 4; mt++) {
#pragma unroll
        for (int nt = 0; nt < 4; nt++) {
            int rg0 = row0 + wm * 64 + mt * 16 + (lane >> 2);
            int col = wn * 32 + nt * 8 + (lane & 3) * 2;
            if (rg0 < N_NODES) {
                float2 o;
                o.x = tanhf(c[mt][nt][0] + bias[nt][0]);
                o.y = tanhf(c[mt][nt][1] + bias[nt][1]);
                __stcs(reinterpret_cast<float2*>(&out[(size_t)rg0 * 128 + col]), o);
            }
            int rg1 = rg0 + 8;
            if (rg1 < N_NODES) {
                float2 o;
                o.x = tanhf(c[mt][nt][2] + bias[nt][0]);
                o.y = tanhf(c[mt][nt][3] + bias[nt][1]);
                __stcs(reinterpret_cast<float2*>(&out[(size_t)rg1 * 128 + col]), o);
            }
        }
    }
}

// ------------------------------ launch -------------------------------------
// Single default stream; no stream/event creation (allocation guard).
extern "C" void kernel_launch(void* const* d_in, const int* in_sizes, int n_in,
                              void* d_out, int out_size)
{
    const float* x     = (const float*)d_in[0];
    const float* na    = (const float*)d_in[1];
    const void*  ei    = d_in[2];
    const float* ea    = (const float*)d_in[3];
    const float* W_in  = (const float*)d_in[4];
    const float* b_in  = (const float*)d_in[5];
    const float* W_out = (const float*)d_in[6];
    const float* b_out = (const float*)d_in[7];
    float* out = (float*)d_out;

    k_probe<<<(N_NODES + 255) / 256, 256>>>((const long long*)ei);
    k_init<<<4096, 256>>>(x, na, ei);

    k_scan1<<<N_SCAN_BLOCKS, SCAN_BLK>>>();
    k_scan3<<<(N_NODES + 255) / 256, 256>>>();

    k_fillz<<<ZB_BLOCKS + FILL_BLOCKS, 256>>>(ei);

    k_aggr<<<AGG_BLOCKS, 32 * AW>>>(ea, W_in, b_in);

    const int gemm_blocks = (N_NODES + 127) / 128;  // 782
    k_out<<<gemm_blocks, 256>>>(W_out, b_out, out);
}

// round 16
// speedup vs baseline: 2.7299x; 1.0458x over previous
#include <cuda_runtime.h>
#include <cuda_bf16.h>
#include <cuda_fp16.h>
#include <math.h>

#define N_NODES 100000
#define N_EDGES 1600000
#define IN_CH   128
#define HIDDEN  2
#define OUT_CH  128
#define ATTR    6
#define CH_TOT  (IN_CH * HIDDEN)   // 256

typedef unsigned long long u64;

// ------------------------------ scratch ------------------------------------
__device__ uint4  g_xch4[(size_t)N_NODES * 16];   // xc fp16: 256B/row, 25.6MB
__device__ uint4  g_aggrh4[(size_t)N_NODES * 32]; // aggr fp16: 512B/row, 51.2MB
__device__ uint4  g_erec[(size_t)N_EDGES];        // CSR (src, eid, dst, 0) 25.6MB
__device__ int    g_deg[N_NODES];
__device__ int    g_rowptr[N_NODES + 1];
__device__ int    g_cursor[N_NODES];
__device__ int    g_ei_is64;

#define SCAN_BLK 512
#define N_SCAN_BLOCKS ((N_NODES + SCAN_BLK - 1) / SCAN_BLK)  // 196
__device__ int g_blockSums[N_SCAN_BLOCKS];

// k_aggr decomposition constants (shared with the zero part of k_fillz)
#define AW    4                        // warps per block
#define ACH   8                        // edges per chunk (N_EDGES % ACH == 0)
#define XBUF  4                        // xc/ea buffers in flight
#define ESLOT 8                        // erec ring slots
#define AGG_BLOCKS 592
#define WTOT  (AGG_BLOCKS * AW)        // 2368 warps

#define ZB_BLOCKS   592                // zero-part blocks in k_fillz
#define FILL_BLOCKS 2048               // fill-part blocks in k_fillz

// ------------------------------ f32x2 helpers ------------------------------
__device__ __forceinline__ u64 pack2(float lo, float hi) {
    u64 d; asm("mov.b64 %0, {%1, %2};" : "=l"(d) : "f"(lo), "f"(hi)); return d;
}
__device__ __forceinline__ void unpack2(u64 d, float& lo, float& hi) {
    asm("mov.b64 {%0, %1}, %2;" : "=f"(lo), "=f"(hi) : "l"(d));
}
__device__ __forceinline__ u64 fma2(u64 a, u64 b, u64 c) {
    u64 d; asm("fma.rn.f32x2 %0, %1, %2, %3;" : "=l"(d) : "l"(a), "l"(b), "l"(c)); return d;
}

// ------------------------------ cp.async helpers ---------------------------
__device__ __forceinline__ void cp16(void* smem, const void* gmem) {
    unsigned s = (unsigned)__cvta_generic_to_shared(smem);
    asm volatile("cp.async.cg.shared.global [%0], [%1], 16;" :: "r"(s), "l"(gmem) : "memory");
}
__device__ __forceinline__ void cp8(void* smem, const void* gmem) {
    unsigned s = (unsigned)__cvta_generic_to_shared(smem);
    asm volatile("cp.async.ca.shared.global [%0], [%1], 8;" :: "r"(s), "l"(gmem) : "memory");
}
#define CP_COMMIT() asm volatile("cp.async.commit_group;" ::: "memory")
#define CP_WAIT2()  asm volatile("cp.async.wait_group 2;" ::: "memory")
#define CP_WAIT0()  asm volatile("cp.async.wait_group 0;" ::: "memory")

// ------------------------------ fp16 helpers -------------------------------
__device__ __forceinline__ unsigned short f2h(float a) {
    unsigned short h; asm("cvt.rn.f16.f32 %0, %1;" : "=h"(h) : "f"(a)); return h;
}
__device__ __forceinline__ float h2f(unsigned short h) {
    float f; asm("cvt.f32.f16 %0, %1;" : "=f"(f) : "h"(h)); return f;
}
__device__ __forceinline__ unsigned f2h2(float lo, float hi) {
    __half2 h = __floats2half2_rn(lo, hi);
    return *reinterpret_cast<unsigned*>(&h);
}

// ------------------------------ probe + zero deg ---------------------------
__global__ void k_probe(const long long* __restrict__ ei)
{
    int i = blockIdx.x * blockDim.x + threadIdx.x;
    if (i < N_NODES) g_deg[i] = 0;
    if (blockIdx.x == 0 && threadIdx.x < 32) {
        int bad = 0;
#pragma unroll
        for (int j = 0; j < 8; j++) {
            long long v = ei[threadIdx.x * 8 + j];
            if (v < 0 || v >= N_NODES) bad = 1;
        }
        unsigned m = __ballot_sync(0xFFFFFFFFu, bad);
        if (threadIdx.x == 0) g_ei_is64 = (m == 0) ? 1 : 0;
    }
}

// ------------- init: fused xc fp16 table build + dst histogram --------------
__global__ void k_init(const float* __restrict__ x, const float* __restrict__ na,
                       const void* __restrict__ ei)
{
    size_t i = (size_t)blockIdx.x * blockDim.x + threadIdx.x;
    size_t stride = (size_t)gridDim.x * blockDim.x;
    const int is64 = g_ei_is64;

    __half2* xch = reinterpret_cast<__half2*>(g_xch4);
    const size_t n_pairs = (size_t)N_NODES * 64;     // 64 half2 per node
    for (size_t j = i; j < n_pairs; j += stride) {
        int n  = (int)(j >> 6);
        int c2 = (int)(j & 63);
        float a, b;
        if (c2 < 63) {
            a = x[(size_t)n * 127 + 2 * c2];
            b = x[(size_t)n * 127 + 2 * c2 + 1];
        } else {
            a = x[(size_t)n * 127 + 126];
            b = na[n];
        }
        xch[j] = __floats2half2_rn(a, b);
    }

    if (is64) {
        const longlong2* d2 = reinterpret_cast<const longlong2*>(
            (const long long*)ei + N_EDGES);
        for (size_t k = i; k < N_EDGES / 2; k += stride) {
            longlong2 v = __ldg(&d2[k]);
            atomicAdd(&g_deg[(int)v.x], 1);
            atomicAdd(&g_deg[(int)v.y], 1);
        }
    } else {
        const int4* d4 = reinterpret_cast<const int4*>((const int*)ei + N_EDGES);
        for (size_t k = i; k < N_EDGES / 4; k += stride) {
            int4 v = __ldg(&d4[k]);
            atomicAdd(&g_deg[v.x], 1);
            atomicAdd(&g_deg[v.y], 1);
            atomicAdd(&g_deg[v.z], 1);
            atomicAdd(&g_deg[v.w], 1);
        }
    }
}

// ------------------------------ CSR scan -----------------------------------
__global__ void k_scan1()
{
    __shared__ int s[SCAN_BLK];
    int t = threadIdx.x;
    int idx = blockIdx.x * SCAN_BLK + t;
    int v = (idx < N_NODES) ? g_deg[idx] : 0;
    s[t] = v;
    __syncthreads();
#pragma unroll
    for (int off = 1; off < SCAN_BLK; off <<= 1) {
        int tv = (t >= off) ? s[t - off] : 0;
        __syncthreads();
        s[t] += tv;
        __syncthreads();
    }
    if (idx < N_NODES) g_rowptr[idx] = s[t] - v;
    if (t == SCAN_BLK - 1) g_blockSums[blockIdx.x] = s[t];
}

// Fused scan2+scan3: each block reduces blockSums[0..sblk) itself.
__global__ void k_scan3()
{
    __shared__ int sdata[256];
    int t = threadIdx.x;
    int sblk = blockIdx.x >> 1;
    sdata[t] = (t < sblk) ? g_blockSums[t] : 0;
    __syncthreads();
#pragma unroll
    for (int off = 128; off > 0; off >>= 1) {
        if (t < off) sdata[t] += sdata[t + off];
        __syncthreads();
    }
    int base = sdata[0];

    int idx = blockIdx.x * blockDim.x + t;
    if (idx < N_NODES) {
        int rp = g_rowptr[idx] + base;
        g_rowptr[idx] = rp;
        g_cursor[idx] = rp;
    }
    if (idx == 0) g_rowptr[N_NODES] = N_EDGES;
}

// ---------- fused: boundary/deg0 zeroing (blocks < ZB) + CSR fill ----------
__global__ void k_fillz(const void* __restrict__ ei)
{
    if (blockIdx.x < ZB_BLOCKS) {
        const uint4 z4 = make_uint4(0u, 0u, 0u, 0u);

        int gw   = blockIdx.x * (blockDim.x >> 5) + (threadIdx.x >> 5);
        int lane = threadIdx.x & 31;
        if (gw < 2 * WTOT) {
            int r = gw >> 1;
            const int chunks_total = N_EDGES / ACH;
            const int cpw = (chunks_total + WTOT - 1) / WTOT;
            const int c0  = r * cpw;
            const int c1  = min(c0 + cpw, chunks_total);
            if (c0 < c1) {
                int p = (gw & 1) ? (c1 * ACH - 1) : (c0 * ACH);
                int lo = 0, hi = N_NODES;
                while (lo + 1 < hi) {
                    int mid = (lo + hi) >> 1;
                    if (g_rowptr[mid] <= p) lo = mid; else hi = mid;
                }
                g_aggrh4[(size_t)lo * 32 + lane] = z4;   // 512B row: 1 uint4/lane
            }
        }
        int n = blockIdx.x * blockDim.x + threadIdx.x;
        if (n < N_NODES && g_rowptr[n] == g_rowptr[n + 1]) {
            for (int q = 0; q < 32; q++) g_aggrh4[(size_t)n * 32 + q] = z4;
        }
        return;
    }

    const int is64 = g_ei_is64;
    int i = (blockIdx.x - ZB_BLOCKS) * blockDim.x + threadIdx.x;
    int stride = FILL_BLOCKS * blockDim.x;
    for (int p = i; p < N_EDGES / 2; p += stride) {
        int e = 2 * p;
        int s0, s1, d0, d1;
        if (is64) {
            const long long* ei64 = (const long long*)ei;
            longlong2 sv = __ldg(reinterpret_cast<const longlong2*>(ei64 + e));
            longlong2 dv = __ldg(reinterpret_cast<const longlong2*>(ei64 + N_EDGES + e));
            s0 = (int)sv.x; s1 = (int)sv.y; d0 = (int)dv.x; d1 = (int)dv.y;
        } else {
            const int* ei32 = (const int*)ei;
            int2 sv = __ldg(reinterpret_cast<const int2*>(ei32 + e));
            int2 dv = __ldg(reinterpret_cast<const int2*>(ei32 + N_EDGES + e));
            s0 = sv.x; s1 = sv.y; d0 = dv.x; d1 = dv.y;
        }
        int p0 = atomicAdd(&g_cursor[d0], 1);
        g_erec[p0] = make_uint4((unsigned)s0, (unsigned)e, (unsigned)d0, 0u);
        int p1 = atomicAdd(&g_cursor[d1], 1);
        g_erec[p1] = make_uint4((unsigned)s1, (unsigned)(e + 1), (unsigned)d1, 0u);
    }
}

// ------------------------------ aggregation --------------------------------
struct LaneW {
    u64 w2[6][4];
    u64 b2[4];
};

__device__ __forceinline__ void edge_accum(
    u64 acc[4], const LaneW& lw, float4 a03, float2 a45, float4 xj)
{
    u64 ee[6];
    ee[0] = pack2(a03.x, a03.x);  ee[1] = pack2(a03.y, a03.y);
    ee[2] = pack2(a03.z, a03.z);  ee[3] = pack2(a03.w, a03.w);
    ee[4] = pack2(a45.x, a45.x);  ee[5] = pack2(a45.y, a45.y);
#pragma unroll
    for (int jj = 0; jj < 4; jj++) {
        u64 s = lw.b2[jj];
#pragma unroll
        for (int a = 0; a < 6; a++) s = fma2(ee[a], lw.w2[a][jj], s);
        float lo, hi;
        unpack2(s, lo, hi);
        lo = fmaxf(lo, 0.f);
        hi = fmaxf(hi, 0.f);
        float xv = (jj == 0) ? xj.x : (jj == 1) ? xj.y : (jj == 2) ? xj.z : xj.w;
        acc[jj] = fma2(pack2(lo, hi), pack2(xv, xv), acc[jj]);
    }
}

// aggr rows are fp16. Sole-owner flush: 1x stcs.128. Boundary: f16x2 reductions.
__device__ __forceinline__ void flush_acc(u64 acc[4], int node, int lane, bool use_atomic)
{
    unsigned r[4];
#pragma unroll
    for (int j = 0; j < 4; j++) {
        float lo, hi;
        unpack2(acc[j], lo, hi);
        r[j] = f2h2(lo, hi);
    }
    if (use_atomic) {
        __half* base = reinterpret_cast<__half*>(g_aggrh4) + (size_t)node * 256 + lane * 8;
#pragma unroll
        for (int j = 0; j < 4; j++)
            asm volatile("red.global.add.noftz.f16x2 [%0], %1;"
                         :: "l"(base + j * 2), "r"(r[j]) : "memory");
    } else {
        __stcs(&g_aggrh4[(size_t)node * 32 + lane], make_uint4(r[0], r[1], r[2], r[3]));
    }
    acc[0] = 0; acc[1] = 0; acc[2] = 0; acc[3] = 0;
}

__global__ void __launch_bounds__(32 * AW, 4) k_aggr(
    const float* __restrict__ ea,    // [E, 6]
    const float* __restrict__ W_in,  // [6, 256]
    const float* __restrict__ b_in)  // [256]
{
    __shared__ __align__(16) __half sx[AW][XBUF][ACH][128];  // 32 KB
    __shared__ __align__(16) float  sa[AW][XBUF][ACH][8];    //  4 KB
    __shared__ __align__(16) uint4  se[AW][ESLOT][ACH];      //  4 KB

    const int lane = threadIdx.x & 31;
    const int w    = threadIdx.x >> 5;
    const int wid  = blockIdx.x * AW + w;

    LaneW lw;
#pragma unroll
    for (int jj = 0; jj < 4; jj++) {
        int j0 = lane * 8 + 2 * jj;
        lw.b2[jj] = pack2(__ldg(&b_in[j0]), __ldg(&b_in[j0 + 1]));
#pragma unroll
        for (int a = 0; a < 6; a++)
            lw.w2[a][jj] = pack2(__ldg(&W_in[a * 256 + j0]),
                                 __ldg(&W_in[a * 256 + j0 + 1]));
    }

    const float2* ea2 = reinterpret_cast<const float2*>(ea);

    const int chunks_total = N_EDGES / ACH;   // exact
    const int cpw  = (chunks_total + WTOT - 1) / WTOT;
    const int c0   = wid * cpw;
    const int c1   = min(c0 + cpw, chunks_total);
    if (c0 >= c1) return;
    const int nch  = c1 - c0;

    auto issue_erec = [&](int c) {
        if (c < nch && lane < 8)
            cp16(&se[w][c & (ESLOT - 1)][lane], &g_erec[(size_t)(c0 + c) * ACH + lane]);
    };
    auto issue_xcea = [&](int c) {
        if (c < nch) {
            int b   = c & (XBUF - 1);
            int s   = c & (ESLOT - 1);
            int seg = lane & 15;
            int hlf = lane >> 4;
#pragma unroll
            for (int pr = 0; pr < ACH / 2; pr++) {
                int j = pr * 2 + hlf;
                int src = (int)se[w][s][j].x;
                cp16(&sx[w][b][j][seg * 8], &g_xch4[(size_t)src * 16 + seg]);
            }
            if (lane < 3 * ACH) {
                int j  = lane / 3;
                int wd = lane % 3;
                int eid = (int)se[w][s][j].y;
                cp8(&sa[w][b][j][wd * 2], &ea2[(size_t)eid * 3 + wd]);
            }
        }
    };

    issue_erec(0); issue_erec(1); issue_erec(2); issue_erec(3);
    CP_COMMIT();
    CP_WAIT0();
    __syncwarp();
    issue_xcea(0); issue_erec(4); CP_COMMIT();
    issue_xcea(1); issue_erec(5); CP_COMMIT();
    issue_xcea(2); issue_erec(6); CP_COMMIT();

    u64 acc[4] = {0, 0, 0, 0};
    int  cur = -1;
    bool first = true;

    for (int i = 0; i < nch; i++) {
        CP_WAIT2();
        __syncwarp();
        issue_xcea(i + 3);
        issue_erec(i + 7);
        CP_COMMIT();

        int b = i & (XBUF - 1);
        int s = i & (ESLOT - 1);
#pragma unroll
        for (int j = 0; j < ACH; j++) {
            int dst = (int)se[w][s][j].z;
            if (dst != cur) {
                if (cur >= 0) {
                    flush_acc(acc, cur, lane, first);
                    first = false;
                }
                cur = dst;
            }
            float4 a03 = *reinterpret_cast<const float4*>(&sa[w][b][j][0]);
            float2 a45 = *reinterpret_cast<const float2*>(&sa[w][b][j][4]);
            const __half2* hp = reinterpret_cast<const __half2*>(&sx[w][b][j][lane * 4]);
            float2 f0 = __half22float2(hp[0]);
            float2 f1 = __half22float2(hp[1]);
            float4 xj = make_float4(f0.x, f0.y, f1.x, f1.y);
            edge_accum(acc, lw, a03, a45, xj);
        }
    }
    if (cur >= 0) flush_acc(acc, cur, lane, true);
}

// ------------------------------ output GEMM (tensor core) ------------------
// A is already fp16 (aggr buffer) -> single A plane, direct load, no cvt.
// B (fp32 weights) split hi/lo in fp16 -> 2 mma planes: A*Bh + A*Bl.
#define KO_BK   32
#define KO_APAD 8    // A row: 32+8 halves = 80B stride (16B-aligned, LDSM bank-distinct)
#define KO_BPAD 8

__device__ __forceinline__ void ldsm_x4(unsigned r[4], unsigned addr) {
    asm volatile("ldmatrix.sync.aligned.m8n8.x4.shared.b16 {%0,%1,%2,%3}, [%4];"
                 : "=r"(r[0]), "=r"(r[1]), "=r"(r[2]), "=r"(r[3]) : "r"(addr));
}
__device__ __forceinline__ void ldsm_x2t(unsigned r[2], unsigned addr) {
    asm volatile("ldmatrix.sync.aligned.m8n8.x2.trans.shared.b16 {%0,%1}, [%2];"
                 : "=r"(r[0]), "=r"(r[1]) : "r"(addr));
}
__device__ __forceinline__ void mma_f16(float c[4], const unsigned a[4], const unsigned b[2]) {
    asm volatile("mma.sync.aligned.m16n8k16.row.col.f32.f16.f16.f32 "
                 "{%0,%1,%2,%3}, {%4,%5,%6,%7}, {%8,%9}, {%0,%1,%2,%3};"
                 : "+f"(c[0]), "+f"(c[1]), "+f"(c[2]), "+f"(c[3])
                 : "r"(a[0]), "r"(a[1]), "r"(a[2]), "r"(a[3]), "r"(b[0]), "r"(b[1]));
}

__global__ void __launch_bounds__(256, 2) k_out(
    const float* __restrict__ W,   // [256, 128]
    const float* __restrict__ bo,  // [128]
    float*       __restrict__ out) // [N, 128]
{
    __shared__ __align__(16) unsigned short Ah[128][KO_BK + KO_APAD];  // fp16 A
    __shared__ __align__(16) unsigned short Bh[KO_BK][128 + KO_BPAD];
    __shared__ __align__(16) unsigned short Bl[KO_BK][128 + KO_BPAD];

    const int tid  = threadIdx.x;
    const int lane = tid & 31;
    const int warp = tid >> 5;
    const int wm   = warp >> 2;
    const int wn   = warp & 3;
    const int row0 = blockIdx.x * 128;

    float c[4][4][4];
#pragma unroll
    for (int mt = 0; mt < 4; mt++)
#pragma unroll
        for (int nt = 0; nt < 4; nt++)
#pragma unroll
            for (int q = 0; q < 4; q++) c[mt][nt][q] = 0.f;

    const unsigned sAh = (unsigned)__cvta_generic_to_shared(&Ah[0][0]);
    const unsigned sBh = (unsigned)__cvta_generic_to_shared(&Bh[0][0]);
    const unsigned sBl = (unsigned)__cvta_generic_to_shared(&Bl[0][0]);
    const int a_row = wm * 64 + (lane & 15);
    const int a_kof = (lane >> 4) << 3;
    const int b_row = (lane & 15);
    const int b_col = wn * 32;

    for (int kc = 0; kc < CH_TOT; kc += KO_BK) {
        // ---- A tile: 128 rows x 32 halves, direct fp16 copy (512 uint4) ----
#pragma unroll
        for (int g = 0; g < 2; g++) {
            int f   = tid * 2 + g;          // 0..511
            int r   = f >> 2;               // 0..127
            int kq  = f & 3;                // 4 x 8-half groups
            int row = row0 + r;
            uint4 v = make_uint4(0u, 0u, 0u, 0u);
            if (row < N_NODES)
                v = __ldcs(&g_aggrh4[((size_t)row * 256 + kc + kq * 8) >> 3]);
            *reinterpret_cast<uint4*>(&Ah[r][kq * 8]) = v;   // 80B row stride, 16B aligned
        }
        // ---- B tile: 32 k x 128 cols, fp32 -> fp16 hi/lo ----
#pragma unroll
        for (int g = 0; g < 4; g++) {
            int f  = tid + g * 256;
            int kr = f >> 5;
            int nq = f & 31;
            float4 v = *reinterpret_cast<const float4*>(&W[(size_t)(kc + kr) * 128 + nq * 4]);
            unsigned short h0 = f2h(v.x), h1 = f2h(v.y), h2 = f2h(v.z), h3 = f2h(v.w);
            unsigned short l0 = f2h(v.x - h2f(h0)), l1 = f2h(v.y - h2f(h1));
            unsigned short l2 = f2h(v.z - h2f(h2)), l3 = f2h(v.w - h2f(h3));
            *reinterpret_cast<unsigned*>(&Bh[kr][nq * 4])     = (unsigned)h0 | ((unsigned)h1 << 16);
            *reinterpret_cast<unsigned*>(&Bh[kr][nq * 4 + 2]) = (unsigned)h2 | ((unsigned)h3 << 16);
            *reinterpret_cast<unsigned*>(&Bl[kr][nq * 4])     = (unsigned)l0 | ((unsigned)l1 << 16);
            *reinterpret_cast<unsigned*>(&Bl[kr][nq * 4 + 2]) = (unsigned)l2 | ((unsigned)l3 << 16);
        }
        __syncthreads();

#pragma unroll
        for (int ks = 0; ks < KO_BK / 16; ks++) {
            unsigned bh[4][2], bl[4][2];
#pragma unroll
            for (int nt = 0; nt < 4; nt++) {
                unsigned boff = (unsigned)(((ks * 16 + b_row) * (128 + KO_BPAD) + b_col + nt * 8) * 2);
                ldsm_x2t(bh[nt], sBh + boff);
                ldsm_x2t(bl[nt], sBl + boff);
            }
#pragma unroll
            for (int mt = 0; mt < 4; mt++) {
                unsigned aoff = (unsigned)(((a_row + mt * 16) * (KO_BK + KO_APAD) + ks * 16 + a_kof) * 2);
                unsigned ah[4];
                ldsm_x4(ah, sAh + aoff);
#pragma unroll
                for (int nt = 0; nt < 4; nt++) {
                    mma_f16(c[mt][nt], ah, bh[nt]);
                    mma_f16(c[mt][nt], ah, bl[nt]);
                }
            }
        }
        __syncthreads();
    }

    float bias[4][2];
#pragma unroll
    for (int nt = 0; nt < 4; nt++) {
        int col = wn * 32 + nt * 8 + (lane & 3) * 2;
        bias[nt][0] = __ldg(&bo[col]);
        bias[nt][1] = __ldg(&bo[col + 1]);
    }
#pragma unroll
    for (int mt = 0; mt < 4; mt++) {
#pragma unroll
        for (int nt = 0; nt < 4; nt++) {
            int rg0 = row0 + wm * 64 + mt * 16 + (lane >> 2);
            int col = wn * 32 + nt * 8 + (lane & 3) * 2;
            if (rg0 < N_NODES) {
                float2 o;
                o.x = tanhf(c[mt][nt][0] + bias[nt][0]);
                o.y = tanhf(c[mt][nt][1] + bias[nt][1]);
                __stcs(reinterpret_cast<float2*>(&out[(size_t)rg0 * 128 + col]), o);
            }
            int rg1 = rg0 + 8;
            if (rg1 < N_NODES) {
                float2 o;
                o.x = tanhf(c[mt][nt][2] + bias[nt][0]);
                o.y = tanhf(c[mt][nt][3] + bias[nt][1]);
                __stcs(reinterpret_cast<float2*>(&out[(size_t)rg1 * 128 + col]), o);
            }
        }
    }
}

// ------------------------------ launch -------------------------------------
extern "C" void kernel_launch(void* const* d_in, const int* in_sizes, int n_in,
                              void* d_out, int out_size)
{
    const float* x     = (const float*)d_in[0];
    const float* na    = (const float*)d_in[1];
    const void*  ei    = d_in[2];
    const float* ea    = (const float*)d_in[3];
    const float* W_in  = (const float*)d_in[4];
    const float* b_in  = (const float*)d_in[5];
    const float* W_out = (const float*)d_in[6];
    const float* b_out = (const float*)d_in[7];
    float* out = (float*)d_out;

    k_probe<<<(N_NODES + 255) / 256, 256>>>((const long long*)ei);
    k_init<<<4096, 256>>>(x, na, ei);

    k_scan1<<<N_SCAN_BLOCKS, SCAN_BLK>>>();
    k_scan3<<<(N_NODES + 255) / 256, 256>>>();

    k_fillz<<<ZB_BLOCKS + FILL_BLOCKS, 256>>>(ei);

    k_aggr<<<AGG_BLOCKS, 32 * AW>>>(ea, W_in, b_in);

    const int gemm_blocks = (N_NODES + 127) / 128;  // 782
    k_out<<<gemm_blocks, 256>>>(W_out, b_out, out);
}

// round 17
// speedup vs baseline: 2.8277x; 1.0358x over previous
#include <cuda_runtime.h>
#include <cuda_bf16.h>
#include <cuda_fp16.h>
#include <math.h>

#define N_NODES 100000
#define N_EDGES 1600000
#define IN_CH   128
#define HIDDEN  2
#define OUT_CH  128
#define ATTR    6
#define CH_TOT  (IN_CH * HIDDEN)   // 256

typedef unsigned long long u64;

// ------------------------------ scratch ------------------------------------
__device__ uint4  g_xch4[(size_t)N_NODES * 16];   // xc fp16: 256B/row, 25.6MB
__device__ uint4  g_aggrh4[(size_t)N_NODES * 32]; // aggr fp16: 512B/row, 51.2MB
__device__ uint4  g_erec[(size_t)N_EDGES];        // CSR (src, eid, dst, 0) 25.6MB
__device__ int    g_deg[N_NODES];
__device__ int    g_rowptr[N_NODES + 1];
__device__ int    g_cursor[N_NODES];
__device__ int    g_ei_is64;
__device__ int    g_segctr;                       // work-stealing counter

#define SCAN_BLK 512
#define N_SCAN_BLOCKS ((N_NODES + SCAN_BLK - 1) / SCAN_BLK)  // 196
__device__ int g_blockSums[N_SCAN_BLOCKS];

// k_aggr decomposition constants (shared with the zero part of k_fillz)
#define AW    4                        // warps per block
#define ACH   8                        // edges per chunk (N_EDGES % ACH == 0)
#define XBUF  4                        // xc/ea buffers in flight
#define ESLOT 8                        // erec ring slots
#define AGG_BLOCKS 592
#define NWARPS (AGG_BLOCKS * AW)       // 2368 persistent warps
#define CHUNKS_TOTAL (N_EDGES / ACH)   // 200000
#define NSEG  4736                     // segments (2 per warp avg)
#define CPS   ((CHUNKS_TOTAL + NSEG - 1) / NSEG)  // 43 chunks per segment

#define ZB_BLOCKS   592                // zero-part blocks in k_fillz
#define FILL_BLOCKS 2048               // fill-part blocks in k_fillz

// ------------------------------ f32x2 helpers ------------------------------
__device__ __forceinline__ u64 pack2(float lo, float hi) {
    u64 d; asm("mov.b64 %0, {%1, %2};" : "=l"(d) : "f"(lo), "f"(hi)); return d;
}
__device__ __forceinline__ void unpack2(u64 d, float& lo, float& hi) {
    asm("mov.b64 {%0, %1}, %2;" : "=f"(lo), "=f"(hi) : "l"(d));
}
__device__ __forceinline__ u64 fma2(u64 a, u64 b, u64 c) {
    u64 d; asm("fma.rn.f32x2 %0, %1, %2, %3;" : "=l"(d) : "l"(a), "l"(b), "l"(c)); return d;
}

// ------------------------------ cp.async helpers ---------------------------
__device__ __forceinline__ void cp16(void* smem, const void* gmem) {
    unsigned s = (unsigned)__cvta_generic_to_shared(smem);
    asm volatile("cp.async.cg.shared.global [%0], [%1], 16;" :: "r"(s), "l"(gmem) : "memory");
}
__device__ __forceinline__ void cp8(void* smem, const void* gmem) {
    unsigned s = (unsigned)__cvta_generic_to_shared(smem);
    asm volatile("cp.async.ca.shared.global [%0], [%1], 8;" :: "r"(s), "l"(gmem) : "memory");
}
#define CP_COMMIT() asm volatile("cp.async.commit_group;" ::: "memory")
#define CP_WAIT2()  asm volatile("cp.async.wait_group 2;" ::: "memory")
#define CP_WAIT0()  asm volatile("cp.async.wait_group 0;" ::: "memory")

// ------------------------------ fp16 helpers -------------------------------
__device__ __forceinline__ unsigned short f2h(float a) {
    unsigned short h; asm("cvt.rn.f16.f32 %0, %1;" : "=h"(h) : "f"(a)); return h;
}
__device__ __forceinline__ float h2f(unsigned short h) {
    float f; asm("cvt.f32.f16 %0, %1;" : "=f"(f) : "h"(h)); return f;
}
__device__ __forceinline__ unsigned f2h2(float lo, float hi) {
    __half2 h = __floats2half2_rn(lo, hi);
    return *reinterpret_cast<unsigned*>(&h);
}

// ------------------------------ probe + zero deg ---------------------------
__global__ void k_probe(const long long* __restrict__ ei)
{
    int i = blockIdx.x * blockDim.x + threadIdx.x;
    if (i < N_NODES) g_deg[i] = 0;
    if (i == 0) g_segctr = 0;
    if (blockIdx.x == 0 && threadIdx.x < 32) {
        int bad = 0;
#pragma unroll
        for (int j = 0; j < 8; j++) {
            long long v = ei[threadIdx.x * 8 + j];
            if (v < 0 || v >= N_NODES) bad = 1;
        }
        unsigned m = __ballot_sync(0xFFFFFFFFu, bad);
        if (threadIdx.x == 0) g_ei_is64 = (m == 0) ? 1 : 0;
    }
}

// ------------- init: fused xc fp16 table build + dst histogram --------------
__global__ void k_init(const float* __restrict__ x, const float* __restrict__ na,
                       const void* __restrict__ ei)
{
    size_t i = (size_t)blockIdx.x * blockDim.x + threadIdx.x;
    size_t stride = (size_t)gridDim.x * blockDim.x;
    const int is64 = g_ei_is64;

    __half2* xch = reinterpret_cast<__half2*>(g_xch4);
    const size_t n_pairs = (size_t)N_NODES * 64;     // 64 half2 per node
    for (size_t j = i; j < n_pairs; j += stride) {
        int n  = (int)(j >> 6);
        int c2 = (int)(j & 63);
        float a, b;
        if (c2 < 63) {
            a = x[(size_t)n * 127 + 2 * c2];
            b = x[(size_t)n * 127 + 2 * c2 + 1];
        } else {
            a = x[(size_t)n * 127 + 126];
            b = na[n];
        }
        xch[j] = __floats2half2_rn(a, b);
    }

    if (is64) {
        const longlong2* d2 = reinterpret_cast<const longlong2*>(
            (const long long*)ei + N_EDGES);
        for (size_t k = i; k < N_EDGES / 2; k += stride) {
            longlong2 v = __ldg(&d2[k]);
            atomicAdd(&g_deg[(int)v.x], 1);
            atomicAdd(&g_deg[(int)v.y], 1);
        }
    } else {
        const int4* d4 = reinterpret_cast<const int4*>((const int*)ei + N_EDGES);
        for (size_t k = i; k < N_EDGES / 4; k += stride) {
            int4 v = __ldg(&d4[k]);
            atomicAdd(&g_deg[v.x], 1);
            atomicAdd(&g_deg[v.y], 1);
            atomicAdd(&g_deg[v.z], 1);
            atomicAdd(&g_deg[v.w], 1);
        }
    }
}

// ------------------------------ CSR scan -----------------------------------
__global__ void k_scan1()
{
    __shared__ int s[SCAN_BLK];
    int t = threadIdx.x;
    int idx = blockIdx.x * SCAN_BLK + t;
    int v = (idx < N_NODES) ? g_deg[idx] : 0;
    s[t] = v;
    __syncthreads();
#pragma unroll
    for (int off = 1; off < SCAN_BLK; off <<= 1) {
        int tv = (t >= off) ? s[t - off] : 0;
        __syncthreads();
        s[t] += tv;
        __syncthreads();
    }
    if (idx < N_NODES) g_rowptr[idx] = s[t] - v;
    if (t == SCAN_BLK - 1) g_blockSums[blockIdx.x] = s[t];
}

// Fused scan2+scan3: each block reduces blockSums[0..sblk) itself.
__global__ void k_scan3()
{
    __shared__ int sdata[256];
    int t = threadIdx.x;
    int sblk = blockIdx.x >> 1;
    sdata[t] = (t < sblk) ? g_blockSums[t] : 0;
    __syncthreads();
#pragma unroll
    for (int off = 128; off > 0; off >>= 1) {
        if (t < off) sdata[t] += sdata[t + off];
        __syncthreads();
    }
    int base = sdata[0];

    int idx = blockIdx.x * blockDim.x + t;
    if (idx < N_NODES) {
        int rp = g_rowptr[idx] + base;
        g_rowptr[idx] = rp;
        g_cursor[idx] = rp;
    }
    if (idx == 0) g_rowptr[N_NODES] = N_EDGES;
}

// ---------- fused: segment-boundary/deg0 zeroing (blocks < ZB) + fill ------
// Segment boundaries are STATIC (seg s covers chunks [s*CPS, (s+1)*CPS)), so
// boundary-node zeroing is independent of which warp steals which segment.
__global__ void k_fillz(const void* __restrict__ ei)
{
    if (blockIdx.x < ZB_BLOCKS) {
        const uint4 z4 = make_uint4(0u, 0u, 0u, 0u);

        int gw   = blockIdx.x * (blockDim.x >> 5) + (threadIdx.x >> 5);  // seg id
        int lane = threadIdx.x & 31;
        if (gw < NSEG) {
            int c0 = gw * CPS;
            int c1 = min(c0 + CPS, CHUNKS_TOTAL);
            if (c0 < c1) {
                int p0 = c0 * ACH;
                int p1 = c1 * ACH - 1;
#pragma unroll
                for (int q = 0; q < 2; q++) {
                    int p = q ? p1 : p0;
                    int lo = 0, hi = N_NODES;
                    while (lo + 1 < hi) {
                        int mid = (lo + hi) >> 1;
                        if (g_rowptr[mid] <= p) lo = mid; else hi = mid;
                    }
                    g_aggrh4[(size_t)lo * 32 + lane] = z4;
                }
            }
        }
        int n = blockIdx.x * blockDim.x + threadIdx.x;
        if (n < N_NODES && g_rowptr[n] == g_rowptr[n + 1]) {
            for (int q = 0; q < 32; q++) g_aggrh4[(size_t)n * 32 + q] = z4;
        }
        return;
    }

    const int is64 = g_ei_is64;
    int i = (blockIdx.x - ZB_BLOCKS) * blockDim.x + threadIdx.x;
    int stride = FILL_BLOCKS * blockDim.x;
    for (int p = i; p < N_EDGES / 2; p += stride) {
        int e = 2 * p;
        int s0, s1, d0, d1;
        if (is64) {
            const long long* ei64 = (const long long*)ei;
            longlong2 sv = __ldg(reinterpret_cast<const longlong2*>(ei64 + e));
            longlong2 dv = __ldg(reinterpret_cast<const longlong2*>(ei64 + N_EDGES + e));
            s0 = (int)sv.x; s1 = (int)sv.y; d0 = (int)dv.x; d1 = (int)dv.y;
        } else {
            const int* ei32 = (const int*)ei;
            int2 sv = __ldg(reinterpret_cast<const int2*>(ei32 + e));
            int2 dv = __ldg(reinterpret_cast<const int2*>(ei32 + N_EDGES + e));
            s0 = sv.x; s1 = sv.y; d0 = dv.x; d1 = dv.y;
        }
        int p0 = atomicAdd(&g_cursor[d0], 1);
        g_erec[p0] = make_uint4((unsigned)s0, (unsigned)e, (unsigned)d0, 0u);
        int p1 = atomicAdd(&g_cursor[d1], 1);
        g_erec[p1] = make_uint4((unsigned)s1, (unsigned)(e + 1), (unsigned)d1, 0u);
    }
}

// ------------------------------ aggregation --------------------------------
struct LaneW {
    u64 w2[6][4];
    u64 b2[4];
};

__device__ __forceinline__ void edge_accum(
    u64 acc[4], const LaneW& lw, float4 a03, float2 a45, float4 xj)
{
    u64 ee[6];
    ee[0] = pack2(a03.x, a03.x);  ee[1] = pack2(a03.y, a03.y);
    ee[2] = pack2(a03.z, a03.z);  ee[3] = pack2(a03.w, a03.w);
    ee[4] = pack2(a45.x, a45.x);  ee[5] = pack2(a45.y, a45.y);
#pragma unroll
    for (int jj = 0; jj < 4; jj++) {
        u64 s = lw.b2[jj];
#pragma unroll
        for (int a = 0; a < 6; a++) s = fma2(ee[a], lw.w2[a][jj], s);
        float lo, hi;
        unpack2(s, lo, hi);
        lo = fmaxf(lo, 0.f);
        hi = fmaxf(hi, 0.f);
        float xv = (jj == 0) ? xj.x : (jj == 1) ? xj.y : (jj == 2) ? xj.z : xj.w;
        acc[jj] = fma2(pack2(lo, hi), pack2(xv, xv), acc[jj]);
    }
}

__device__ __forceinline__ void flush_acc(u64 acc[4], int node, int lane, bool use_atomic)
{
    unsigned r[4];
#pragma unroll
    for (int j = 0; j < 4; j++) {
        float lo, hi;
        unpack2(acc[j], lo, hi);
        r[j] = f2h2(lo, hi);
    }
    if (use_atomic) {
        __half* base = reinterpret_cast<__half*>(g_aggrh4) + (size_t)node * 256 + lane * 8;
#pragma unroll
        for (int j = 0; j < 4; j++)
            asm volatile("red.global.add.noftz.f16x2 [%0], %1;"
                         :: "l"(base + j * 2), "r"(r[j]) : "memory");
    } else {
        __stcs(&g_aggrh4[(size_t)node * 32 + lane], make_uint4(r[0], r[1], r[2], r[3]));
    }
    acc[0] = 0; acc[1] = 0; acc[2] = 0; acc[3] = 0;
}

__global__ void __launch_bounds__(32 * AW, 4) k_aggr(
    const float* __restrict__ ea,    // [E, 6]
    const float* __restrict__ W_in,  // [6, 256]
    const float* __restrict__ b_in)  // [256]
{
    __shared__ __align__(16) __half sx[AW][XBUF][ACH][128];  // 32 KB
    __shared__ __align__(16) float  sa[AW][XBUF][ACH][8];    //  4 KB
    __shared__ __align__(16) uint4  se[AW][ESLOT][ACH];      //  4 KB

    const int lane = threadIdx.x & 31;
    const int w    = threadIdx.x >> 5;

    LaneW lw;
#pragma unroll
    for (int jj = 0; jj < 4; jj++) {
        int j0 = lane * 8 + 2 * jj;
        lw.b2[jj] = pack2(__ldg(&b_in[j0]), __ldg(&b_in[j0 + 1]));
#pragma unroll
        for (int a = 0; a < 6; a++)
            lw.w2[a][jj] = pack2(__ldg(&W_in[a * 256 + j0]),
                                 __ldg(&W_in[a * 256 + j0 + 1]));
    }

    const float2* ea2 = reinterpret_cast<const float2*>(ea);

    // ---- persistent warp: steal segments ----
    while (true) {
        int seg;
        if (lane == 0) seg = atomicAdd(&g_segctr, 1);
        seg = __shfl_sync(0xFFFFFFFFu, seg, 0);
        if (seg >= NSEG) break;

        const int c0  = seg * CPS;
        const int c1  = min(c0 + CPS, CHUNKS_TOTAL);
        if (c0 >= c1) continue;
        const int nch = c1 - c0;

        auto issue_erec = [&](int c) {
            if (c < nch && lane < 8)
                cp16(&se[w][c & (ESLOT - 1)][lane], &g_erec[(size_t)(c0 + c) * ACH + lane]);
        };
        auto issue_xcea = [&](int c) {
            if (c < nch) {
                int b   = c & (XBUF - 1);
                int s   = c & (ESLOT - 1);
                int seg16 = lane & 15;
                int hlf   = lane >> 4;
#pragma unroll
                for (int pr = 0; pr < ACH / 2; pr++) {
                    int j = pr * 2 + hlf;
                    int src = (int)se[w][s][j].x;
                    cp16(&sx[w][b][j][seg16 * 8], &g_xch4[(size_t)src * 16 + seg16]);
                }
                if (lane < 3 * ACH) {
                    int j  = lane / 3;
                    int wd = lane % 3;
                    int eid = (int)se[w][s][j].y;
                    cp8(&sa[w][b][j][wd * 2], &ea2[(size_t)eid * 3 + wd]);
                }
            }
        };

        issue_erec(0); issue_erec(1); issue_erec(2); issue_erec(3);
        CP_COMMIT();
        CP_WAIT0();          // also drains any stale groups from prior segment
        __syncwarp();
        issue_xcea(0); issue_erec(4); CP_COMMIT();
        issue_xcea(1); issue_erec(5); CP_COMMIT();
        issue_xcea(2); issue_erec(6); CP_COMMIT();

        u64 acc[4] = {0, 0, 0, 0};
        int  cur = -1;
        bool first = true;

        for (int i = 0; i < nch; i++) {
            CP_WAIT2();
            __syncwarp();
            issue_xcea(i + 3);
            issue_erec(i + 7);
            CP_COMMIT();

            int b = i & (XBUF - 1);
            int s = i & (ESLOT - 1);
#pragma unroll
            for (int j = 0; j < ACH; j++) {
                int dst = (int)se[w][s][j].z;
                if (dst != cur) {
                    if (cur >= 0) {
                        flush_acc(acc, cur, lane, first);
                        first = false;
                    }
                    cur = dst;
                }
                float4 a03 = *reinterpret_cast<const float4*>(&sa[w][b][j][0]);
                float2 a45 = *reinterpret_cast<const float2*>(&sa[w][b][j][4]);
                const __half2* hp = reinterpret_cast<const __half2*>(&sx[w][b][j][lane * 4]);
                float2 f0 = __half22float2(hp[0]);
                float2 f1 = __half22float2(hp[1]);
                float4 xj = make_float4(f0.x, f0.y, f1.x, f1.y);
                edge_accum(acc, lw, a03, a45, xj);
            }
        }
        if (cur >= 0) flush_acc(acc, cur, lane, true);
    }
}

// ------------------------------ output GEMM (tensor core) ------------------
// A already fp16 (aggr buffer) -> single A plane. B split hi/lo fp16.
#define KO_BK   32
#define KO_APAD 8
#define KO_BPAD 8

__device__ __forceinline__ void ldsm_x4(unsigned r[4], unsigned addr) {
    asm volatile("ldmatrix.sync.aligned.m8n8.x4.shared.b16 {%0,%1,%2,%3}, [%4];"
                 : "=r"(r[0]), "=r"(r[1]), "=r"(r[2]), "=r"(r[3]) : "r"(addr));
}
__device__ __forceinline__ void ldsm_x2t(unsigned r[2], unsigned addr) {
    asm volatile("ldmatrix.sync.aligned.m8n8.x2.trans.shared.b16 {%0,%1}, [%2];"
                 : "=r"(r[0]), "=r"(r[1]) : "r"(addr));
}
__device__ __forceinline__ void mma_f16(float c[4], const unsigned a[4], const unsigned b[2]) {
    asm volatile("mma.sync.aligned.m16n8k16.row.col.f32.f16.f16.f32 "
                 "{%0,%1,%2,%3}, {%4,%5,%6,%7}, {%8,%9}, {%0,%1,%2,%3};"
                 : "+f"(c[0]), "+f"(c[1]), "+f"(c[2]), "+f"(c[3])
                 : "r"(a[0]), "r"(a[1]), "r"(a[2]), "r"(a[3]), "r"(b[0]), "r"(b[1]));
}

__global__ void __launch_bounds__(256, 2) k_out(
    const float* __restrict__ W,   // [256, 128]
    const float* __restrict__ bo,  // [128]
    float*       __restrict__ out) // [N, 128]
{
    __shared__ __align__(16) unsigned short Ah[128][KO_BK + KO_APAD];
    __shared__ __align__(16) unsigned short Bh[KO_BK][128 + KO_BPAD];
    __shared__ __align__(16) unsigned short Bl[KO_BK][128 + KO_BPAD];

    const int tid  = threadIdx.x;
    const int lane = tid & 31;
    const int warp = tid >> 5;
    const int wm   = warp >> 2;
    const int wn   = warp & 3;
    const int row0 = blockIdx.x * 128;

    float c[4][4][4];
#pragma unroll
    for (int mt = 0; mt < 4; mt++)
#pragma unroll
        for (int nt = 0; nt < 4; nt++)
#pragma unroll
            for (int q = 0; q < 4; q++) c[mt][nt][q] = 0.f;

    const unsigned sAh = (unsigned)__cvta_generic_to_shared(&Ah[0][0]);
    const unsigned sBh = (unsigned)__cvta_generic_to_shared(&Bh[0][0]);
    const unsigned sBl = (unsigned)__cvta_generic_to_shared(&Bl[0][0]);
    const int a_row = wm * 64 + (lane & 15);
    const int a_kof = (lane >> 4) << 3;
    const int b_row = (lane & 15);
    const int b_col = wn * 32;

    for (int kc = 0; kc < CH_TOT; kc += KO_BK) {
#pragma unroll
        for (int g = 0; g < 2; g++) {
            int f   = tid * 2 + g;
            int r   = f >> 2;
            int kq  = f & 3;
            int row = row0 + r;
            uint4 v = make_uint4(0u, 0u, 0u, 0u);
            if (row < N_NODES)
                v = __ldcs(&g_aggrh4[((size_t)row * 256 + kc + kq * 8) >> 3]);
            *reinterpret_cast<uint4*>(&Ah[r][kq * 8]) = v;
        }
#pragma unroll
        for (int g = 0; g < 4; g++) {
            int f  = tid + g * 256;
            int kr = f >> 5;
            int nq = f & 31;
            float4 v = *reinterpret_cast<const float4*>(&W[(size_t)(kc + kr) * 128 + nq * 4]);
            unsigned short h0 = f2h(v.x), h1 = f2h(v.y), h2 = f2h(v.z), h3 = f2h(v.w);
            unsigned short l0 = f2h(v.x - h2f(h0)), l1 = f2h(v.y - h2f(h1));
            unsigned short l2 = f2h(v.z - h2f(h2)), l3 = f2h(v.w - h2f(h3));
            *reinterpret_cast<unsigned*>(&Bh[kr][nq * 4])     = (unsigned)h0 | ((unsigned)h1 << 16);
            *reinterpret_cast<unsigned*>(&Bh[kr][nq * 4 + 2]) = (unsigned)h2 | ((unsigned)h3 << 16);
            *reinterpret_cast<unsigned*>(&Bl[kr][nq * 4])     = (unsigned)l0 | ((unsigned)l1 << 16);
            *reinterpret_cast<unsigned*>(&Bl[kr][nq * 4 + 2]) = (unsigned)l2 | ((unsigned)l3 << 16);
        }
        __syncthreads();

#pragma unroll
        for (int ks = 0; ks < KO_BK / 16; ks++) {
            unsigned bh[4][2], bl[4][2];
#pragma unroll
            for (int nt = 0; nt < 4; nt++) {
                unsigned boff = (unsigned)(((ks * 16 + b_row) * (128 + KO_BPAD) + b_col + nt * 8) * 2);
                ldsm_x2t(bh[nt], sBh + boff);
                ldsm_x2t(bl[nt], sBl + boff);
            }
#pragma unroll
            for (int mt = 0; mt < 4; mt++) {
                unsigned aoff = (unsigned)(((a_row + mt * 16) * (KO_BK + KO_APAD) + ks * 16 + a_kof) * 2);
                unsigned ah[4];
                ldsm_x4(ah, sAh + aoff);
#pragma unroll
                for (int nt = 0; nt < 4; nt++) {
                    mma_f16(c[mt][nt], ah, bh[nt]);
                    mma_f16(c[mt][nt], ah, bl[nt]);
                }
            }
        }
        __syncthreads();
    }

    float bias[4][2];
#pragma unroll
    for (int nt = 0; nt < 4; nt++) {
        int col = wn * 32 + nt * 8 + (lane & 3) * 2;
        bias[nt][0] = __ldg(&bo[col]);
        bias[nt][1] = __ldg(&bo[col + 1]);
    }
#pragma unroll
    for (int mt = 0; mt < 4; mt++) {
#pragma unroll
        for (int nt = 0; nt < 4; nt++) {
            int rg0 = row0 + wm * 64 + mt * 16 + (lane >> 2);
            int col = wn * 32 + nt * 8 + (lane & 3) * 2;
            if (rg0 < N_NODES) {
                float2 o;
                o.x = tanhf(c[mt][nt][0] + bias[nt][0]);
                o.y = tanhf(c[mt][nt][1] + bias[nt][1]);
                __stcs(reinterpret_cast<float2*>(&out[(size_t)rg0 * 128 + col]), o);
            }
            int rg1 = rg0 + 8;
            if (rg1 < N_NODES) {
                float2 o;
                o.x = tanhf(c[mt][nt][2] + bias[nt][0]);
                o.y = tanhf(c[mt][nt][3] + bias[nt][1]);
                __stcs(reinterpret_cast<float2*>(&out[(size_t)rg1 * 128 + col]), o);
            }
        }
    }
}

// ------------------------------ launch -------------------------------------
extern "C" void kernel_launch(void* const* d_in, const int* in_sizes, int n_in,
                              void* d_out, int out_size)
{
    const float* x     = (const float*)d_in[0];
    const float* na    = (const float*)d_in[1];
    const void*  ei    = d_in[2];
    const float* ea    = (const float*)d_in[3];
    const float* W_in  = (const float*)d_in[4];
    const float* b_in  = (const float*)d_in[5];
    const float* W_out = (const float*)d_in[6];
    const float* b_out = (const float*)d_in[7];
    float* out = (float*)d_out;

    k_probe<<<(N_NODES + 255) / 256, 256>>>((const long long*)ei);
    k_init<<<4096, 256>>>(x, na, ei);

    k_scan1<<<N_SCAN_BLOCKS, SCAN_BLK>>>();
    k_scan3<<<(N_NODES + 255) / 256, 256>>>();

    k_fillz<<<ZB_BLOCKS + FILL_BLOCKS, 256>>>(ei);

    k_aggr<<<AGG_BLOCKS, 32 * AW>>>(ea, W_in, b_in);

    const int gemm_blocks = (N_NODES + 127) / 128;  // 782
    k_out<<<gemm_blocks, 256>>>(W_out, b_out, out);
}